// round 7
// baseline (speedup 1.0000x reference)
#include <cuda_runtime.h>
#include <math.h>

#define Bn 8
#define Ln 2048
#define Cn 7
#define Dn 512
#define Wn 24
#define NF 56
#define EPSf 1e-5f
#define TT 16
#define THRESH 1e-12f
#define DCUT 57.0f

// ---------------- scratch (device globals; allocation-free kernel_launch) ----
__device__ float g_xcomb[Bn*Ln*NF];
__device__ float g_c[(size_t)Bn*Ln*Dn];
__device__ float g_sq[Bn*Ln];
__device__ float g_sq128[Bn*Ln];
__device__ float g_pe[Ln*Dn];
__device__ float g_pef[Ln*Dn];
__device__ float g_pel[Ln*Dn];
__device__ float g_S[(size_t)Bn*Ln*Ln];
__device__ float g_tsum[(size_t)Bn*Ln*Dn];
__device__ int   g_flag[Bn*16*16];       // per-128x128-tile "S nonzero" flag
__device__ int   g_needfull[Bn*136];     // screen verdict per symmetric pair

// ---------------- helpers -----------------------------------------------------
__device__ __forceinline__ float totf(float x) {
    unsigned u;
    asm("cvt.rna.tf32.f32 %0, %1;" : "=r"(u) : "f"(x));
    return __uint_as_float(u);
}

__device__ __forceinline__ void mma_tf32(float* d, const unsigned* a, const unsigned* b) {
    asm volatile(
        "mma.sync.aligned.m16n8k8.row.col.f32.tf32.tf32.f32 "
        "{%0,%1,%2,%3}, {%4,%5,%6,%7}, {%8,%9}, {%0,%1,%2,%3};"
        : "+f"(d[0]), "+f"(d[1]), "+f"(d[2]), "+f"(d[3])
        : "r"(a[0]), "r"(a[1]), "r"(a[2]), "r"(a[3]), "r"(b[0]), "r"(b[1]));
}

__device__ __forceinline__ float blockReduce(float v, float* red) {
    #pragma unroll
    for (int o = 16; o; o >>= 1) v += __shfl_xor_sync(0xffffffffu, v, o);
    if ((threadIdx.x & 31) == 0) red[threadIdx.x >> 5] = v;
    __syncthreads();
    float s = red[0];
    #pragma unroll
    for (int i = 1; i < 8; i++) s += red[i];
    __syncthreads();
    return s;
}

// ---------------- 1) window stats + lags --------------------------------------
__global__ __launch_bounds__(256)
void features_kernel(const float* __restrict__ x) {
    int gid = blockIdx.x * blockDim.x + threadIdx.x;
    if (gid >= Bn*Ln*Cn) return;
    int ch = gid % Cn;
    int t  = (gid / Cn) % Ln;
    int b  = gid / (Cn*Ln);
    const float* xb = x + (size_t)b*Ln*Cn;
    float v[Wn];
    #pragma unroll
    for (int w = 0; w < Wn; w++) {
        int tt = t - (Wn-1) + w; tt = tt < 0 ? 0 : tt;
        v[w] = xb[tt*Cn + ch];
    }
    float s = 0.f, mx = v[0], mn = v[0];
    #pragma unroll
    for (int w = 0; w < Wn; w++) { s += v[w]; mx = fmaxf(mx, v[w]); mn = fminf(mn, v[w]); }
    float mean = s * (1.0f/Wn);
    float m2 = 0.f;
    #pragma unroll
    for (int w = 0; w < Wn; w++) { float d = v[w]-mean; m2 += d*d; }
    float sd = sqrtf(m2 * (1.0f/(Wn-1)));
    float xc = v[Wn-1];
    int t3 = t-3; t3 = t3 < 0 ? 0 : t3;
    int t5 = t-5; t5 = t5 < 0 ? 0 : t5;
    int t7 = t-7; t7 = t7 < 0 ? 0 : t7;
    float* o = g_xcomb + ((size_t)b*Ln + t)*NF;
    o[ch]      = xc;
    o[7  + ch] = mean;
    o[14 + ch] = mx;
    o[21 + ch] = mn;
    o[28 + ch] = sd;
    o[35 + ch] = xc - xb[t3*Cn + ch];
    o[42 + ch] = xc - xb[t5*Cn + ch];
    o[49 + ch] = xc - xb[t7*Cn + ch];
}

// ---------------- 2) circular conv1d(k=3) + bias + LN + sumsq(+first128) ------
__global__ __launch_bounds__(256)
void conv_ln_kernel(const float* __restrict__ conv_w, const float* __restrict__ conv_b,
                    const float* __restrict__ gamma_c, const float* __restrict__ beta_c) {
    __shared__ float sx[TT+2][NF];
    __shared__ float semb[TT][Dn];
    int b  = blockIdx.y;
    int t0 = blockIdx.x * TT;
    int tid = threadIdx.x;
    for (int i = tid; i < (TT+2)*NF; i += 256) {
        int r = i / NF, f = i - r*NF;
        int tt = (t0 - 1 + r + Ln) & (Ln - 1);
        sx[r][f] = g_xcomb[((size_t)b*Ln + tt)*NF + f];
    }
    __syncthreads();
    int d0 = tid * 2;
    float acc0[TT], acc1[TT];
    float bb0 = conv_b[d0], bb1 = conv_b[d0+1];
    #pragma unroll
    for (int t = 0; t < TT; t++) { acc0[t] = bb0; acc1[t] = bb1; }
    const float* w0p = conv_w + (size_t)d0*NF*3;
    const float* w1p = w0p + NF*3;
    for (int f = 0; f < NF; f++) {
        float w00 = w0p[f*3+0], w01 = w0p[f*3+1], w02 = w0p[f*3+2];
        float w10 = w1p[f*3+0], w11 = w1p[f*3+1], w12 = w1p[f*3+2];
        float sv[TT+2];
        #pragma unroll
        for (int r = 0; r < TT+2; r++) sv[r] = sx[r][f];
        #pragma unroll
        for (int t = 0; t < TT; t++) {
            acc0[t] += sv[t]*w00 + sv[t+1]*w01 + sv[t+2]*w02;
            acc1[t] += sv[t]*w10 + sv[t+1]*w11 + sv[t+2]*w12;
        }
    }
    #pragma unroll
    for (int t = 0; t < TT; t++) { semb[t][d0] = acc0[t]; semb[t][d0+1] = acc1[t]; }
    __syncthreads();
    int warp = tid >> 5, lane = tid & 31;
    for (int rr = warp; rr < TT; rr += 8) {
        float s = 0.f;
        for (int i = lane; i < Dn; i += 32) s += semb[rr][i];
        #pragma unroll
        for (int o = 16; o; o >>= 1) s += __shfl_xor_sync(0xffffffffu, s, o);
        float mu = s * (1.0f/Dn);
        float q = 0.f;
        for (int i = lane; i < Dn; i += 32) { float d = semb[rr][i]-mu; q += d*d; }
        #pragma unroll
        for (int o = 16; o; o >>= 1) q += __shfl_xor_sync(0xffffffffu, q, o);
        float inv = rsqrtf(q*(1.0f/Dn) + EPSf);
        int t = t0 + rr;
        float* cp = g_c + ((size_t)b*Ln + t)*Dn;
        float sq = 0.f, sq128 = 0.f;
        for (int i = lane; i < Dn; i += 32) {
            float cv = (semb[rr][i]-mu)*inv*gamma_c[i] + beta_c[i];
            cp[i] = cv;
            sq += cv*cv;
            if (i < 128) sq128 += cv*cv;
        }
        #pragma unroll
        for (int o = 16; o; o >>= 1) sq += __shfl_xor_sync(0xffffffffu, sq, o);
        #pragma unroll
        for (int o = 16; o; o >>= 1) sq128 += __shfl_xor_sync(0xffffffffu, sq128, o);
        if (lane == 0) {
            g_sq[b*Ln + t] = sq;
            g_sq128[b*Ln + t] = sq128;
        }
    }
}

// ---------------- 3) sinusoid PE + LN(pe) + LN(pe_learned) --------------------
__global__ __launch_bounds__(256)
void pe_kernel(const float* __restrict__ pe_learned,
               const float* __restrict__ gf, const float* __restrict__ bf,
               const float* __restrict__ gl, const float* __restrict__ bl) {
    __shared__ float red[8];
    int t = blockIdx.x;
    int tid = threadIdx.x;
    int dA = tid, dB = tid + 256;
    const float kdiv = -9.210340371976184f / (float)Dn;
    float divA = expf((float)(dA & ~1) * kdiv);
    float divB = expf((float)(dB & ~1) * kdiv);
    float sA, cA, sB, cB;
    sincosf((float)t * divA, &sA, &cA);
    sincosf((float)t * divB, &sB, &cB);
    float v0 = (dA & 1) ? cA : sA;
    float v1 = (dB & 1) ? cB : sB;
    g_pe[t*Dn + dA] = v0;
    g_pe[t*Dn + dB] = v1;
    float mu = blockReduce(v0 + v1, red) * (1.0f/Dn);
    float c0 = v0 - mu, c1 = v1 - mu;
    float var = blockReduce(c0*c0 + c1*c1, red) * (1.0f/Dn);
    float inv = rsqrtf(var + EPSf);
    g_pef[t*Dn + dA] = c0*inv*gf[dA] + bf[dA];
    g_pef[t*Dn + dB] = c1*inv*gf[dB] + bf[dB];
    float u0 = pe_learned[t*Dn + dA], u1 = pe_learned[t*Dn + dB];
    float mu2 = blockReduce(u0 + u1, red) * (1.0f/Dn);
    float e0 = u0 - mu2, e1 = u1 - mu2;
    float var2 = blockReduce(e0*e0 + e1*e1, red) * (1.0f/Dn);
    float inv2 = rsqrtf(var2 + EPSf);
    g_pel[t*Dn + dA] = e0*inv2*gl[dA] + bl[dA];
    g_pel[t*Dn + dB] = e1*inv2*gl[dB] + bl[dB];
}

// ---------------- 4a) screen: K=128 lower-bound on dist per tile-pair ---------
__global__ __launch_bounds__(256)
void screen_kernel() {
    __shared__ float As[2][128][20];
    __shared__ float Bs[2][128][20];
    __shared__ float redm[8];
    int b = blockIdx.y;
    int r = blockIdx.x, ti = 0;
    while (r >= 16 - ti) { r -= 16 - ti; ti++; }
    int tj = ti + r;
    const float* Cb = g_c + (size_t)b*Ln*Dn;
    int i0 = ti*128, j0 = tj*128;
    int tid = threadIdx.x;
    int warp = tid >> 5, lane = tid & 31;
    int wm = (warp >> 2) * 64;
    int wn = (warp & 3) * 32;
    int g = lane >> 2, th = lane & 3;

    int lrow = tid >> 1, lk = (tid & 1) * 8;
    const float* Ag = Cb + (size_t)(i0 + lrow)*Dn + lk;
    const float* Bg = Cb + (size_t)(j0 + lrow)*Dn + lk;

    float acc[4][4][4];
    #pragma unroll
    for (int i = 0; i < 4; i++)
        #pragma unroll
        for (int j = 0; j < 4; j++)
            #pragma unroll
            for (int q = 0; q < 4; q++) acc[i][j][q] = 0.f;

    float4 pa0 = *(const float4*)(Ag);
    float4 pa1 = *(const float4*)(Ag + 4);
    float4 pb0 = *(const float4*)(Bg);
    float4 pb1 = *(const float4*)(Bg + 4);
    #pragma unroll
    for (int q = 0; q < 4; q++) {
        As[0][lrow][lk+q]   = totf(((float*)&pa0)[q]);
        As[0][lrow][lk+4+q] = totf(((float*)&pa1)[q]);
        Bs[0][lrow][lk+q]   = totf(((float*)&pb0)[q]);
        Bs[0][lrow][lk+4+q] = totf(((float*)&pb1)[q]);
    }
    __syncthreads();
    int cur = 0;
    for (int kt = 0; kt < 8; kt++) {
        if (kt < 7) {
            int ko = (kt+1)*16;
            pa0 = *(const float4*)(Ag + ko);
            pa1 = *(const float4*)(Ag + ko + 4);
            pb0 = *(const float4*)(Bg + ko);
            pb1 = *(const float4*)(Bg + ko + 4);
        }
        #pragma unroll
        for (int k8 = 0; k8 < 16; k8 += 8) {
            unsigned af[4][4], bf_[4][2];
            #pragma unroll
            for (int fm = 0; fm < 4; fm++) {
                const float* ap = &As[cur][wm + fm*16 + g][k8 + th];
                af[fm][0] = __float_as_uint(ap[0]);
                af[fm][1] = __float_as_uint(ap[8*20]);
                af[fm][2] = __float_as_uint(ap[4]);
                af[fm][3] = __float_as_uint(ap[8*20 + 4]);
            }
            #pragma unroll
            for (int fn = 0; fn < 4; fn++) {
                const float* bp = &Bs[cur][wn + fn*8 + g][k8 + th];
                bf_[fn][0] = __float_as_uint(bp[0]);
                bf_[fn][1] = __float_as_uint(bp[4]);
            }
            #pragma unroll
            for (int fm = 0; fm < 4; fm++)
                #pragma unroll
                for (int fn = 0; fn < 4; fn++)
                    mma_tf32(acc[fm][fn], af[fm], bf_[fn]);
        }
        if (kt < 7) {
            int nxt = cur ^ 1;
            #pragma unroll
            for (int q = 0; q < 4; q++) {
                As[nxt][lrow][lk+q]   = totf(((float*)&pa0)[q]);
                As[nxt][lrow][lk+4+q] = totf(((float*)&pa1)[q]);
                Bs[nxt][lrow][lk+q]   = totf(((float*)&pb0)[q]);
                Bs[nxt][lrow][lk+4+q] = totf(((float*)&pb1)[q]);
            }
            __syncthreads();
            cur = nxt;
        }
    }
    // min over tile of dist128 = sq128_i + sq128_j - 2*dot128
    float sqj[4][2];
    #pragma unroll
    for (int fn = 0; fn < 4; fn++) {
        int j = j0 + wn + fn*8 + th*2;
        sqj[fn][0] = g_sq128[b*Ln + j];
        sqj[fn][1] = g_sq128[b*Ln + j + 1];
    }
    float mind = 1e30f;
    #pragma unroll
    for (int fm = 0; fm < 4; fm++) {
        #pragma unroll
        for (int rr = 0; rr < 2; rr++) {
            int i = i0 + wm + fm*16 + g + rr*8;
            float sqi = g_sq128[b*Ln + i];
            #pragma unroll
            for (int fn = 0; fn < 4; fn++) {
                float d0v = sqi + sqj[fn][0] - 2.0f*acc[fm][fn][rr*2+0];
                float d1v = sqi + sqj[fn][1] - 2.0f*acc[fm][fn][rr*2+1];
                mind = fminf(mind, fminf(d0v, d1v));
            }
        }
    }
    #pragma unroll
    for (int o = 16; o; o >>= 1) mind = fminf(mind, __shfl_xor_sync(0xffffffffu, mind, o));
    if (lane == 0) redm[warp] = mind;
    __syncthreads();
    if (tid == 0) {
        float m = redm[0];
        #pragma unroll
        for (int i = 1; i < 8; i++) m = fminf(m, redm[i]);
        int need = (m < DCUT) ? 1 : 0;
        g_needfull[b*136 + blockIdx.x] = need;
        if (!need) {
            g_flag[b*256 + ti*16 + tj] = 0;
            g_flag[b*256 + tj*16 + ti] = 0;
        }
    }
}

// ---------------- 4b) symmetric Gram (tf32 mma) for surviving pairs -----------
__global__ __launch_bounds__(256)
void gram_kernel() {
    __shared__ float As[2][128][20];
    __shared__ float Bs[2][128][20];
    __shared__ float redm[8];
    __shared__ int s_act;
    int b = blockIdx.y;
    if (!g_needfull[b*136 + blockIdx.x]) return;
    int r = blockIdx.x, ti = 0;
    while (r >= 16 - ti) { r -= 16 - ti; ti++; }
    int tj = ti + r;
    const float* Cb = g_c + (size_t)b*Ln*Dn;
    int i0 = ti*128, j0 = tj*128;
    int tid = threadIdx.x;
    int warp = tid >> 5, lane = tid & 31;
    int wm = (warp >> 2) * 64;
    int wn = (warp & 3) * 32;
    int g = lane >> 2, th = lane & 3;

    int lrow = tid >> 1, lk = (tid & 1) * 8;
    const float* Ag = Cb + (size_t)(i0 + lrow)*Dn + lk;
    const float* Bg = Cb + (size_t)(j0 + lrow)*Dn + lk;

    float acc[4][4][4];
    #pragma unroll
    for (int i = 0; i < 4; i++)
        #pragma unroll
        for (int j = 0; j < 4; j++)
            #pragma unroll
            for (int q = 0; q < 4; q++) acc[i][j][q] = 0.f;

    float4 pa0 = *(const float4*)(Ag);
    float4 pa1 = *(const float4*)(Ag + 4);
    float4 pb0 = *(const float4*)(Bg);
    float4 pb1 = *(const float4*)(Bg + 4);
    #pragma unroll
    for (int q = 0; q < 4; q++) {
        As[0][lrow][lk+q]   = totf(((float*)&pa0)[q]);
        As[0][lrow][lk+4+q] = totf(((float*)&pa1)[q]);
        Bs[0][lrow][lk+q]   = totf(((float*)&pb0)[q]);
        Bs[0][lrow][lk+4+q] = totf(((float*)&pb1)[q]);
    }
    __syncthreads();
    int cur = 0;
    for (int kt = 0; kt < 32; kt++) {
        if (kt < 31) {
            int ko = (kt+1)*16;
            pa0 = *(const float4*)(Ag + ko);
            pa1 = *(const float4*)(Ag + ko + 4);
            pb0 = *(const float4*)(Bg + ko);
            pb1 = *(const float4*)(Bg + ko + 4);
        }
        #pragma unroll
        for (int k8 = 0; k8 < 16; k8 += 8) {
            unsigned af[4][4], bf_[4][2];
            #pragma unroll
            for (int fm = 0; fm < 4; fm++) {
                const float* ap = &As[cur][wm + fm*16 + g][k8 + th];
                af[fm][0] = __float_as_uint(ap[0]);
                af[fm][1] = __float_as_uint(ap[8*20]);
                af[fm][2] = __float_as_uint(ap[4]);
                af[fm][3] = __float_as_uint(ap[8*20 + 4]);
            }
            #pragma unroll
            for (int fn = 0; fn < 4; fn++) {
                const float* bp = &Bs[cur][wn + fn*8 + g][k8 + th];
                bf_[fn][0] = __float_as_uint(bp[0]);
                bf_[fn][1] = __float_as_uint(bp[4]);
            }
            #pragma unroll
            for (int fm = 0; fm < 4; fm++)
                #pragma unroll
                for (int fn = 0; fn < 4; fn++)
                    mma_tf32(acc[fm][fn], af[fm], bf_[fn]);
        }
        if (kt < 31) {
            int nxt = cur ^ 1;
            #pragma unroll
            for (int q = 0; q < 4; q++) {
                As[nxt][lrow][lk+q]   = totf(((float*)&pa0)[q]);
                As[nxt][lrow][lk+4+q] = totf(((float*)&pa1)[q]);
                Bs[nxt][lrow][lk+q]   = totf(((float*)&pb0)[q]);
                Bs[nxt][lrow][lk+4+q] = totf(((float*)&pb1)[q]);
            }
            __syncthreads();
            cur = nxt;
        }
    }
    float sqj[4][2];
    #pragma unroll
    for (int fn = 0; fn < 4; fn++) {
        int j = j0 + wn + fn*8 + th*2;
        sqj[fn][0] = g_sq[b*Ln + j];
        sqj[fn][1] = g_sq[b*Ln + j + 1];
    }
    float mymax = 0.f;
    #pragma unroll
    for (int fm = 0; fm < 4; fm++) {
        #pragma unroll
        for (int rr = 0; rr < 2; rr++) {
            int i = i0 + wm + fm*16 + g + rr*8;
            float sqi = g_sq[b*Ln + i];
            #pragma unroll
            for (int fn = 0; fn < 4; fn++) {
                float d0v = fmaxf(sqi + sqj[fn][0] - 2.0f*acc[fm][fn][rr*2+0], 0.0f);
                float d1v = fmaxf(sqi + sqj[fn][1] - 2.0f*acc[fm][fn][rr*2+1], 0.0f);
                float s0 = __expf(-0.5f * d0v);
                float s1 = __expf(-0.5f * d1v);
                acc[fm][fn][rr*2+0] = s0;
                acc[fm][fn][rr*2+1] = s1;
                mymax = fmaxf(mymax, fmaxf(s0, s1));
            }
        }
    }
    #pragma unroll
    for (int o = 16; o; o >>= 1) mymax = fmaxf(mymax, __shfl_xor_sync(0xffffffffu, mymax, o));
    if (lane == 0) redm[warp] = mymax;
    __syncthreads();
    if (tid == 0) {
        float m = redm[0];
        #pragma unroll
        for (int i = 1; i < 8; i++) m = fmaxf(m, redm[i]);
        int a = (m > THRESH) ? 1 : 0;
        s_act = a;
        g_flag[b*256 + ti*16 + tj] = a;
        g_flag[b*256 + tj*16 + ti] = a;
    }
    __syncthreads();
    if (s_act) {
        float* Sb = g_S + (size_t)b*Ln*Ln;
        #pragma unroll
        for (int fm = 0; fm < 4; fm++) {
            #pragma unroll
            for (int rr = 0; rr < 2; rr++) {
                int i = i0 + wm + fm*16 + g + rr*8;
                #pragma unroll
                for (int fn = 0; fn < 4; fn++) {
                    int j = j0 + wn + fn*8 + th*2;
                    float s0 = acc[fm][fn][rr*2+0];
                    float s1 = acc[fm][fn][rr*2+1];
                    *(float2*)&Sb[(size_t)i*Ln + j] = make_float2(s0, s1);
                    if (ti != tj) {
                        Sb[(size_t)j*Ln + i]     = s0;
                        Sb[(size_t)(j+1)*Ln + i] = s1;
                    }
                }
            }
        }
    }
}

// ---------------- 5) sem = S@c / rowsum over ACTIVE chunks (rowsum fused) -----
__global__ __launch_bounds__(256)
void sem_kernel() {
    __shared__ float As[2][128][20];
    __shared__ float Bs[2][16][136];
    __shared__ int s_list[16];
    __shared__ int s_nact;
    __shared__ float srs[256];
    int b  = blockIdx.z;
    int i0 = blockIdx.x * 128;
    int d0 = blockIdx.y * 128;
    const float* Cb = g_c + (size_t)b*Ln*Dn;
    const float* Sb = g_S + (size_t)b*Ln*Ln;
    int tid = threadIdx.x;
    int warp = tid >> 5, lane = tid & 31;
    int wm = (warp >> 2) * 64;
    int wn = (warp & 3) * 32;
    int g = lane >> 2, th = lane & 3;

    if (tid == 0) {
        const int* fl = g_flag + b*256 + (i0 >> 7)*16;
        int n = 0;
        #pragma unroll
        for (int tj = 0; tj < 16; tj++)
            if (fl[tj]) s_list[n++] = tj;
        s_nact = n;
    }
    __syncthreads();
    int total = s_nact * 8;

    int lrow = tid >> 1, lk = (tid & 1) * 8;
    int kB = tid >> 4, dB = (tid & 15) * 8;
    const float* Ag = Sb + (size_t)(i0 + lrow)*Ln + lk;
    const float* Bg = Cb + (size_t)kB*Dn + d0 + dB;

    float acc[4][4][4];
    #pragma unroll
    for (int i = 0; i < 4; i++)
        #pragma unroll
        for (int j = 0; j < 4; j++)
            #pragma unroll
            for (int q = 0; q < 4; q++) acc[i][j][q] = 0.f;

    float rs = 0.f;
    int k0 = s_list[0] * 128;
    float4 pa0 = *(const float4*)(Ag + k0);
    float4 pa1 = *(const float4*)(Ag + k0 + 4);
    float4 pb0 = *(const float4*)(Bg + (size_t)k0*Dn);
    float4 pb1 = *(const float4*)(Bg + (size_t)k0*Dn + 4);
    rs += (pa0.x+pa0.y+pa0.z+pa0.w) + (pa1.x+pa1.y+pa1.z+pa1.w);
    #pragma unroll
    for (int q = 0; q < 4; q++) {
        As[0][lrow][lk+q]   = totf(((float*)&pa0)[q]);
        As[0][lrow][lk+4+q] = totf(((float*)&pa1)[q]);
        Bs[0][kB][dB+q]     = totf(((float*)&pb0)[q]);
        Bs[0][kB][dB+4+q]   = totf(((float*)&pb1)[q]);
    }
    __syncthreads();
    int cur = 0;
    for (int st = 0; st < total; st++) {
        if (st + 1 < total) {
            int kn = s_list[(st+1) >> 3] * 128 + ((st+1) & 7) * 16;
            pa0 = *(const float4*)(Ag + kn);
            pa1 = *(const float4*)(Ag + kn + 4);
            pb0 = *(const float4*)(Bg + (size_t)kn*Dn);
            pb1 = *(const float4*)(Bg + (size_t)kn*Dn + 4);
        }
        #pragma unroll
        for (int k8 = 0; k8 < 16; k8 += 8) {
            unsigned af[4][4], bf_[4][2];
            #pragma unroll
            for (int fm = 0; fm < 4; fm++) {
                const float* ap = &As[cur][wm + fm*16 + g][k8 + th];
                af[fm][0] = __float_as_uint(ap[0]);
                af[fm][1] = __float_as_uint(ap[8*20]);
                af[fm][2] = __float_as_uint(ap[4]);
                af[fm][3] = __float_as_uint(ap[8*20 + 4]);
            }
            #pragma unroll
            for (int fn = 0; fn < 4; fn++) {
                const float* bp = &Bs[cur][k8 + th][wn + fn*8 + g];
                bf_[fn][0] = __float_as_uint(bp[0]);
                bf_[fn][1] = __float_as_uint(bp[4*136]);
            }
            #pragma unroll
            for (int fm = 0; fm < 4; fm++)
                #pragma unroll
                for (int fn = 0; fn < 4; fn++)
                    mma_tf32(acc[fm][fn], af[fm], bf_[fn]);
        }
        if (st + 1 < total) {
            int nxt = cur ^ 1;
            rs += (pa0.x+pa0.y+pa0.z+pa0.w) + (pa1.x+pa1.y+pa1.z+pa1.w);
            #pragma unroll
            for (int q = 0; q < 4; q++) {
                As[nxt][lrow][lk+q]   = totf(((float*)&pa0)[q]);
                As[nxt][lrow][lk+4+q] = totf(((float*)&pa1)[q]);
                Bs[nxt][kB][dB+q]     = totf(((float*)&pb0)[q]);
                Bs[nxt][kB][dB+4+q]   = totf(((float*)&pb1)[q]);
            }
            __syncthreads();
            cur = nxt;
        }
    }
    __syncthreads();
    srs[tid] = rs;
    __syncthreads();
    float* Tb = g_tsum + (size_t)b*Ln*Dn;
    #pragma unroll
    for (int fm = 0; fm < 4; fm++) {
        #pragma unroll
        for (int rr = 0; rr < 2; rr++) {
            int i = i0 + wm + fm*16 + g + rr*8;
            int rl = i - i0;
            float rinv = 1.0f / (srs[2*rl] + srs[2*rl+1]);
            #pragma unroll
            for (int fn = 0; fn < 4; fn++) {
                int j = d0 + wn + fn*8 + th*2;
                float2 cv = *(const float2*)&Cb[(size_t)i*Dn + j];
                float2 pv = *(const float2*)&g_pe[i*Dn + j];
                float2 ov;
                ov.x = cv.x + pv.x + acc[fm][fn][rr*2+0]*rinv;
                ov.y = cv.y + pv.y + acc[fm][fn][rr*2+1]*rinv;
                *(float2*)&Tb[(size_t)i*Dn + j] = ov;
            }
        }
    }
}

// ---------------- 6) LN(tsum) + weighted mix ----------------------------------
__global__ __launch_bounds__(256)
void final_kernel(const float* __restrict__ wp,
                  const float* __restrict__ gt, const float* __restrict__ bt,
                  float* __restrict__ out) {
    __shared__ float red[8];
    int row = blockIdx.x;
    int t = row & (Ln - 1);
    int tid = threadIdx.x;
    int dA = tid, dB = tid + 256;
    const float* tp = g_tsum + (size_t)row*Dn;
    float v0 = tp[dA], v1 = tp[dB];
    float mu = blockReduce(v0 + v1, red) * (1.0f/Dn);
    float c0 = v0 - mu, c1 = v1 - mu;
    float var = blockReduce(c0*c0 + c1*c1, red) * (1.0f/Dn);
    float inv = rsqrtf(var + EPSf);
    float w0 = wp[0], w1 = wp[1], w2 = wp[2], w3 = wp[3];
    float mx = fmaxf(fmaxf(w0, w1), fmaxf(w2, w3));
    float e0 = expf(w0-mx), e1 = expf(w1-mx), e2 = expf(w2-mx), e3 = expf(w3-mx);
    float esum = 1.0f / (e0+e1+e2+e3);
    w0 = e0*esum; w1 = e1*esum; w2 = e2*esum; w3 = e3*esum;
    const float* cp = g_c + (size_t)row*Dn;
    float tpe0 = c0*inv*gt[dA] + bt[dA];
    float tpe1 = c1*inv*gt[dB] + bt[dB];
    out[(size_t)row*Dn + dA] = w0*cp[dA] + w1*g_pef[t*Dn+dA] + w2*g_pel[t*Dn+dA] + w3*tpe0;
    out[(size_t)row*Dn + dB] = w0*cp[dB] + w1*g_pef[t*Dn+dB] + w2*g_pel[t*Dn+dB] + w3*tpe1;
}

// ---------------- launch ------------------------------------------------------
extern "C" void kernel_launch(void* const* d_in, const int* in_sizes, int n_in,
                              void* d_out, int out_size) {
    const float* x          = (const float*)d_in[0];
    const float* conv_w     = (const float*)d_in[1];
    const float* conv_b     = (const float*)d_in[2];
    const float* pe_learned = (const float*)d_in[3];
    const float* wp         = (const float*)d_in[4];
    const float* gamma_c    = (const float*)d_in[5];
    const float* beta_c     = (const float*)d_in[6];
    const float* gamma_f    = (const float*)d_in[7];
    const float* beta_f     = (const float*)d_in[8];
    const float* gamma_l    = (const float*)d_in[9];
    const float* beta_l     = (const float*)d_in[10];
    const float* gamma_t    = (const float*)d_in[11];
    const float* beta_t     = (const float*)d_in[12];

    features_kernel<<<(Bn*Ln*Cn + 255)/256, 256>>>(x);
    conv_ln_kernel<<<dim3(Ln/TT, Bn), 256>>>(conv_w, conv_b, gamma_c, beta_c);
    pe_kernel<<<Ln, 256>>>(pe_learned, gamma_f, beta_f, gamma_l, beta_l);
    screen_kernel<<<dim3(136, Bn), 256>>>();
    gram_kernel<<<dim3(136, Bn), 256>>>();
    sem_kernel<<<dim3(16, 4, Bn), 256>>>();
    final_kernel<<<Bn*Ln, 256>>>(wp, gamma_t, beta_t, (float*)d_out);
}

// round 8
// speedup vs baseline: 1.2348x; 1.2348x over previous
#include <cuda_runtime.h>
#include <math.h>

#define Bn 8
#define Ln 2048
#define Cn 7
#define Dn 512
#define Wn 24
#define NF 56
#define EPSf 1e-5f
#define TT 16
#define THRESH 1e-12f
#define DCUT 70.0f

// ---------------- scratch (device globals; allocation-free kernel_launch) ----
__device__ float g_xcomb[Bn*Ln*NF];
__device__ float g_c[(size_t)Bn*Ln*Dn];
__device__ float g_sq[Bn*Ln];
__device__ float g_sq256[Bn*Ln];
__device__ float g_pe[Ln*Dn];
__device__ float g_pef[Ln*Dn];
__device__ float g_pel[Ln*Dn];
__device__ float g_S[(size_t)Bn*Ln*Ln];
__device__ float g_tsum[(size_t)Bn*Ln*Dn];
__device__ int   g_flag[Bn*16*16];       // per-128x128-tile "S nonzero" flag

// ---------------- helpers -----------------------------------------------------
__device__ __forceinline__ float totf(float x) {
    unsigned u;
    asm("cvt.rna.tf32.f32 %0, %1;" : "=r"(u) : "f"(x));
    return __uint_as_float(u);
}

__device__ __forceinline__ void mma_tf32(float* d, const unsigned* a, const unsigned* b) {
    asm volatile(
        "mma.sync.aligned.m16n8k8.row.col.f32.tf32.tf32.f32 "
        "{%0,%1,%2,%3}, {%4,%5,%6,%7}, {%8,%9}, {%0,%1,%2,%3};"
        : "+f"(d[0]), "+f"(d[1]), "+f"(d[2]), "+f"(d[3])
        : "r"(a[0]), "r"(a[1]), "r"(a[2]), "r"(a[3]), "r"(b[0]), "r"(b[1]));
}

__device__ __forceinline__ float blockReduce(float v, float* red) {
    #pragma unroll
    for (int o = 16; o; o >>= 1) v += __shfl_xor_sync(0xffffffffu, v, o);
    if ((threadIdx.x & 31) == 0) red[threadIdx.x >> 5] = v;
    __syncthreads();
    float s = red[0];
    #pragma unroll
    for (int i = 1; i < 8; i++) s += red[i];
    __syncthreads();
    return s;
}

// ---------------- 1) window stats + lags --------------------------------------
__global__ __launch_bounds__(256)
void features_kernel(const float* __restrict__ x) {
    int gid = blockIdx.x * blockDim.x + threadIdx.x;
    if (gid >= Bn*Ln*Cn) return;
    int ch = gid % Cn;
    int t  = (gid / Cn) % Ln;
    int b  = gid / (Cn*Ln);
    const float* xb = x + (size_t)b*Ln*Cn;
    float v[Wn];
    #pragma unroll
    for (int w = 0; w < Wn; w++) {
        int tt = t - (Wn-1) + w; tt = tt < 0 ? 0 : tt;
        v[w] = xb[tt*Cn + ch];
    }
    float s = 0.f, mx = v[0], mn = v[0];
    #pragma unroll
    for (int w = 0; w < Wn; w++) { s += v[w]; mx = fmaxf(mx, v[w]); mn = fminf(mn, v[w]); }
    float mean = s * (1.0f/Wn);
    float m2 = 0.f;
    #pragma unroll
    for (int w = 0; w < Wn; w++) { float d = v[w]-mean; m2 += d*d; }
    float sd = sqrtf(m2 * (1.0f/(Wn-1)));
    float xc = v[Wn-1];
    int t3 = t-3; t3 = t3 < 0 ? 0 : t3;
    int t5 = t-5; t5 = t5 < 0 ? 0 : t5;
    int t7 = t-7; t7 = t7 < 0 ? 0 : t7;
    float* o = g_xcomb + ((size_t)b*Ln + t)*NF;
    o[ch]      = xc;
    o[7  + ch] = mean;
    o[14 + ch] = mx;
    o[21 + ch] = mn;
    o[28 + ch] = sd;
    o[35 + ch] = xc - xb[t3*Cn + ch];
    o[42 + ch] = xc - xb[t5*Cn + ch];
    o[49 + ch] = xc - xb[t7*Cn + ch];
}

// ---------------- 2) circular conv1d(k=3) + bias + LN + sumsq(+first256) ------
__global__ __launch_bounds__(256)
void conv_ln_kernel(const float* __restrict__ conv_w, const float* __restrict__ conv_b,
                    const float* __restrict__ gamma_c, const float* __restrict__ beta_c) {
    __shared__ float sx[TT+2][NF];
    __shared__ float semb[TT][Dn];
    int b  = blockIdx.y;
    int t0 = blockIdx.x * TT;
    int tid = threadIdx.x;
    for (int i = tid; i < (TT+2)*NF; i += 256) {
        int r = i / NF, f = i - r*NF;
        int tt = (t0 - 1 + r + Ln) & (Ln - 1);
        sx[r][f] = g_xcomb[((size_t)b*Ln + tt)*NF + f];
    }
    __syncthreads();
    int d0 = tid * 2;
    float acc0[TT], acc1[TT];
    float bb0 = conv_b[d0], bb1 = conv_b[d0+1];
    #pragma unroll
    for (int t = 0; t < TT; t++) { acc0[t] = bb0; acc1[t] = bb1; }
    const float* w0p = conv_w + (size_t)d0*NF*3;
    const float* w1p = w0p + NF*3;
    for (int f = 0; f < NF; f++) {
        float w00 = w0p[f*3+0], w01 = w0p[f*3+1], w02 = w0p[f*3+2];
        float w10 = w1p[f*3+0], w11 = w1p[f*3+1], w12 = w1p[f*3+2];
        float sv[TT+2];
        #pragma unroll
        for (int r = 0; r < TT+2; r++) sv[r] = sx[r][f];
        #pragma unroll
        for (int t = 0; t < TT; t++) {
            acc0[t] += sv[t]*w00 + sv[t+1]*w01 + sv[t+2]*w02;
            acc1[t] += sv[t]*w10 + sv[t+1]*w11 + sv[t+2]*w12;
        }
    }
    #pragma unroll
    for (int t = 0; t < TT; t++) { semb[t][d0] = acc0[t]; semb[t][d0+1] = acc1[t]; }
    __syncthreads();
    int warp = tid >> 5, lane = tid & 31;
    for (int rr = warp; rr < TT; rr += 8) {
        float s = 0.f;
        for (int i = lane; i < Dn; i += 32) s += semb[rr][i];
        #pragma unroll
        for (int o = 16; o; o >>= 1) s += __shfl_xor_sync(0xffffffffu, s, o);
        float mu = s * (1.0f/Dn);
        float q = 0.f;
        for (int i = lane; i < Dn; i += 32) { float d = semb[rr][i]-mu; q += d*d; }
        #pragma unroll
        for (int o = 16; o; o >>= 1) q += __shfl_xor_sync(0xffffffffu, q, o);
        float inv = rsqrtf(q*(1.0f/Dn) + EPSf);
        int t = t0 + rr;
        float* cp = g_c + ((size_t)b*Ln + t)*Dn;
        float sq = 0.f, sq256 = 0.f;
        for (int i = lane; i < Dn; i += 32) {
            float cv = (semb[rr][i]-mu)*inv*gamma_c[i] + beta_c[i];
            cp[i] = cv;
            sq += cv*cv;
            if (i < 256) sq256 += cv*cv;
        }
        #pragma unroll
        for (int o = 16; o; o >>= 1) sq += __shfl_xor_sync(0xffffffffu, sq, o);
        #pragma unroll
        for (int o = 16; o; o >>= 1) sq256 += __shfl_xor_sync(0xffffffffu, sq256, o);
        if (lane == 0) {
            g_sq[b*Ln + t] = sq;
            g_sq256[b*Ln + t] = sq256;
        }
    }
}

// ---------------- 3) sinusoid PE + LN(pe) + LN(pe_learned) --------------------
__global__ __launch_bounds__(256)
void pe_kernel(const float* __restrict__ pe_learned,
               const float* __restrict__ gf, const float* __restrict__ bf,
               const float* __restrict__ gl, const float* __restrict__ bl) {
    __shared__ float red[8];
    int t = blockIdx.x;
    int tid = threadIdx.x;
    int dA = tid, dB = tid + 256;
    const float kdiv = -9.210340371976184f / (float)Dn;
    float divA = expf((float)(dA & ~1) * kdiv);
    float divB = expf((float)(dB & ~1) * kdiv);
    float sA, cA, sB, cB;
    sincosf((float)t * divA, &sA, &cA);
    sincosf((float)t * divB, &sB, &cB);
    float v0 = (dA & 1) ? cA : sA;
    float v1 = (dB & 1) ? cB : sB;
    g_pe[t*Dn + dA] = v0;
    g_pe[t*Dn + dB] = v1;
    float mu = blockReduce(v0 + v1, red) * (1.0f/Dn);
    float c0 = v0 - mu, c1 = v1 - mu;
    float var = blockReduce(c0*c0 + c1*c1, red) * (1.0f/Dn);
    float inv = rsqrtf(var + EPSf);
    g_pef[t*Dn + dA] = c0*inv*gf[dA] + bf[dA];
    g_pef[t*Dn + dB] = c1*inv*gf[dB] + bf[dB];
    float u0 = pe_learned[t*Dn + dA], u1 = pe_learned[t*Dn + dB];
    float mu2 = blockReduce(u0 + u1, red) * (1.0f/Dn);
    float e0 = u0 - mu2, e1 = u1 - mu2;
    float var2 = blockReduce(e0*e0 + e1*e1, red) * (1.0f/Dn);
    float inv2 = rsqrtf(var2 + EPSf);
    g_pel[t*Dn + dA] = e0*inv2*gl[dA] + bl[dA];
    g_pel[t*Dn + dB] = e1*inv2*gl[dB] + bl[dB];
}

// ---------------- 4) symmetric Gram (tf32 mma) + mid-loop early exit ----------
__global__ __launch_bounds__(256)
void gram_kernel() {
    __shared__ float As[2][128][20];
    __shared__ float Bs[2][128][20];
    __shared__ float redm[8];
    __shared__ int s_flag;
    int b = blockIdx.y;
    int r = blockIdx.x, ti = 0;
    while (r >= 16 - ti) { r -= 16 - ti; ti++; }
    int tj = ti + r;
    const float* Cb = g_c + (size_t)b*Ln*Dn;
    int i0 = ti*128, j0 = tj*128;
    int tid = threadIdx.x;
    int warp = tid >> 5, lane = tid & 31;
    int wm = (warp >> 2) * 64;
    int wn = (warp & 3) * 32;
    int g = lane >> 2, th = lane & 3;

    int lrow = tid >> 1, lk = (tid & 1) * 8;
    const float* Ag = Cb + (size_t)(i0 + lrow)*Dn + lk;
    const float* Bg = Cb + (size_t)(j0 + lrow)*Dn + lk;

    float acc[4][4][4];
    #pragma unroll
    for (int i = 0; i < 4; i++)
        #pragma unroll
        for (int j = 0; j < 4; j++)
            #pragma unroll
            for (int q = 0; q < 4; q++) acc[i][j][q] = 0.f;

    float4 pa0 = *(const float4*)(Ag);
    float4 pa1 = *(const float4*)(Ag + 4);
    float4 pb0 = *(const float4*)(Bg);
    float4 pb1 = *(const float4*)(Bg + 4);
    #pragma unroll
    for (int q = 0; q < 4; q++) {
        As[0][lrow][lk+q]   = totf(((float*)&pa0)[q]);
        As[0][lrow][lk+4+q] = totf(((float*)&pa1)[q]);
        Bs[0][lrow][lk+q]   = totf(((float*)&pb0)[q]);
        Bs[0][lrow][lk+4+q] = totf(((float*)&pb1)[q]);
    }
    __syncthreads();
    int cur = 0;
    for (int kt = 0; kt < 32; kt++) {
        if (kt < 31) {
            int ko = (kt+1)*16;
            pa0 = *(const float4*)(Ag + ko);
            pa1 = *(const float4*)(Ag + ko + 4);
            pb0 = *(const float4*)(Bg + ko);
            pb1 = *(const float4*)(Bg + ko + 4);
        }
        #pragma unroll
        for (int k8 = 0; k8 < 16; k8 += 8) {
            unsigned af[4][4], bf_[4][2];
            #pragma unroll
            for (int fm = 0; fm < 4; fm++) {
                const float* ap = &As[cur][wm + fm*16 + g][k8 + th];
                af[fm][0] = __float_as_uint(ap[0]);
                af[fm][1] = __float_as_uint(ap[8*20]);
                af[fm][2] = __float_as_uint(ap[4]);
                af[fm][3] = __float_as_uint(ap[8*20 + 4]);
            }
            #pragma unroll
            for (int fn = 0; fn < 4; fn++) {
                const float* bp = &Bs[cur][wn + fn*8 + g][k8 + th];
                bf_[fn][0] = __float_as_uint(bp[0]);
                bf_[fn][1] = __float_as_uint(bp[4]);
            }
            #pragma unroll
            for (int fm = 0; fm < 4; fm++)
                #pragma unroll
                for (int fn = 0; fn < 4; fn++)
                    mma_tf32(acc[fm][fn], af[fm], bf_[fn]);
        }
        if (kt == 15 && ti != tj) {
            // rigorous lower bound: dist >= sq256_i + sq256_j - 2*dot256 (rest >= 0)
            float sqj2[4][2];
            #pragma unroll
            for (int fn = 0; fn < 4; fn++) {
                int j = j0 + wn + fn*8 + th*2;
                sqj2[fn][0] = g_sq256[b*Ln + j];
                sqj2[fn][1] = g_sq256[b*Ln + j + 1];
            }
            float mind = 1e30f;
            #pragma unroll
            for (int fm = 0; fm < 4; fm++) {
                #pragma unroll
                for (int rr = 0; rr < 2; rr++) {
                    int i = i0 + wm + fm*16 + g + rr*8;
                    float sqi2 = g_sq256[b*Ln + i];
                    #pragma unroll
                    for (int fn = 0; fn < 4; fn++) {
                        float d0v = sqi2 + sqj2[fn][0] - 2.0f*acc[fm][fn][rr*2+0];
                        float d1v = sqi2 + sqj2[fn][1] - 2.0f*acc[fm][fn][rr*2+1];
                        mind = fminf(mind, fminf(d0v, d1v));
                    }
                }
            }
            #pragma unroll
            for (int o = 16; o; o >>= 1) mind = fminf(mind, __shfl_xor_sync(0xffffffffu, mind, o));
            if (lane == 0) redm[warp] = mind;
            __syncthreads();
            if (tid == 0) {
                float m = redm[0];
                #pragma unroll
                for (int i = 1; i < 8; i++) m = fminf(m, redm[i]);
                s_flag = (m > DCUT) ? 1 : 0;
            }
            __syncthreads();
            if (s_flag) {
                if (tid == 0) {
                    g_flag[b*256 + ti*16 + tj] = 0;
                    g_flag[b*256 + tj*16 + ti] = 0;
                }
                return;
            }
        }
        if (kt < 31) {
            int nxt = cur ^ 1;
            #pragma unroll
            for (int q = 0; q < 4; q++) {
                As[nxt][lrow][lk+q]   = totf(((float*)&pa0)[q]);
                As[nxt][lrow][lk+4+q] = totf(((float*)&pa1)[q]);
                Bs[nxt][lrow][lk+q]   = totf(((float*)&pb0)[q]);
                Bs[nxt][lrow][lk+4+q] = totf(((float*)&pb1)[q]);
            }
            __syncthreads();
            cur = nxt;
        }
    }
    float sqj[4][2];
    #pragma unroll
    for (int fn = 0; fn < 4; fn++) {
        int j = j0 + wn + fn*8 + th*2;
        sqj[fn][0] = g_sq[b*Ln + j];
        sqj[fn][1] = g_sq[b*Ln + j + 1];
    }
    float mymax = 0.f;
    #pragma unroll
    for (int fm = 0; fm < 4; fm++) {
        #pragma unroll
        for (int rr = 0; rr < 2; rr++) {
            int i = i0 + wm + fm*16 + g + rr*8;
            float sqi = g_sq[b*Ln + i];
            #pragma unroll
            for (int fn = 0; fn < 4; fn++) {
                float d0v = fmaxf(sqi + sqj[fn][0] - 2.0f*acc[fm][fn][rr*2+0], 0.0f);
                float d1v = fmaxf(sqi + sqj[fn][1] - 2.0f*acc[fm][fn][rr*2+1], 0.0f);
                float s0 = __expf(-0.5f * d0v);
                float s1 = __expf(-0.5f * d1v);
                acc[fm][fn][rr*2+0] = s0;
                acc[fm][fn][rr*2+1] = s1;
                mymax = fmaxf(mymax, fmaxf(s0, s1));
            }
        }
    }
    #pragma unroll
    for (int o = 16; o; o >>= 1) mymax = fmaxf(mymax, __shfl_xor_sync(0xffffffffu, mymax, o));
    if (lane == 0) redm[warp] = mymax;
    __syncthreads();
    if (tid == 0) {
        float m = redm[0];
        #pragma unroll
        for (int i = 1; i < 8; i++) m = fmaxf(m, redm[i]);
        int a = (m > THRESH) ? 1 : 0;
        s_flag = a;
        g_flag[b*256 + ti*16 + tj] = a;
        g_flag[b*256 + tj*16 + ti] = a;
    }
    __syncthreads();
    if (s_flag) {
        float* Sb = g_S + (size_t)b*Ln*Ln;
        #pragma unroll
        for (int fm = 0; fm < 4; fm++) {
            #pragma unroll
            for (int rr = 0; rr < 2; rr++) {
                int i = i0 + wm + fm*16 + g + rr*8;
                #pragma unroll
                for (int fn = 0; fn < 4; fn++) {
                    int j = j0 + wn + fn*8 + th*2;
                    float s0 = acc[fm][fn][rr*2+0];
                    float s1 = acc[fm][fn][rr*2+1];
                    *(float2*)&Sb[(size_t)i*Ln + j] = make_float2(s0, s1);
                    if (ti != tj) {
                        Sb[(size_t)j*Ln + i]     = s0;
                        Sb[(size_t)(j+1)*Ln + i] = s1;
                    }
                }
            }
        }
    }
}

// ---------------- 5) sem = S@c / rowsum over ACTIVE chunks (rowsum fused) -----
__global__ __launch_bounds__(256)
void sem_kernel() {
    __shared__ float As[2][128][20];
    __shared__ float Bs[2][16][136];
    __shared__ int s_list[16];
    __shared__ int s_nact;
    __shared__ float srs[256];
    int b  = blockIdx.z;
    int i0 = blockIdx.x * 128;
    int d0 = blockIdx.y * 128;
    const float* Cb = g_c + (size_t)b*Ln*Dn;
    const float* Sb = g_S + (size_t)b*Ln*Ln;
    int tid = threadIdx.x;
    int warp = tid >> 5, lane = tid & 31;
    int wm = (warp >> 2) * 64;
    int wn = (warp & 3) * 32;
    int g = lane >> 2, th = lane & 3;

    if (tid == 0) {
        const int* fl = g_flag + b*256 + (i0 >> 7)*16;
        int n = 0;
        #pragma unroll
        for (int tj = 0; tj < 16; tj++)
            if (fl[tj]) s_list[n++] = tj;
        s_nact = n;
    }
    __syncthreads();
    int total = s_nact * 8;

    int lrow = tid >> 1, lk = (tid & 1) * 8;
    int kB = tid >> 4, dB = (tid & 15) * 8;
    const float* Ag = Sb + (size_t)(i0 + lrow)*Ln + lk;
    const float* Bg = Cb + (size_t)kB*Dn + d0 + dB;

    float acc[4][4][4];
    #pragma unroll
    for (int i = 0; i < 4; i++)
        #pragma unroll
        for (int j = 0; j < 4; j++)
            #pragma unroll
            for (int q = 0; q < 4; q++) acc[i][j][q] = 0.f;

    float rs = 0.f;
    int k0 = s_list[0] * 128;
    float4 pa0 = *(const float4*)(Ag + k0);
    float4 pa1 = *(const float4*)(Ag + k0 + 4);
    float4 pb0 = *(const float4*)(Bg + (size_t)k0*Dn);
    float4 pb1 = *(const float4*)(Bg + (size_t)k0*Dn + 4);
    rs += (pa0.x+pa0.y+pa0.z+pa0.w) + (pa1.x+pa1.y+pa1.z+pa1.w);
    #pragma unroll
    for (int q = 0; q < 4; q++) {
        As[0][lrow][lk+q]   = totf(((float*)&pa0)[q]);
        As[0][lrow][lk+4+q] = totf(((float*)&pa1)[q]);
        Bs[0][kB][dB+q]     = totf(((float*)&pb0)[q]);
        Bs[0][kB][dB+4+q]   = totf(((float*)&pb1)[q]);
    }
    __syncthreads();
    int cur = 0;
    for (int st = 0; st < total; st++) {
        if (st + 1 < total) {
            int kn = s_list[(st+1) >> 3] * 128 + ((st+1) & 7) * 16;
            pa0 = *(const float4*)(Ag + kn);
            pa1 = *(const float4*)(Ag + kn + 4);
            pb0 = *(const float4*)(Bg + (size_t)kn*Dn);
            pb1 = *(const float4*)(Bg + (size_t)kn*Dn + 4);
        }
        #pragma unroll
        for (int k8 = 0; k8 < 16; k8 += 8) {
            unsigned af[4][4], bf_[4][2];
            #pragma unroll
            for (int fm = 0; fm < 4; fm++) {
                const float* ap = &As[cur][wm + fm*16 + g][k8 + th];
                af[fm][0] = __float_as_uint(ap[0]);
                af[fm][1] = __float_as_uint(ap[8*20]);
                af[fm][2] = __float_as_uint(ap[4]);
                af[fm][3] = __float_as_uint(ap[8*20 + 4]);
            }
            #pragma unroll
            for (int fn = 0; fn < 4; fn++) {
                const float* bp = &Bs[cur][k8 + th][wn + fn*8 + g];
                bf_[fn][0] = __float_as_uint(bp[0]);
                bf_[fn][1] = __float_as_uint(bp[4*136]);
            }
            #pragma unroll
            for (int fm = 0; fm < 4; fm++)
                #pragma unroll
                for (int fn = 0; fn < 4; fn++)
                    mma_tf32(acc[fm][fn], af[fm], bf_[fn]);
        }
        if (st + 1 < total) {
            int nxt = cur ^ 1;
            rs += (pa0.x+pa0.y+pa0.z+pa0.w) + (pa1.x+pa1.y+pa1.z+pa1.w);
            #pragma unroll
            for (int q = 0; q < 4; q++) {
                As[nxt][lrow][lk+q]   = totf(((float*)&pa0)[q]);
                As[nxt][lrow][lk+4+q] = totf(((float*)&pa1)[q]);
                Bs[nxt][kB][dB+q]     = totf(((float*)&pb0)[q]);
                Bs[nxt][kB][dB+4+q]   = totf(((float*)&pb1)[q]);
            }
            __syncthreads();
            cur = nxt;
        }
    }
    __syncthreads();
    srs[tid] = rs;
    __syncthreads();
    float* Tb = g_tsum + (size_t)b*Ln*Dn;
    #pragma unroll
    for (int fm = 0; fm < 4; fm++) {
        #pragma unroll
        for (int rr = 0; rr < 2; rr++) {
            int i = i0 + wm + fm*16 + g + rr*8;
            int rl = i - i0;
            float rinv = 1.0f / (srs[2*rl] + srs[2*rl+1]);
            #pragma unroll
            for (int fn = 0; fn < 4; fn++) {
                int j = d0 + wn + fn*8 + th*2;
                float2 cv = *(const float2*)&Cb[(size_t)i*Dn + j];
                float2 pv = *(const float2*)&g_pe[i*Dn + j];
                float2 ov;
                ov.x = cv.x + pv.x + acc[fm][fn][rr*2+0]*rinv;
                ov.y = cv.y + pv.y + acc[fm][fn][rr*2+1]*rinv;
                *(float2*)&Tb[(size_t)i*Dn + j] = ov;
            }
        }
    }
}

// ---------------- 6) LN(tsum) + weighted mix ----------------------------------
__global__ __launch_bounds__(256)
void final_kernel(const float* __restrict__ wp,
                  const float* __restrict__ gt, const float* __restrict__ bt,
                  float* __restrict__ out) {
    __shared__ float red[8];
    int row = blockIdx.x;
    int t = row & (Ln - 1);
    int tid = threadIdx.x;
    int dA = tid, dB = tid + 256;
    const float* tp = g_tsum + (size_t)row*Dn;
    float v0 = tp[dA], v1 = tp[dB];
    float mu = blockReduce(v0 + v1, red) * (1.0f/Dn);
    float c0 = v0 - mu, c1 = v1 - mu;
    float var = blockReduce(c0*c0 + c1*c1, red) * (1.0f/Dn);
    float inv = rsqrtf(var + EPSf);
    float w0 = wp[0], w1 = wp[1], w2 = wp[2], w3 = wp[3];
    float mx = fmaxf(fmaxf(w0, w1), fmaxf(w2, w3));
    float e0 = expf(w0-mx), e1 = expf(w1-mx), e2 = expf(w2-mx), e3 = expf(w3-mx);
    float esum = 1.0f / (e0+e1+e2+e3);
    w0 = e0*esum; w1 = e1*esum; w2 = e2*esum; w3 = e3*esum;
    const float* cp = g_c + (size_t)row*Dn;
    float tpe0 = c0*inv*gt[dA] + bt[dA];
    float tpe1 = c1*inv*gt[dB] + bt[dB];
    out[(size_t)row*Dn + dA] = w0*cp[dA] + w1*g_pef[t*Dn+dA] + w2*g_pel[t*Dn+dA] + w3*tpe0;
    out[(size_t)row*Dn + dB] = w0*cp[dB] + w1*g_pef[t*Dn+dB] + w2*g_pel[t*Dn+dB] + w3*tpe1;
}

// ---------------- launch ------------------------------------------------------
extern "C" void kernel_launch(void* const* d_in, const int* in_sizes, int n_in,
                              void* d_out, int out_size) {
    const float* x          = (const float*)d_in[0];
    const float* conv_w     = (const float*)d_in[1];
    const float* conv_b     = (const float*)d_in[2];
    const float* pe_learned = (const float*)d_in[3];
    const float* wp         = (const float*)d_in[4];
    const float* gamma_c    = (const float*)d_in[5];
    const float* beta_c     = (const float*)d_in[6];
    const float* gamma_f    = (const float*)d_in[7];
    const float* beta_f     = (const float*)d_in[8];
    const float* gamma_l    = (const float*)d_in[9];
    const float* beta_l     = (const float*)d_in[10];
    const float* gamma_t    = (const float*)d_in[11];
    const float* beta_t     = (const float*)d_in[12];

    features_kernel<<<(Bn*Ln*Cn + 255)/256, 256>>>(x);
    conv_ln_kernel<<<dim3(Ln/TT, Bn), 256>>>(conv_w, conv_b, gamma_c, beta_c);
    pe_kernel<<<Ln, 256>>>(pe_learned, gamma_f, beta_f, gamma_l, beta_l);
    gram_kernel<<<dim3(136, Bn), 256>>>();
    sem_kernel<<<dim3(16, 4, Bn), 256>>>();
    final_kernel<<<Bn*Ln, 256>>>(wp, gamma_t, beta_t, (float*)d_out);
}

// round 9
// speedup vs baseline: 1.2410x; 1.0050x over previous
#include <cuda_runtime.h>
#include <math.h>

#define Bn 8
#define Ln 2048
#define Cn 7
#define Dn 512
#define Wn 24
#define NF 56
#define EPSf 1e-5f
#define TT 16
#define THRESH 1e-12f
#define DCUT 60.0f

// ---------------- scratch (device globals; allocation-free kernel_launch) ----
__device__ float g_xcomb[Bn*Ln*NF];
__device__ float g_c[(size_t)Bn*Ln*Dn];
__device__ float g_sq[Bn*Ln];
__device__ float g_sq160[Bn*Ln];
__device__ float g_sq256[Bn*Ln];
__device__ float g_sq384[Bn*Ln];
__device__ float g_pe[Ln*Dn];
__device__ float g_pef[Ln*Dn];
__device__ float g_pel[Ln*Dn];
__device__ float g_S[(size_t)Bn*Ln*Ln];
__device__ float g_tsum[(size_t)Bn*Ln*Dn];
__device__ int   g_flag[Bn*16*16];       // per-128x128-tile "S nonzero" flag

// ---------------- helpers -----------------------------------------------------
__device__ __forceinline__ float totf(float x) {
    unsigned u;
    asm("cvt.rna.tf32.f32 %0, %1;" : "=r"(u) : "f"(x));
    return __uint_as_float(u);
}

__device__ __forceinline__ void mma_tf32(float* d, const unsigned* a, const unsigned* b) {
    asm volatile(
        "mma.sync.aligned.m16n8k8.row.col.f32.tf32.tf32.f32 "
        "{%0,%1,%2,%3}, {%4,%5,%6,%7}, {%8,%9}, {%0,%1,%2,%3};"
        : "+f"(d[0]), "+f"(d[1]), "+f"(d[2]), "+f"(d[3])
        : "r"(a[0]), "r"(a[1]), "r"(a[2]), "r"(a[3]), "r"(b[0]), "r"(b[1]));
}

__device__ __forceinline__ float blockReduce(float v, float* red) {
    #pragma unroll
    for (int o = 16; o; o >>= 1) v += __shfl_xor_sync(0xffffffffu, v, o);
    if ((threadIdx.x & 31) == 0) red[threadIdx.x >> 5] = v;
    __syncthreads();
    float s = red[0];
    #pragma unroll
    for (int i = 1; i < 8; i++) s += red[i];
    __syncthreads();
    return s;
}

// ---------------- 1) window stats + lags --------------------------------------
__global__ __launch_bounds__(256)
void features_kernel(const float* __restrict__ x) {
    int gid = blockIdx.x * blockDim.x + threadIdx.x;
    if (gid >= Bn*Ln*Cn) return;
    int ch = gid % Cn;
    int t  = (gid / Cn) % Ln;
    int b  = gid / (Cn*Ln);
    const float* xb = x + (size_t)b*Ln*Cn;
    float v[Wn];
    #pragma unroll
    for (int w = 0; w < Wn; w++) {
        int tt = t - (Wn-1) + w; tt = tt < 0 ? 0 : tt;
        v[w] = xb[tt*Cn + ch];
    }
    float s = 0.f, mx = v[0], mn = v[0];
    #pragma unroll
    for (int w = 0; w < Wn; w++) { s += v[w]; mx = fmaxf(mx, v[w]); mn = fminf(mn, v[w]); }
    float mean = s * (1.0f/Wn);
    float m2 = 0.f;
    #pragma unroll
    for (int w = 0; w < Wn; w++) { float d = v[w]-mean; m2 += d*d; }
    float sd = sqrtf(m2 * (1.0f/(Wn-1)));
    float xc = v[Wn-1];
    int t3 = t-3; t3 = t3 < 0 ? 0 : t3;
    int t5 = t-5; t5 = t5 < 0 ? 0 : t5;
    int t7 = t-7; t7 = t7 < 0 ? 0 : t7;
    float* o = g_xcomb + ((size_t)b*Ln + t)*NF;
    o[ch]      = xc;
    o[7  + ch] = mean;
    o[14 + ch] = mx;
    o[21 + ch] = mn;
    o[28 + ch] = sd;
    o[35 + ch] = xc - xb[t3*Cn + ch];
    o[42 + ch] = xc - xb[t5*Cn + ch];
    o[49 + ch] = xc - xb[t7*Cn + ch];
}

// ---------------- 2) circular conv1d(k=3) + bias + LN + partial sumsq ---------
__global__ __launch_bounds__(256)
void conv_ln_kernel(const float* __restrict__ conv_w, const float* __restrict__ conv_b,
                    const float* __restrict__ gamma_c, const float* __restrict__ beta_c) {
    __shared__ float sx[TT+2][NF];
    __shared__ float semb[TT][Dn];
    int b  = blockIdx.y;
    int t0 = blockIdx.x * TT;
    int tid = threadIdx.x;
    for (int i = tid; i < (TT+2)*NF; i += 256) {
        int r = i / NF, f = i - r*NF;
        int tt = (t0 - 1 + r + Ln) & (Ln - 1);
        sx[r][f] = g_xcomb[((size_t)b*Ln + tt)*NF + f];
    }
    __syncthreads();
    int d0 = tid * 2;
    float acc0[TT], acc1[TT];
    float bb0 = conv_b[d0], bb1 = conv_b[d0+1];
    #pragma unroll
    for (int t = 0; t < TT; t++) { acc0[t] = bb0; acc1[t] = bb1; }
    const float* w0p = conv_w + (size_t)d0*NF*3;
    const float* w1p = w0p + NF*3;
    for (int f = 0; f < NF; f++) {
        float w00 = w0p[f*3+0], w01 = w0p[f*3+1], w02 = w0p[f*3+2];
        float w10 = w1p[f*3+0], w11 = w1p[f*3+1], w12 = w1p[f*3+2];
        float sv[TT+2];
        #pragma unroll
        for (int r = 0; r < TT+2; r++) sv[r] = sx[r][f];
        #pragma unroll
        for (int t = 0; t < TT; t++) {
            acc0[t] += sv[t]*w00 + sv[t+1]*w01 + sv[t+2]*w02;
            acc1[t] += sv[t]*w10 + sv[t+1]*w11 + sv[t+2]*w12;
        }
    }
    #pragma unroll
    for (int t = 0; t < TT; t++) { semb[t][d0] = acc0[t]; semb[t][d0+1] = acc1[t]; }
    __syncthreads();
    int warp = tid >> 5, lane = tid & 31;
    for (int rr = warp; rr < TT; rr += 8) {
        float s = 0.f;
        for (int i = lane; i < Dn; i += 32) s += semb[rr][i];
        #pragma unroll
        for (int o = 16; o; o >>= 1) s += __shfl_xor_sync(0xffffffffu, s, o);
        float mu = s * (1.0f/Dn);
        float q = 0.f;
        for (int i = lane; i < Dn; i += 32) { float d = semb[rr][i]-mu; q += d*d; }
        #pragma unroll
        for (int o = 16; o; o >>= 1) q += __shfl_xor_sync(0xffffffffu, q, o);
        float inv = rsqrtf(q*(1.0f/Dn) + EPSf);
        int t = t0 + rr;
        float* cp = g_c + ((size_t)b*Ln + t)*Dn;
        float sq = 0.f, s160 = 0.f, s256 = 0.f, s384 = 0.f;
        for (int i = lane; i < Dn; i += 32) {
            float cv = (semb[rr][i]-mu)*inv*gamma_c[i] + beta_c[i];
            cp[i] = cv;
            float c2 = cv*cv;
            sq += c2;
            if (i < 160) s160 += c2;
            if (i < 256) s256 += c2;
            if (i < 384) s384 += c2;
        }
        #pragma unroll
        for (int o = 16; o; o >>= 1) {
            sq   += __shfl_xor_sync(0xffffffffu, sq, o);
            s160 += __shfl_xor_sync(0xffffffffu, s160, o);
            s256 += __shfl_xor_sync(0xffffffffu, s256, o);
            s384 += __shfl_xor_sync(0xffffffffu, s384, o);
        }
        if (lane == 0) {
            g_sq[b*Ln + t]    = sq;
            g_sq160[b*Ln + t] = s160;
            g_sq256[b*Ln + t] = s256;
            g_sq384[b*Ln + t] = s384;
        }
    }
}

// ---------------- 3) sinusoid PE + LN(pe) + LN(pe_learned) --------------------
__global__ __launch_bounds__(256)
void pe_kernel(const float* __restrict__ pe_learned,
               const float* __restrict__ gf, const float* __restrict__ bf,
               const float* __restrict__ gl, const float* __restrict__ bl) {
    __shared__ float red[8];
    int t = blockIdx.x;
    int tid = threadIdx.x;
    int dA = tid, dB = tid + 256;
    const float kdiv = -9.210340371976184f / (float)Dn;
    float divA = expf((float)(dA & ~1) * kdiv);
    float divB = expf((float)(dB & ~1) * kdiv);
    float sA, cA, sB, cB;
    sincosf((float)t * divA, &sA, &cA);
    sincosf((float)t * divB, &sB, &cB);
    float v0 = (dA & 1) ? cA : sA;
    float v1 = (dB & 1) ? cB : sB;
    g_pe[t*Dn + dA] = v0;
    g_pe[t*Dn + dB] = v1;
    float mu = blockReduce(v0 + v1, red) * (1.0f/Dn);
    float c0 = v0 - mu, c1 = v1 - mu;
    float var = blockReduce(c0*c0 + c1*c1, red) * (1.0f/Dn);
    float inv = rsqrtf(var + EPSf);
    g_pef[t*Dn + dA] = c0*inv*gf[dA] + bf[dA];
    g_pef[t*Dn + dB] = c1*inv*gf[dB] + bf[dB];
    float u0 = pe_learned[t*Dn + dA], u1 = pe_learned[t*Dn + dB];
    float mu2 = blockReduce(u0 + u1, red) * (1.0f/Dn);
    float e0 = u0 - mu2, e1 = u1 - mu2;
    float var2 = blockReduce(e0*e0 + e1*e1, red) * (1.0f/Dn);
    float inv2 = rsqrtf(var2 + EPSf);
    g_pel[t*Dn + dA] = e0*inv2*gl[dA] + bl[dA];
    g_pel[t*Dn + dB] = e1*inv2*gl[dB] + bl[dB];
}

// ---------------- 4) symmetric Gram (tf32 mma) + checkpoint ladder ------------
__global__ __launch_bounds__(256)
void gram_kernel() {
    __shared__ float As[2][128][20];
    __shared__ float Bs[2][128][20];
    __shared__ float redm[8];
    __shared__ int s_flag;
    int b = blockIdx.y;
    int r = blockIdx.x, ti = 0;
    while (r >= 16 - ti) { r -= 16 - ti; ti++; }
    int tj = ti + r;
    const float* Cb = g_c + (size_t)b*Ln*Dn;
    int i0 = ti*128, j0 = tj*128;
    int tid = threadIdx.x;
    int warp = tid >> 5, lane = tid & 31;
    int wm = (warp >> 2) * 64;
    int wn = (warp & 3) * 32;
    int g = lane >> 2, th = lane & 3;

    int lrow = tid >> 1, lk = (tid & 1) * 8;
    const float* Ag = Cb + (size_t)(i0 + lrow)*Dn + lk;
    const float* Bg = Cb + (size_t)(j0 + lrow)*Dn + lk;

    float acc[4][4][4];
    #pragma unroll
    for (int i = 0; i < 4; i++)
        #pragma unroll
        for (int j = 0; j < 4; j++)
            #pragma unroll
            for (int q = 0; q < 4; q++) acc[i][j][q] = 0.f;

    float4 pa0 = *(const float4*)(Ag);
    float4 pa1 = *(const float4*)(Ag + 4);
    float4 pb0 = *(const float4*)(Bg);
    float4 pb1 = *(const float4*)(Bg + 4);
    #pragma unroll
    for (int q = 0; q < 4; q++) {
        As[0][lrow][lk+q]   = totf(((float*)&pa0)[q]);
        As[0][lrow][lk+4+q] = totf(((float*)&pa1)[q]);
        Bs[0][lrow][lk+q]   = totf(((float*)&pb0)[q]);
        Bs[0][lrow][lk+4+q] = totf(((float*)&pb1)[q]);
    }
    __syncthreads();
    int cur = 0;
    for (int kt = 0; kt < 32; kt++) {
        if (kt < 31) {
            int ko = (kt+1)*16;
            pa0 = *(const float4*)(Ag + ko);
            pa1 = *(const float4*)(Ag + ko + 4);
            pb0 = *(const float4*)(Bg + ko);
            pb1 = *(const float4*)(Bg + ko + 4);
        }
        #pragma unroll
        for (int k8 = 0; k8 < 16; k8 += 8) {
            unsigned af[4][4], bf_[4][2];
            #pragma unroll
            for (int fm = 0; fm < 4; fm++) {
                const float* ap = &As[cur][wm + fm*16 + g][k8 + th];
                af[fm][0] = __float_as_uint(ap[0]);
                af[fm][1] = __float_as_uint(ap[8*20]);
                af[fm][2] = __float_as_uint(ap[4]);
                af[fm][3] = __float_as_uint(ap[8*20 + 4]);
            }
            #pragma unroll
            for (int fn = 0; fn < 4; fn++) {
                const float* bp = &Bs[cur][wn + fn*8 + g][k8 + th];
                bf_[fn][0] = __float_as_uint(bp[0]);
                bf_[fn][1] = __float_as_uint(bp[4]);
            }
            #pragma unroll
            for (int fm = 0; fm < 4; fm++)
                #pragma unroll
                for (int fn = 0; fn < 4; fn++)
                    mma_tf32(acc[fm][fn], af[fm], bf_[fn]);
        }
        if (ti != tj && (kt == 9 || kt == 15 || kt == 23)) {
            // rigorous lower bound: dist >= sqK_i + sqK_j - 2*dotK  (tail >= 0)
            const float* sqp = (kt == 9) ? g_sq160 : (kt == 15) ? g_sq256 : g_sq384;
            float sqj2[4][2];
            #pragma unroll
            for (int fn = 0; fn < 4; fn++) {
                int j = j0 + wn + fn*8 + th*2;
                sqj2[fn][0] = sqp[b*Ln + j];
                sqj2[fn][1] = sqp[b*Ln + j + 1];
            }
            float mind = 1e30f;
            #pragma unroll
            for (int fm = 0; fm < 4; fm++) {
                #pragma unroll
                for (int rr = 0; rr < 2; rr++) {
                    int i = i0 + wm + fm*16 + g + rr*8;
                    float sqi2 = sqp[b*Ln + i];
                    #pragma unroll
                    for (int fn = 0; fn < 4; fn++) {
                        float d0v = sqi2 + sqj2[fn][0] - 2.0f*acc[fm][fn][rr*2+0];
                        float d1v = sqi2 + sqj2[fn][1] - 2.0f*acc[fm][fn][rr*2+1];
                        mind = fminf(mind, fminf(d0v, d1v));
                    }
                }
            }
            #pragma unroll
            for (int o = 16; o; o >>= 1) mind = fminf(mind, __shfl_xor_sync(0xffffffffu, mind, o));
            if (lane == 0) redm[warp] = mind;
            __syncthreads();
            if (tid == 0) {
                float m = redm[0];
                #pragma unroll
                for (int i = 1; i < 8; i++) m = fminf(m, redm[i]);
                s_flag = (m > DCUT) ? 1 : 0;
            }
            __syncthreads();
            if (s_flag) {
                if (tid == 0) {
                    g_flag[b*256 + ti*16 + tj] = 0;
                    g_flag[b*256 + tj*16 + ti] = 0;
                }
                return;
            }
        }
        if (kt < 31) {
            int nxt = cur ^ 1;
            #pragma unroll
            for (int q = 0; q < 4; q++) {
                As[nxt][lrow][lk+q]   = totf(((float*)&pa0)[q]);
                As[nxt][lrow][lk+4+q] = totf(((float*)&pa1)[q]);
                Bs[nxt][lrow][lk+q]   = totf(((float*)&pb0)[q]);
                Bs[nxt][lrow][lk+4+q] = totf(((float*)&pb1)[q]);
            }
            __syncthreads();
            cur = nxt;
        }
    }
    float sqj[4][2];
    #pragma unroll
    for (int fn = 0; fn < 4; fn++) {
        int j = j0 + wn + fn*8 + th*2;
        sqj[fn][0] = g_sq[b*Ln + j];
        sqj[fn][1] = g_sq[b*Ln + j + 1];
    }
    float mymax = 0.f;
    #pragma unroll
    for (int fm = 0; fm < 4; fm++) {
        #pragma unroll
        for (int rr = 0; rr < 2; rr++) {
            int i = i0 + wm + fm*16 + g + rr*8;
            float sqi = g_sq[b*Ln + i];
            #pragma unroll
            for (int fn = 0; fn < 4; fn++) {
                float d0v = fmaxf(sqi + sqj[fn][0] - 2.0f*acc[fm][fn][rr*2+0], 0.0f);
                float d1v = fmaxf(sqi + sqj[fn][1] - 2.0f*acc[fm][fn][rr*2+1], 0.0f);
                float s0 = __expf(-0.5f * d0v);
                float s1 = __expf(-0.5f * d1v);
                acc[fm][fn][rr*2+0] = s0;
                acc[fm][fn][rr*2+1] = s1;
                mymax = fmaxf(mymax, fmaxf(s0, s1));
            }
        }
    }
    #pragma unroll
    for (int o = 16; o; o >>= 1) mymax = fmaxf(mymax, __shfl_xor_sync(0xffffffffu, mymax, o));
    if (lane == 0) redm[warp] = mymax;
    __syncthreads();
    if (tid == 0) {
        float m = redm[0];
        #pragma unroll
        for (int i = 1; i < 8; i++) m = fmaxf(m, redm[i]);
        int a = (m > THRESH) ? 1 : 0;
        s_flag = a;
        g_flag[b*256 + ti*16 + tj] = a;
        g_flag[b*256 + tj*16 + ti] = a;
    }
    __syncthreads();
    if (s_flag) {
        float* Sb = g_S + (size_t)b*Ln*Ln;
        #pragma unroll
        for (int fm = 0; fm < 4; fm++) {
            #pragma unroll
            for (int rr = 0; rr < 2; rr++) {
                int i = i0 + wm + fm*16 + g + rr*8;
                #pragma unroll
                for (int fn = 0; fn < 4; fn++) {
                    int j = j0 + wn + fn*8 + th*2;
                    float s0 = acc[fm][fn][rr*2+0];
                    float s1 = acc[fm][fn][rr*2+1];
                    *(float2*)&Sb[(size_t)i*Ln + j] = make_float2(s0, s1);
                    if (ti != tj) {
                        Sb[(size_t)j*Ln + i]     = s0;
                        Sb[(size_t)(j+1)*Ln + i] = s1;
                    }
                }
            }
        }
    }
}

// ---------------- 5) sem = S@c / rowsum over ACTIVE chunks (rowsum fused) -----
__global__ __launch_bounds__(256)
void sem_kernel() {
    __shared__ float As[2][128][20];
    __shared__ float Bs[2][16][136];
    __shared__ int s_list[16];
    __shared__ int s_nact;
    __shared__ float srs[256];
    int b  = blockIdx.z;
    int i0 = blockIdx.x * 128;
    int d0 = blockIdx.y * 128;
    const float* Cb = g_c + (size_t)b*Ln*Dn;
    const float* Sb = g_S + (size_t)b*Ln*Ln;
    int tid = threadIdx.x;
    int warp = tid >> 5, lane = tid & 31;
    int wm = (warp >> 2) * 64;
    int wn = (warp & 3) * 32;
    int g = lane >> 2, th = lane & 3;

    if (tid == 0) {
        const int* fl = g_flag + b*256 + (i0 >> 7)*16;
        int n = 0;
        #pragma unroll
        for (int tj = 0; tj < 16; tj++)
            if (fl[tj]) s_list[n++] = tj;
        s_nact = n;
    }
    __syncthreads();
    int total = s_nact * 8;

    int lrow = tid >> 1, lk = (tid & 1) * 8;
    int kB = tid >> 4, dB = (tid & 15) * 8;
    const float* Ag = Sb + (size_t)(i0 + lrow)*Ln + lk;
    const float* Bg = Cb + (size_t)kB*Dn + d0 + dB;

    float acc[4][4][4];
    #pragma unroll
    for (int i = 0; i < 4; i++)
        #pragma unroll
        for (int j = 0; j < 4; j++)
            #pragma unroll
            for (int q = 0; q < 4; q++) acc[i][j][q] = 0.f;

    float rs = 0.f;
    int k0 = s_list[0] * 128;
    float4 pa0 = *(const float4*)(Ag + k0);
    float4 pa1 = *(const float4*)(Ag + k0 + 4);
    float4 pb0 = *(const float4*)(Bg + (size_t)k0*Dn);
    float4 pb1 = *(const float4*)(Bg + (size_t)k0*Dn + 4);
    rs += (pa0.x+pa0.y+pa0.z+pa0.w) + (pa1.x+pa1.y+pa1.z+pa1.w);
    #pragma unroll
    for (int q = 0; q < 4; q++) {
        As[0][lrow][lk+q]   = totf(((float*)&pa0)[q]);
        As[0][lrow][lk+4+q] = totf(((float*)&pa1)[q]);
        Bs[0][kB][dB+q]     = totf(((float*)&pb0)[q]);
        Bs[0][kB][dB+4+q]   = totf(((float*)&pb1)[q]);
    }
    __syncthreads();
    int cur = 0;
    for (int st = 0; st < total; st++) {
        if (st + 1 < total) {
            int kn = s_list[(st+1) >> 3] * 128 + ((st+1) & 7) * 16;
            pa0 = *(const float4*)(Ag + kn);
            pa1 = *(const float4*)(Ag + kn + 4);
            pb0 = *(const float4*)(Bg + (size_t)kn*Dn);
            pb1 = *(const float4*)(Bg + (size_t)kn*Dn + 4);
        }
        #pragma unroll
        for (int k8 = 0; k8 < 16; k8 += 8) {
            unsigned af[4][4], bf_[4][2];
            #pragma unroll
            for (int fm = 0; fm < 4; fm++) {
                const float* ap = &As[cur][wm + fm*16 + g][k8 + th];
                af[fm][0] = __float_as_uint(ap[0]);
                af[fm][1] = __float_as_uint(ap[8*20]);
                af[fm][2] = __float_as_uint(ap[4]);
                af[fm][3] = __float_as_uint(ap[8*20 + 4]);
            }
            #pragma unroll
            for (int fn = 0; fn < 4; fn++) {
                const float* bp = &Bs[cur][k8 + th][wn + fn*8 + g];
                bf_[fn][0] = __float_as_uint(bp[0]);
                bf_[fn][1] = __float_as_uint(bp[4*136]);
            }
            #pragma unroll
            for (int fm = 0; fm < 4; fm++)
                #pragma unroll
                for (int fn = 0; fn < 4; fn++)
                    mma_tf32(acc[fm][fn], af[fm], bf_[fn]);
        }
        if (st + 1 < total) {
            int nxt = cur ^ 1;
            rs += (pa0.x+pa0.y+pa0.z+pa0.w) + (pa1.x+pa1.y+pa1.z+pa1.w);
            #pragma unroll
            for (int q = 0; q < 4; q++) {
                As[nxt][lrow][lk+q]   = totf(((float*)&pa0)[q]);
                As[nxt][lrow][lk+4+q] = totf(((float*)&pa1)[q]);
                Bs[nxt][kB][dB+q]     = totf(((float*)&pb0)[q]);
                Bs[nxt][kB][dB+4+q]   = totf(((float*)&pb1)[q]);
            }
            __syncthreads();
            cur = nxt;
        }
    }
    __syncthreads();
    srs[tid] = rs;
    __syncthreads();
    float* Tb = g_tsum + (size_t)b*Ln*Dn;
    #pragma unroll
    for (int fm = 0; fm < 4; fm++) {
        #pragma unroll
        for (int rr = 0; rr < 2; rr++) {
            int i = i0 + wm + fm*16 + g + rr*8;
            int rl = i - i0;
            float rinv = 1.0f / (srs[2*rl] + srs[2*rl+1]);
            #pragma unroll
            for (int fn = 0; fn < 4; fn++) {
                int j = d0 + wn + fn*8 + th*2;
                float2 cv = *(const float2*)&Cb[(size_t)i*Dn + j];
                float2 pv = *(const float2*)&g_pe[i*Dn + j];
                float2 ov;
                ov.x = cv.x + pv.x + acc[fm][fn][rr*2+0]*rinv;
                ov.y = cv.y + pv.y + acc[fm][fn][rr*2+1]*rinv;
                *(float2*)&Tb[(size_t)i*Dn + j] = ov;
            }
        }
    }
}

// ---------------- 6) LN(tsum) + weighted mix ----------------------------------
__global__ __launch_bounds__(256)
void final_kernel(const float* __restrict__ wp,
                  const float* __restrict__ gt, const float* __restrict__ bt,
                  float* __restrict__ out) {
    __shared__ float red[8];
    int row = blockIdx.x;
    int t = row & (Ln - 1);
    int tid = threadIdx.x;
    int dA = tid, dB = tid + 256;
    const float* tp = g_tsum + (size_t)row*Dn;
    float v0 = tp[dA], v1 = tp[dB];
    float mu = blockReduce(v0 + v1, red) * (1.0f/Dn);
    float c0 = v0 - mu, c1 = v1 - mu;
    float var = blockReduce(c0*c0 + c1*c1, red) * (1.0f/Dn);
    float inv = rsqrtf(var + EPSf);
    float w0 = wp[0], w1 = wp[1], w2 = wp[2], w3 = wp[3];
    float mx = fmaxf(fmaxf(w0, w1), fmaxf(w2, w3));
    float e0 = expf(w0-mx), e1 = expf(w1-mx), e2 = expf(w2-mx), e3 = expf(w3-mx);
    float esum = 1.0f / (e0+e1+e2+e3);
    w0 = e0*esum; w1 = e1*esum; w2 = e2*esum; w3 = e3*esum;
    const float* cp = g_c + (size_t)row*Dn;
    float tpe0 = c0*inv*gt[dA] + bt[dA];
    float tpe1 = c1*inv*gt[dB] + bt[dB];
    out[(size_t)row*Dn + dA] = w0*cp[dA] + w1*g_pef[t*Dn+dA] + w2*g_pel[t*Dn+dA] + w3*tpe0;
    out[(size_t)row*Dn + dB] = w0*cp[dB] + w1*g_pef[t*Dn+dB] + w2*g_pel[t*Dn+dB] + w3*tpe1;
}

// ---------------- launch ------------------------------------------------------
extern "C" void kernel_launch(void* const* d_in, const int* in_sizes, int n_in,
                              void* d_out, int out_size) {
    const float* x          = (const float*)d_in[0];
    const float* conv_w     = (const float*)d_in[1];
    const float* conv_b     = (const float*)d_in[2];
    const float* pe_learned = (const float*)d_in[3];
    const float* wp         = (const float*)d_in[4];
    const float* gamma_c    = (const float*)d_in[5];
    const float* beta_c     = (const float*)d_in[6];
    const float* gamma_f    = (const float*)d_in[7];
    const float* beta_f     = (const float*)d_in[8];
    const float* gamma_l    = (const float*)d_in[9];
    const float* beta_l     = (const float*)d_in[10];
    const float* gamma_t    = (const float*)d_in[11];
    const float* beta_t     = (const float*)d_in[12];

    features_kernel<<<(Bn*Ln*Cn + 255)/256, 256>>>(x);
    conv_ln_kernel<<<dim3(Ln/TT, Bn), 256>>>(conv_w, conv_b, gamma_c, beta_c);
    pe_kernel<<<Ln, 256>>>(pe_learned, gamma_f, beta_f, gamma_l, beta_l);
    gram_kernel<<<dim3(136, Bn), 256>>>();
    sem_kernel<<<dim3(16, 4, Bn), 256>>>();
    final_kernel<<<Bn*Ln, 256>>>(wp, gamma_t, beta_t, (float*)d_out);
}

// round 10
// speedup vs baseline: 1.9620x; 1.5810x over previous
#include <cuda_runtime.h>
#include <math.h>

#define Bn 8
#define Ln 2048
#define Cn 7
#define Dn 512
#define Wn 24
#define NF 56
#define EPSf 1e-5f
#define TT 16
#define THRESH 1e-12f
#define DCUT 60.0f

// ---------------- scratch (device globals; allocation-free kernel_launch) ----
__device__ float g_xcomb[Bn*Ln*NF];
__device__ float g_wT[NF*3*Dn];          // transposed conv weights [f*3+k][d]
__device__ float g_c[(size_t)Bn*Ln*Dn];
__device__ float g_sq[Bn*Ln];
__device__ float g_sq160[Bn*Ln];
__device__ float g_sq256[Bn*Ln];
__device__ float g_sq384[Bn*Ln];
__device__ float g_pe[Ln*Dn];
__device__ float g_pef[Ln*Dn];
__device__ float g_pel[Ln*Dn];
__device__ float g_S[(size_t)Bn*Ln*Ln];
__device__ float g_tsum[(size_t)Bn*Ln*Dn];
__device__ int   g_flag32[Bn*16*64];     // per (stripe of 128 rows) x (32-col chunk) activity

// ---------------- helpers -----------------------------------------------------
__device__ __forceinline__ float totf(float x) {
    unsigned u;
    asm("cvt.rna.tf32.f32 %0, %1;" : "=r"(u) : "f"(x));
    return __uint_as_float(u);
}

__device__ __forceinline__ void mma_tf32(float* d, const unsigned* a, const unsigned* b) {
    asm volatile(
        "mma.sync.aligned.m16n8k8.row.col.f32.tf32.tf32.f32 "
        "{%0,%1,%2,%3}, {%4,%5,%6,%7}, {%8,%9}, {%0,%1,%2,%3};"
        : "+f"(d[0]), "+f"(d[1]), "+f"(d[2]), "+f"(d[3])
        : "r"(a[0]), "r"(a[1]), "r"(a[2]), "r"(a[3]), "r"(b[0]), "r"(b[1]));
}

__device__ __forceinline__ float blockReduce(float v, float* red) {
    #pragma unroll
    for (int o = 16; o; o >>= 1) v += __shfl_xor_sync(0xffffffffu, v, o);
    if ((threadIdx.x & 31) == 0) red[threadIdx.x >> 5] = v;
    __syncthreads();
    float s = red[0];
    #pragma unroll
    for (int i = 1; i < 8; i++) s += red[i];
    __syncthreads();
    return s;
}

// ---------------- 0) conv weight transpose ------------------------------------
__global__ __launch_bounds__(256)
void wtrans_kernel(const float* __restrict__ cw) {
    int idx = blockIdx.x * 256 + threadIdx.x;
    if (idx >= NF*3*Dn) return;
    int d = idx & (Dn-1);
    int f3k = idx >> 9;
    g_wT[idx] = cw[d*NF*3 + f3k];
}

// ---------------- 1) window stats + lags --------------------------------------
__global__ __launch_bounds__(256)
void features_kernel(const float* __restrict__ x) {
    int gid = blockIdx.x * blockDim.x + threadIdx.x;
    if (gid >= Bn*Ln*Cn) return;
    int ch = gid % Cn;
    int t  = (gid / Cn) % Ln;
    int b  = gid / (Cn*Ln);
    const float* xb = x + (size_t)b*Ln*Cn;
    float v[Wn];
    #pragma unroll
    for (int w = 0; w < Wn; w++) {
        int tt = t - (Wn-1) + w; tt = tt < 0 ? 0 : tt;
        v[w] = xb[tt*Cn + ch];
    }
    float s = 0.f, mx = v[0], mn = v[0];
    #pragma unroll
    for (int w = 0; w < Wn; w++) { s += v[w]; mx = fmaxf(mx, v[w]); mn = fminf(mn, v[w]); }
    float mean = s * (1.0f/Wn);
    float m2 = 0.f;
    #pragma unroll
    for (int w = 0; w < Wn; w++) { float d = v[w]-mean; m2 += d*d; }
    float sd = sqrtf(m2 * (1.0f/(Wn-1)));
    float xc = v[Wn-1];
    int t3 = t-3; t3 = t3 < 0 ? 0 : t3;
    int t5 = t-5; t5 = t5 < 0 ? 0 : t5;
    int t7 = t-7; t7 = t7 < 0 ? 0 : t7;
    float* o = g_xcomb + ((size_t)b*Ln + t)*NF;
    o[ch]      = xc;
    o[7  + ch] = mean;
    o[14 + ch] = mx;
    o[21 + ch] = mn;
    o[28 + ch] = sd;
    o[35 + ch] = xc - xb[t3*Cn + ch];
    o[42 + ch] = xc - xb[t5*Cn + ch];
    o[49 + ch] = xc - xb[t7*Cn + ch];
}

// ---------------- 2) circular conv1d(k=3) + bias + LN + partial sumsq ---------
__global__ __launch_bounds__(256)
void conv_ln_kernel(const float* __restrict__ conv_b,
                    const float* __restrict__ gamma_c, const float* __restrict__ beta_c) {
    __shared__ float sx[TT+2][NF];
    __shared__ float semb[TT][Dn];
    int b  = blockIdx.y;
    int t0 = blockIdx.x * TT;
    int tid = threadIdx.x;
    for (int i = tid; i < (TT+2)*NF; i += 256) {
        int r = i / NF, f = i - r*NF;
        int tt = (t0 - 1 + r + Ln) & (Ln - 1);
        sx[r][f] = g_xcomb[((size_t)b*Ln + tt)*NF + f];
    }
    __syncthreads();
    int d0 = tid * 2;
    float acc0[TT], acc1[TT];
    float bb0 = conv_b[d0], bb1 = conv_b[d0+1];
    #pragma unroll
    for (int t = 0; t < TT; t++) { acc0[t] = bb0; acc1[t] = bb1; }
    const float2* wtp = (const float2*)g_wT;   // [f*3+k][Dn] viewed as float2 pairs
    for (int f = 0; f < NF; f++) {
        float2 wk0 = wtp[(f*3+0)*(Dn/2) + tid];
        float2 wk1 = wtp[(f*3+1)*(Dn/2) + tid];
        float2 wk2 = wtp[(f*3+2)*(Dn/2) + tid];
        float sv[TT+2];
        #pragma unroll
        for (int r = 0; r < TT+2; r++) sv[r] = sx[r][f];
        #pragma unroll
        for (int t = 0; t < TT; t++) {
            acc0[t] += sv[t]*wk0.x + sv[t+1]*wk1.x + sv[t+2]*wk2.x;
            acc1[t] += sv[t]*wk0.y + sv[t+1]*wk1.y + sv[t+2]*wk2.y;
        }
    }
    #pragma unroll
    for (int t = 0; t < TT; t++) { semb[t][d0] = acc0[t]; semb[t][d0+1] = acc1[t]; }
    __syncthreads();
    int warp = tid >> 5, lane = tid & 31;
    for (int rr = warp; rr < TT; rr += 8) {
        float s = 0.f;
        for (int i = lane; i < Dn; i += 32) s += semb[rr][i];
        #pragma unroll
        for (int o = 16; o; o >>= 1) s += __shfl_xor_sync(0xffffffffu, s, o);
        float mu = s * (1.0f/Dn);
        float q = 0.f;
        for (int i = lane; i < Dn; i += 32) { float d = semb[rr][i]-mu; q += d*d; }
        #pragma unroll
        for (int o = 16; o; o >>= 1) q += __shfl_xor_sync(0xffffffffu, q, o);
        float inv = rsqrtf(q*(1.0f/Dn) + EPSf);
        int t = t0 + rr;
        float* cp = g_c + ((size_t)b*Ln + t)*Dn;
        float sq = 0.f, s160 = 0.f, s256 = 0.f, s384 = 0.f;
        for (int i = lane; i < Dn; i += 32) {
            float cv = (semb[rr][i]-mu)*inv*gamma_c[i] + beta_c[i];
            cp[i] = cv;
            float c2 = cv*cv;
            sq += c2;
            if (i < 160) s160 += c2;
            if (i < 256) s256 += c2;
            if (i < 384) s384 += c2;
        }
        #pragma unroll
        for (int o = 16; o; o >>= 1) {
            sq   += __shfl_xor_sync(0xffffffffu, sq, o);
            s160 += __shfl_xor_sync(0xffffffffu, s160, o);
            s256 += __shfl_xor_sync(0xffffffffu, s256, o);
            s384 += __shfl_xor_sync(0xffffffffu, s384, o);
        }
        if (lane == 0) {
            g_sq[b*Ln + t]    = sq;
            g_sq160[b*Ln + t] = s160;
            g_sq256[b*Ln + t] = s256;
            g_sq384[b*Ln + t] = s384;
        }
    }
}

// ---------------- 3) sinusoid PE + LN(pe) + LN(pe_learned) --------------------
__global__ __launch_bounds__(256)
void pe_kernel(const float* __restrict__ pe_learned,
               const float* __restrict__ gf, const float* __restrict__ bf,
               const float* __restrict__ gl, const float* __restrict__ bl) {
    __shared__ float red[8];
    int t = blockIdx.x;
    int tid = threadIdx.x;
    int dA = tid, dB = tid + 256;
    const float kdiv = -9.210340371976184f / (float)Dn;
    float divA = expf((float)(dA & ~1) * kdiv);
    float divB = expf((float)(dB & ~1) * kdiv);
    float sA, cA, sB, cB;
    sincosf((float)t * divA, &sA, &cA);
    sincosf((float)t * divB, &sB, &cB);
    float v0 = (dA & 1) ? cA : sA;
    float v1 = (dB & 1) ? cB : sB;
    g_pe[t*Dn + dA] = v0;
    g_pe[t*Dn + dB] = v1;
    float mu = blockReduce(v0 + v1, red) * (1.0f/Dn);
    float c0 = v0 - mu, c1 = v1 - mu;
    float var = blockReduce(c0*c0 + c1*c1, red) * (1.0f/Dn);
    float inv = rsqrtf(var + EPSf);
    g_pef[t*Dn + dA] = c0*inv*gf[dA] + bf[dA];
    g_pef[t*Dn + dB] = c1*inv*gf[dB] + bf[dB];
    float u0 = pe_learned[t*Dn + dA], u1 = pe_learned[t*Dn + dB];
    float mu2 = blockReduce(u0 + u1, red) * (1.0f/Dn);
    float e0 = u0 - mu2, e1 = u1 - mu2;
    float var2 = blockReduce(e0*e0 + e1*e1, red) * (1.0f/Dn);
    float inv2 = rsqrtf(var2 + EPSf);
    g_pel[t*Dn + dA] = e0*inv2*gl[dA] + bl[dA];
    g_pel[t*Dn + dB] = e1*inv2*gl[dB] + bl[dB];
}

// ---------------- 4) symmetric Gram (tf32 mma) + checkpoints + 32-chunk flags -
__global__ __launch_bounds__(256)
void gram_kernel() {
    __shared__ float As[2][128][20];
    __shared__ float Bs[2][128][20];
    __shared__ float redm[8];
    __shared__ float s_cgm[8];
    __shared__ float s_rgm[8][2];
    __shared__ int s_flag;
    int b = blockIdx.y;
    int r = blockIdx.x, ti = 0;
    while (r >= 16 - ti) { r -= 16 - ti; ti++; }
    int tj = ti + r;
    const float* Cb = g_c + (size_t)b*Ln*Dn;
    int i0 = ti*128, j0 = tj*128;
    int tid = threadIdx.x;
    int warp = tid >> 5, lane = tid & 31;
    int wm = (warp >> 2) * 64;
    int wn = (warp & 3) * 32;
    int g = lane >> 2, th = lane & 3;

    int lrow = tid >> 1, lk = (tid & 1) * 8;
    const float* Ag = Cb + (size_t)(i0 + lrow)*Dn + lk;
    const float* Bg = Cb + (size_t)(j0 + lrow)*Dn + lk;

    float acc[4][4][4];
    #pragma unroll
    for (int i = 0; i < 4; i++)
        #pragma unroll
        for (int j = 0; j < 4; j++)
            #pragma unroll
            for (int q = 0; q < 4; q++) acc[i][j][q] = 0.f;

    float4 pa0 = *(const float4*)(Ag);
    float4 pa1 = *(const float4*)(Ag + 4);
    float4 pb0 = *(const float4*)(Bg);
    float4 pb1 = *(const float4*)(Bg + 4);
    #pragma unroll
    for (int q = 0; q < 4; q++) {
        As[0][lrow][lk+q]   = totf(((float*)&pa0)[q]);
        As[0][lrow][lk+4+q] = totf(((float*)&pa1)[q]);
        Bs[0][lrow][lk+q]   = totf(((float*)&pb0)[q]);
        Bs[0][lrow][lk+4+q] = totf(((float*)&pb1)[q]);
    }
    __syncthreads();
    int cur = 0;
    for (int kt = 0; kt < 32; kt++) {
        if (kt < 31) {
            int ko = (kt+1)*16;
            pa0 = *(const float4*)(Ag + ko);
            pa1 = *(const float4*)(Ag + ko + 4);
            pb0 = *(const float4*)(Bg + ko);
            pb1 = *(const float4*)(Bg + ko + 4);
        }
        #pragma unroll
        for (int k8 = 0; k8 < 16; k8 += 8) {
            unsigned af[4][4], bf_[4][2];
            #pragma unroll
            for (int fm = 0; fm < 4; fm++) {
                const float* ap = &As[cur][wm + fm*16 + g][k8 + th];
                af[fm][0] = __float_as_uint(ap[0]);
                af[fm][1] = __float_as_uint(ap[8*20]);
                af[fm][2] = __float_as_uint(ap[4]);
                af[fm][3] = __float_as_uint(ap[8*20 + 4]);
            }
            #pragma unroll
            for (int fn = 0; fn < 4; fn++) {
                const float* bp = &Bs[cur][wn + fn*8 + g][k8 + th];
                bf_[fn][0] = __float_as_uint(bp[0]);
                bf_[fn][1] = __float_as_uint(bp[4]);
            }
            #pragma unroll
            for (int fm = 0; fm < 4; fm++)
                #pragma unroll
                for (int fn = 0; fn < 4; fn++)
                    mma_tf32(acc[fm][fn], af[fm], bf_[fn]);
        }
        if (ti != tj && (kt == 15 || kt == 23)) {
            // rigorous lower bound: dist >= sqK_i + sqK_j - 2*dotK  (tail >= 0)
            const float* sqp = (kt == 15) ? g_sq256 : g_sq384;
            float sqj2[4][2];
            #pragma unroll
            for (int fn = 0; fn < 4; fn++) {
                int j = j0 + wn + fn*8 + th*2;
                sqj2[fn][0] = sqp[b*Ln + j];
                sqj2[fn][1] = sqp[b*Ln + j + 1];
            }
            float mind = 1e30f;
            #pragma unroll
            for (int fm = 0; fm < 4; fm++) {
                #pragma unroll
                for (int rr = 0; rr < 2; rr++) {
                    int i = i0 + wm + fm*16 + g + rr*8;
                    float sqi2 = sqp[b*Ln + i];
                    #pragma unroll
                    for (int fn = 0; fn < 4; fn++) {
                        float d0v = sqi2 + sqj2[fn][0] - 2.0f*acc[fm][fn][rr*2+0];
                        float d1v = sqi2 + sqj2[fn][1] - 2.0f*acc[fm][fn][rr*2+1];
                        mind = fminf(mind, fminf(d0v, d1v));
                    }
                }
            }
            #pragma unroll
            for (int o = 16; o; o >>= 1) mind = fminf(mind, __shfl_xor_sync(0xffffffffu, mind, o));
            if (lane == 0) redm[warp] = mind;
            __syncthreads();
            if (tid == 0) {
                float m = redm[0];
                #pragma unroll
                for (int i = 1; i < 8; i++) m = fminf(m, redm[i]);
                s_flag = (m > DCUT) ? 1 : 0;
            }
            __syncthreads();
            if (s_flag) {
                if (tid == 0) {
                    int* f0 = g_flag32 + (b*16 + ti)*64 + tj*4;
                    int* f1 = g_flag32 + (b*16 + tj)*64 + ti*4;
                    #pragma unroll
                    for (int q = 0; q < 4; q++) { f0[q] = 0; f1[q] = 0; }
                }
                return;
            }
        }
        if (kt < 31) {
            int nxt = cur ^ 1;
            #pragma unroll
            for (int q = 0; q < 4; q++) {
                As[nxt][lrow][lk+q]   = totf(((float*)&pa0)[q]);
                As[nxt][lrow][lk+4+q] = totf(((float*)&pa1)[q]);
                Bs[nxt][lrow][lk+q]   = totf(((float*)&pb0)[q]);
                Bs[nxt][lrow][lk+4+q] = totf(((float*)&pb1)[q]);
            }
            __syncthreads();
            cur = nxt;
        }
    }
    float sqj[4][2];
    #pragma unroll
    for (int fn = 0; fn < 4; fn++) {
        int j = j0 + wn + fn*8 + th*2;
        sqj[fn][0] = g_sq[b*Ln + j];
        sqj[fn][1] = g_sq[b*Ln + j + 1];
    }
    float cgmax = 0.f, rg0 = 0.f, rg1 = 0.f;
    #pragma unroll
    for (int fm = 0; fm < 4; fm++) {
        #pragma unroll
        for (int rr = 0; rr < 2; rr++) {
            int i = i0 + wm + fm*16 + g + rr*8;
            float sqi = g_sq[b*Ln + i];
            #pragma unroll
            for (int fn = 0; fn < 4; fn++) {
                float d0v = fmaxf(sqi + sqj[fn][0] - 2.0f*acc[fm][fn][rr*2+0], 0.0f);
                float d1v = fmaxf(sqi + sqj[fn][1] - 2.0f*acc[fm][fn][rr*2+1], 0.0f);
                float s0 = __expf(-0.5f * d0v);
                float s1 = __expf(-0.5f * d1v);
                acc[fm][fn][rr*2+0] = s0;
                acc[fm][fn][rr*2+1] = s1;
                float m01 = fmaxf(s0, s1);
                cgmax = fmaxf(cgmax, m01);
                if (fm < 2) rg0 = fmaxf(rg0, m01); else rg1 = fmaxf(rg1, m01);
            }
        }
    }
    #pragma unroll
    for (int o = 16; o; o >>= 1) {
        cgmax = fmaxf(cgmax, __shfl_xor_sync(0xffffffffu, cgmax, o));
        rg0   = fmaxf(rg0,   __shfl_xor_sync(0xffffffffu, rg0, o));
        rg1   = fmaxf(rg1,   __shfl_xor_sync(0xffffffffu, rg1, o));
    }
    if (lane == 0) { s_cgm[warp] = cgmax; s_rgm[warp][0] = rg0; s_rgm[warp][1] = rg1; }
    __syncthreads();
    if (tid == 0) {
        float tilem = s_cgm[0];
        #pragma unroll
        for (int i = 1; i < 8; i++) tilem = fmaxf(tilem, s_cgm[i]);
        int act = (tilem > THRESH) ? 1 : 0;
        s_flag = act;
        int* f0 = g_flag32 + (b*16 + ti)*64 + tj*4;
        int* f1 = g_flag32 + (b*16 + tj)*64 + ti*4;
        if (act) {
            #pragma unroll
            for (int cg = 0; cg < 4; cg++)
                f0[cg] = (fmaxf(s_cgm[cg], s_cgm[4+cg]) > THRESH) ? 1 : 0;
            if (ti != tj) {
                #pragma unroll
                for (int h = 0; h < 2; h++)
                    #pragma unroll
                    for (int fh = 0; fh < 2; fh++) {
                        float m = s_rgm[h*4+0][fh];
                        m = fmaxf(m, s_rgm[h*4+1][fh]);
                        m = fmaxf(m, s_rgm[h*4+2][fh]);
                        m = fmaxf(m, s_rgm[h*4+3][fh]);
                        f1[h*2+fh] = (m > THRESH) ? 1 : 0;
                    }
            }
        } else {
            #pragma unroll
            for (int q = 0; q < 4; q++) { f0[q] = 0; if (ti != tj) f1[q] = 0; }
        }
    }
    __syncthreads();
    if (s_flag) {
        float* Sb = g_S + (size_t)b*Ln*Ln;
        #pragma unroll
        for (int fm = 0; fm < 4; fm++) {
            #pragma unroll
            for (int rr = 0; rr < 2; rr++) {
                int i = i0 + wm + fm*16 + g + rr*8;
                #pragma unroll
                for (int fn = 0; fn < 4; fn++) {
                    int j = j0 + wn + fn*8 + th*2;
                    float s0 = acc[fm][fn][rr*2+0];
                    float s1 = acc[fm][fn][rr*2+1];
                    *(float2*)&Sb[(size_t)i*Ln + j] = make_float2(s0, s1);
                    if (ti != tj) {
                        Sb[(size_t)j*Ln + i]     = s0;
                        Sb[(size_t)(j+1)*Ln + i] = s1;
                    }
                }
            }
        }
    }
}

// ---------------- 5) sem = S@c / rowsum over ACTIVE 32-chunks (rowsum fused) --
__global__ __launch_bounds__(256)
void sem_kernel() {
    __shared__ float As[2][128][20];
    __shared__ float Bs[2][16][136];
    __shared__ int s_list[64];
    __shared__ int s_nact;
    __shared__ float srs[256];
    int b  = blockIdx.z;
    int i0 = blockIdx.x * 128;
    int d0 = blockIdx.y * 128;
    const float* Cb = g_c + (size_t)b*Ln*Dn;
    const float* Sb = g_S + (size_t)b*Ln*Ln;
    int tid = threadIdx.x;
    int warp = tid >> 5, lane = tid & 31;
    int wm = (warp >> 2) * 64;
    int wn = (warp & 3) * 32;
    int g = lane >> 2, th = lane & 3;

    if (tid == 0) {
        const int* fl = g_flag32 + (b*16 + (i0 >> 7))*64;
        int n = 0;
        for (int c = 0; c < 64; c++)
            if (fl[c]) s_list[n++] = c;
        s_nact = n;
    }
    __syncthreads();
    int total = s_nact * 2;          // each 32-chunk = 2 BK16 steps

    int lrow = tid >> 1, lk = (tid & 1) * 8;
    int kB = tid >> 4, dB = (tid & 15) * 8;
    const float* Ag = Sb + (size_t)(i0 + lrow)*Ln + lk;
    const float* Bg = Cb + (size_t)kB*Dn + d0 + dB;

    float acc[4][4][4];
    #pragma unroll
    for (int i = 0; i < 4; i++)
        #pragma unroll
        for (int j = 0; j < 4; j++)
            #pragma unroll
            for (int q = 0; q < 4; q++) acc[i][j][q] = 0.f;

    float rs = 0.f;
    int k0 = s_list[0] * 32;
    float4 pa0 = *(const float4*)(Ag + k0);
    float4 pa1 = *(const float4*)(Ag + k0 + 4);
    float4 pb0 = *(const float4*)(Bg + (size_t)k0*Dn);
    float4 pb1 = *(const float4*)(Bg + (size_t)k0*Dn + 4);
    rs += (pa0.x+pa0.y+pa0.z+pa0.w) + (pa1.x+pa1.y+pa1.z+pa1.w);
    #pragma unroll
    for (int q = 0; q < 4; q++) {
        As[0][lrow][lk+q]   = totf(((float*)&pa0)[q]);
        As[0][lrow][lk+4+q] = totf(((float*)&pa1)[q]);
        Bs[0][kB][dB+q]     = totf(((float*)&pb0)[q]);
        Bs[0][kB][dB+4+q]   = totf(((float*)&pb1)[q]);
    }
    __syncthreads();
    int cur = 0;
    for (int st = 0; st < total; st++) {
        if (st + 1 < total) {
            int kn = s_list[(st+1) >> 1] * 32 + ((st+1) & 1) * 16;
            pa0 = *(const float4*)(Ag + kn);
            pa1 = *(const float4*)(Ag + kn + 4);
            pb0 = *(const float4*)(Bg + (size_t)kn*Dn);
            pb1 = *(const float4*)(Bg + (size_t)kn*Dn + 4);
        }
        #pragma unroll
        for (int k8 = 0; k8 < 16; k8 += 8) {
            unsigned af[4][4], bf_[4][2];
            #pragma unroll
            for (int fm = 0; fm < 4; fm++) {
                const float* ap = &As[cur][wm + fm*16 + g][k8 + th];
                af[fm][0] = __float_as_uint(ap[0]);
                af[fm][1] = __float_as_uint(ap[8*20]);
                af[fm][2] = __float_as_uint(ap[4]);
                af[fm][3] = __float_as_uint(ap[8*20 + 4]);
            }
            #pragma unroll
            for (int fn = 0; fn < 4; fn++) {
                const float* bp = &Bs[cur][k8 + th][wn + fn*8 + g];
                bf_[fn][0] = __float_as_uint(bp[0]);
                bf_[fn][1] = __float_as_uint(bp[4*136]);
            }
            #pragma unroll
            for (int fm = 0; fm < 4; fm++)
                #pragma unroll
                for (int fn = 0; fn < 4; fn++)
                    mma_tf32(acc[fm][fn], af[fm], bf_[fn]);
        }
        if (st + 1 < total) {
            int nxt = cur ^ 1;
            rs += (pa0.x+pa0.y+pa0.z+pa0.w) + (pa1.x+pa1.y+pa1.z+pa1.w);
            #pragma unroll
            for (int q = 0; q < 4; q++) {
                As[nxt][lrow][lk+q]   = totf(((float*)&pa0)[q]);
                As[nxt][lrow][lk+4+q] = totf(((float*)&pa1)[q]);
                Bs[nxt][kB][dB+q]     = totf(((float*)&pb0)[q]);
                Bs[nxt][kB][dB+4+q]   = totf(((float*)&pb1)[q]);
            }
            __syncthreads();
            cur = nxt;
        }
    }
    __syncthreads();
    srs[tid] = rs;
    __syncthreads();
    float* Tb = g_tsum + (size_t)b*Ln*Dn;
    #pragma unroll
    for (int fm = 0; fm < 4; fm++) {
        #pragma unroll
        for (int rr = 0; rr < 2; rr++) {
            int i = i0 + wm + fm*16 + g + rr*8;
            int rl = i - i0;
            float rinv = 1.0f / (srs[2*rl] + srs[2*rl+1]);
            #pragma unroll
            for (int fn = 0; fn < 4; fn++) {
                int j = d0 + wn + fn*8 + th*2;
                float2 cv = *(const float2*)&Cb[(size_t)i*Dn + j];
                float2 pv = *(const float2*)&g_pe[i*Dn + j];
                float2 ov;
                ov.x = cv.x + pv.x + acc[fm][fn][rr*2+0]*rinv;
                ov.y = cv.y + pv.y + acc[fm][fn][rr*2+1]*rinv;
                *(float2*)&Tb[(size_t)i*Dn + j] = ov;
            }
        }
    }
}

// ---------------- 6) LN(tsum) + weighted mix ----------------------------------
__global__ __launch_bounds__(256)
void final_kernel(const float* __restrict__ wp,
                  const float* __restrict__ gt, const float* __restrict__ bt,
                  float* __restrict__ out) {
    __shared__ float red[8];
    int row = blockIdx.x;
    int t = row & (Ln - 1);
    int tid = threadIdx.x;
    int dA = tid, dB = tid + 256;
    const float* tp = g_tsum + (size_t)row*Dn;
    float v0 = tp[dA], v1 = tp[dB];
    float mu = blockReduce(v0 + v1, red) * (1.0f/Dn);
    float c0 = v0 - mu, c1 = v1 - mu;
    float var = blockReduce(c0*c0 + c1*c1, red) * (1.0f/Dn);
    float inv = rsqrtf(var + EPSf);
    float w0 = wp[0], w1 = wp[1], w2 = wp[2], w3 = wp[3];
    float mx = fmaxf(fmaxf(w0, w1), fmaxf(w2, w3));
    float e0 = expf(w0-mx), e1 = expf(w1-mx), e2 = expf(w2-mx), e3 = expf(w3-mx);
    float esum = 1.0f / (e0+e1+e2+e3);
    w0 = e0*esum; w1 = e1*esum; w2 = e2*esum; w3 = e3*esum;
    const float* cp = g_c + (size_t)row*Dn;
    float tpe0 = c0*inv*gt[dA] + bt[dA];
    float tpe1 = c1*inv*gt[dB] + bt[dB];
    out[(size_t)row*Dn + dA] = w0*cp[dA] + w1*g_pef[t*Dn+dA] + w2*g_pel[t*Dn+dA] + w3*tpe0;
    out[(size_t)row*Dn + dB] = w0*cp[dB] + w1*g_pef[t*Dn+dB] + w2*g_pel[t*Dn+dB] + w3*tpe1;
}

// ---------------- launch ------------------------------------------------------
extern "C" void kernel_launch(void* const* d_in, const int* in_sizes, int n_in,
                              void* d_out, int out_size) {
    const float* x          = (const float*)d_in[0];
    const float* conv_w     = (const float*)d_in[1];
    const float* conv_b     = (const float*)d_in[2];
    const float* pe_learned = (const float*)d_in[3];
    const float* wp         = (const float*)d_in[4];
    const float* gamma_c    = (const float*)d_in[5];
    const float* beta_c     = (const float*)d_in[6];
    const float* gamma_f    = (const float*)d_in[7];
    const float* beta_f     = (const float*)d_in[8];
    const float* gamma_l    = (const float*)d_in[9];
    const float* beta_l     = (const float*)d_in[10];
    const float* gamma_t    = (const float*)d_in[11];
    const float* beta_t     = (const float*)d_in[12];

    wtrans_kernel<<<(NF*3*Dn + 255)/256, 256>>>(conv_w);
    features_kernel<<<(Bn*Ln*Cn + 255)/256, 256>>>(x);
    conv_ln_kernel<<<dim3(Ln/TT, Bn), 256>>>(conv_b, gamma_c, beta_c);
    pe_kernel<<<Ln, 256>>>(pe_learned, gamma_f, beta_f, gamma_l, beta_l);
    gram_kernel<<<dim3(136, Bn), 256>>>();
    sem_kernel<<<dim3(16, 4, Bn), 256>>>();
    final_kernel<<<Bn*Ln, 256>>>(wp, gamma_t, beta_t, (float*)d_out);
}

// round 11
// speedup vs baseline: 2.1618x; 1.1018x over previous
#include <cuda_runtime.h>
#include <math.h>

#define Bn 8
#define Ln 2048
#define Cn 7
#define Dn 512
#define Wn 24
#define NF 56
#define EPSf 1e-5f
#define TT 16
#define THRESH 1e-8f
#define DCUT 42.0f

// ---------------- scratch (device globals; allocation-free kernel_launch) ----
__device__ float g_xcomb[Bn*Ln*NF];
__device__ float g_wT[NF*3*Dn];          // transposed conv weights [f*3+k][d]
__device__ float g_c[(size_t)Bn*Ln*Dn];
__device__ float g_sq[Bn*Ln];
__device__ float g_sq96[Bn*Ln];
__device__ float g_sq160[Bn*Ln];
__device__ float g_sq256[Bn*Ln];
__device__ float g_pe[Ln*Dn];
__device__ float g_pef[Ln*Dn];
__device__ float g_pel[Ln*Dn];
__device__ float g_S[(size_t)Bn*Ln*Ln];
__device__ float g_tsum[(size_t)Bn*Ln*Dn];
__device__ int   g_flag32[Bn*16*64];     // per (stripe of 128 rows) x (32-col chunk) activity

// ---------------- helpers -----------------------------------------------------
__device__ __forceinline__ float totf(float x) {
    unsigned u;
    asm("cvt.rna.tf32.f32 %0, %1;" : "=r"(u) : "f"(x));
    return __uint_as_float(u);
}

__device__ __forceinline__ void mma_tf32(float* d, const unsigned* a, const unsigned* b) {
    asm volatile(
        "mma.sync.aligned.m16n8k8.row.col.f32.tf32.tf32.f32 "
        "{%0,%1,%2,%3}, {%4,%5,%6,%7}, {%8,%9}, {%0,%1,%2,%3};"
        : "+f"(d[0]), "+f"(d[1]), "+f"(d[2]), "+f"(d[3])
        : "r"(a[0]), "r"(a[1]), "r"(a[2]), "r"(a[3]), "r"(b[0]), "r"(b[1]));
}

__device__ __forceinline__ float blockReduce(float v, float* red) {
    #pragma unroll
    for (int o = 16; o; o >>= 1) v += __shfl_xor_sync(0xffffffffu, v, o);
    if ((threadIdx.x & 31) == 0) red[threadIdx.x >> 5] = v;
    __syncthreads();
    float s = red[0];
    #pragma unroll
    for (int i = 1; i < 8; i++) s += red[i];
    __syncthreads();
    return s;
}

// ---------------- 0) conv weight transpose ------------------------------------
__global__ __launch_bounds__(256)
void wtrans_kernel(const float* __restrict__ cw) {
    int idx = blockIdx.x * 256 + threadIdx.x;
    if (idx >= NF*3*Dn) return;
    int d = idx & (Dn-1);
    int f3k = idx >> 9;
    g_wT[idx] = cw[d*NF*3 + f3k];
}

// ---------------- 1) window stats + lags --------------------------------------
__global__ __launch_bounds__(256)
void features_kernel(const float* __restrict__ x) {
    int gid = blockIdx.x * blockDim.x + threadIdx.x;
    if (gid >= Bn*Ln*Cn) return;
    int ch = gid % Cn;
    int t  = (gid / Cn) % Ln;
    int b  = gid / (Cn*Ln);
    const float* xb = x + (size_t)b*Ln*Cn;
    float v[Wn];
    #pragma unroll
    for (int w = 0; w < Wn; w++) {
        int tt = t - (Wn-1) + w; tt = tt < 0 ? 0 : tt;
        v[w] = xb[tt*Cn + ch];
    }
    float s = 0.f, mx = v[0], mn = v[0];
    #pragma unroll
    for (int w = 0; w < Wn; w++) { s += v[w]; mx = fmaxf(mx, v[w]); mn = fminf(mn, v[w]); }
    float mean = s * (1.0f/Wn);
    float m2 = 0.f;
    #pragma unroll
    for (int w = 0; w < Wn; w++) { float d = v[w]-mean; m2 += d*d; }
    float sd = sqrtf(m2 * (1.0f/(Wn-1)));
    float xc = v[Wn-1];
    int t3 = t-3; t3 = t3 < 0 ? 0 : t3;
    int t5 = t-5; t5 = t5 < 0 ? 0 : t5;
    int t7 = t-7; t7 = t7 < 0 ? 0 : t7;
    float* o = g_xcomb + ((size_t)b*Ln + t)*NF;
    o[ch]      = xc;
    o[7  + ch] = mean;
    o[14 + ch] = mx;
    o[21 + ch] = mn;
    o[28 + ch] = sd;
    o[35 + ch] = xc - xb[t3*Cn + ch];
    o[42 + ch] = xc - xb[t5*Cn + ch];
    o[49 + ch] = xc - xb[t7*Cn + ch];
}

// ---------------- 2) circular conv1d(k=3) + bias + LN + partial sumsq ---------
__global__ __launch_bounds__(256)
void conv_ln_kernel(const float* __restrict__ conv_b,
                    const float* __restrict__ gamma_c, const float* __restrict__ beta_c) {
    __shared__ float sx[TT+2][NF];
    __shared__ float semb[TT][Dn];
    int b  = blockIdx.y;
    int t0 = blockIdx.x * TT;
    int tid = threadIdx.x;
    for (int i = tid; i < (TT+2)*NF; i += 256) {
        int r = i / NF, f = i - r*NF;
        int tt = (t0 - 1 + r + Ln) & (Ln - 1);
        sx[r][f] = g_xcomb[((size_t)b*Ln + tt)*NF + f];
    }
    __syncthreads();
    int d0 = tid * 2;
    float acc0[TT], acc1[TT];
    float bb0 = conv_b[d0], bb1 = conv_b[d0+1];
    #pragma unroll
    for (int t = 0; t < TT; t++) { acc0[t] = bb0; acc1[t] = bb1; }
    const float2* wtp = (const float2*)g_wT;   // [f*3+k][Dn] viewed as float2 pairs
    for (int f = 0; f < NF; f++) {
        float2 wk0 = wtp[(f*3+0)*(Dn/2) + tid];
        float2 wk1 = wtp[(f*3+1)*(Dn/2) + tid];
        float2 wk2 = wtp[(f*3+2)*(Dn/2) + tid];
        float sv[TT+2];
        #pragma unroll
        for (int r = 0; r < TT+2; r++) sv[r] = sx[r][f];
        #pragma unroll
        for (int t = 0; t < TT; t++) {
            acc0[t] += sv[t]*wk0.x + sv[t+1]*wk1.x + sv[t+2]*wk2.x;
            acc1[t] += sv[t]*wk0.y + sv[t+1]*wk1.y + sv[t+2]*wk2.y;
        }
    }
    #pragma unroll
    for (int t = 0; t < TT; t++) { semb[t][d0] = acc0[t]; semb[t][d0+1] = acc1[t]; }
    __syncthreads();
    int warp = tid >> 5, lane = tid & 31;
    for (int rr = warp; rr < TT; rr += 8) {
        float s = 0.f;
        for (int i = lane; i < Dn; i += 32) s += semb[rr][i];
        #pragma unroll
        for (int o = 16; o; o >>= 1) s += __shfl_xor_sync(0xffffffffu, s, o);
        float mu = s * (1.0f/Dn);
        float q = 0.f;
        for (int i = lane; i < Dn; i += 32) { float d = semb[rr][i]-mu; q += d*d; }
        #pragma unroll
        for (int o = 16; o; o >>= 1) q += __shfl_xor_sync(0xffffffffu, q, o);
        float inv = rsqrtf(q*(1.0f/Dn) + EPSf);
        int t = t0 + rr;
        float* cp = g_c + ((size_t)b*Ln + t)*Dn;
        float sq = 0.f, s96 = 0.f, s160 = 0.f, s256 = 0.f;
        for (int i = lane; i < Dn; i += 32) {
            float cv = (semb[rr][i]-mu)*inv*gamma_c[i] + beta_c[i];
            cp[i] = cv;
            float c2 = cv*cv;
            sq += c2;
            if (i < 96)  s96  += c2;
            if (i < 160) s160 += c2;
            if (i < 256) s256 += c2;
        }
        #pragma unroll
        for (int o = 16; o; o >>= 1) {
            sq   += __shfl_xor_sync(0xffffffffu, sq, o);
            s96  += __shfl_xor_sync(0xffffffffu, s96, o);
            s160 += __shfl_xor_sync(0xffffffffu, s160, o);
            s256 += __shfl_xor_sync(0xffffffffu, s256, o);
        }
        if (lane == 0) {
            g_sq[b*Ln + t]    = sq;
            g_sq96[b*Ln + t]  = s96;
            g_sq160[b*Ln + t] = s160;
            g_sq256[b*Ln + t] = s256;
        }
    }
}

// ---------------- 3) sinusoid PE + LN(pe) + LN(pe_learned) --------------------
__global__ __launch_bounds__(256)
void pe_kernel(const float* __restrict__ pe_learned,
               const float* __restrict__ gf, const float* __restrict__ bf,
               const float* __restrict__ gl, const float* __restrict__ bl) {
    __shared__ float red[8];
    int t = blockIdx.x;
    int tid = threadIdx.x;
    int dA = tid, dB = tid + 256;
    const float kdiv = -9.210340371976184f / (float)Dn;
    float divA = expf((float)(dA & ~1) * kdiv);
    float divB = expf((float)(dB & ~1) * kdiv);
    float sA, cA, sB, cB;
    sincosf((float)t * divA, &sA, &cA);
    sincosf((float)t * divB, &sB, &cB);
    float v0 = (dA & 1) ? cA : sA;
    float v1 = (dB & 1) ? cB : sB;
    g_pe[t*Dn + dA] = v0;
    g_pe[t*Dn + dB] = v1;
    float mu = blockReduce(v0 + v1, red) * (1.0f/Dn);
    float c0 = v0 - mu, c1 = v1 - mu;
    float var = blockReduce(c0*c0 + c1*c1, red) * (1.0f/Dn);
    float inv = rsqrtf(var + EPSf);
    g_pef[t*Dn + dA] = c0*inv*gf[dA] + bf[dA];
    g_pef[t*Dn + dB] = c1*inv*gf[dB] + bf[dB];
    float u0 = pe_learned[t*Dn + dA], u1 = pe_learned[t*Dn + dB];
    float mu2 = blockReduce(u0 + u1, red) * (1.0f/Dn);
    float e0 = u0 - mu2, e1 = u1 - mu2;
    float var2 = blockReduce(e0*e0 + e1*e1, red) * (1.0f/Dn);
    float inv2 = rsqrtf(var2 + EPSf);
    g_pel[t*Dn + dA] = e0*inv2*gl[dA] + bl[dA];
    g_pel[t*Dn + dB] = e1*inv2*gl[dB] + bl[dB];
}

// ---------------- 4) symmetric Gram (tf32 mma) + checkpoint ladder ------------
// diag-major tile order: expensive near-diagonal tiles launch first
__global__ __launch_bounds__(256)
void gram_kernel() {
    __shared__ float As[2][128][20];
    __shared__ float Bs[2][128][20];
    __shared__ float redm[8];
    __shared__ float s_cgm[8];
    __shared__ float s_rgm[8][2];
    __shared__ int s_flag;
    int b = blockIdx.y;
    int rr_ = blockIdx.x, dia = 0;
    while (rr_ >= 16 - dia) { rr_ -= 16 - dia; dia++; }
    int ti = rr_, tj = rr_ + dia;
    const float* Cb = g_c + (size_t)b*Ln*Dn;
    int i0 = ti*128, j0 = tj*128;
    int tid = threadIdx.x;
    int warp = tid >> 5, lane = tid & 31;
    int wm = (warp >> 2) * 64;
    int wn = (warp & 3) * 32;
    int g = lane >> 2, th = lane & 3;

    int lrow = tid >> 1, lk = (tid & 1) * 8;
    const float* Ag = Cb + (size_t)(i0 + lrow)*Dn + lk;
    const float* Bg = Cb + (size_t)(j0 + lrow)*Dn + lk;

    float acc[4][4][4];
    #pragma unroll
    for (int i = 0; i < 4; i++)
        #pragma unroll
        for (int j = 0; j < 4; j++)
            #pragma unroll
            for (int q = 0; q < 4; q++) acc[i][j][q] = 0.f;

    float4 pa0 = *(const float4*)(Ag);
    float4 pa1 = *(const float4*)(Ag + 4);
    float4 pb0 = *(const float4*)(Bg);
    float4 pb1 = *(const float4*)(Bg + 4);
    #pragma unroll
    for (int q = 0; q < 4; q++) {
        As[0][lrow][lk+q]   = totf(((float*)&pa0)[q]);
        As[0][lrow][lk+4+q] = totf(((float*)&pa1)[q]);
        Bs[0][lrow][lk+q]   = totf(((float*)&pb0)[q]);
        Bs[0][lrow][lk+4+q] = totf(((float*)&pb1)[q]);
    }
    __syncthreads();
    int cur = 0;
    for (int kt = 0; kt < 32; kt++) {
        if (kt < 31) {
            int ko = (kt+1)*16;
            pa0 = *(const float4*)(Ag + ko);
            pa1 = *(const float4*)(Ag + ko + 4);
            pb0 = *(const float4*)(Bg + ko);
            pb1 = *(const float4*)(Bg + ko + 4);
        }
        #pragma unroll
        for (int k8 = 0; k8 < 16; k8 += 8) {
            unsigned af[4][4], bf_[4][2];
            #pragma unroll
            for (int fm = 0; fm < 4; fm++) {
                const float* ap = &As[cur][wm + fm*16 + g][k8 + th];
                af[fm][0] = __float_as_uint(ap[0]);
                af[fm][1] = __float_as_uint(ap[8*20]);
                af[fm][2] = __float_as_uint(ap[4]);
                af[fm][3] = __float_as_uint(ap[8*20 + 4]);
            }
            #pragma unroll
            for (int fn = 0; fn < 4; fn++) {
                const float* bp = &Bs[cur][wn + fn*8 + g][k8 + th];
                bf_[fn][0] = __float_as_uint(bp[0]);
                bf_[fn][1] = __float_as_uint(bp[4]);
            }
            #pragma unroll
            for (int fm = 0; fm < 4; fm++)
                #pragma unroll
                for (int fn = 0; fn < 4; fn++)
                    mma_tf32(acc[fm][fn], af[fm], bf_[fn]);
        }
        if (ti != tj && (kt == 5 || kt == 9 || kt == 15)) {
            // rigorous lower bound: dist >= sqK_i + sqK_j - 2*dotK  (tail >= 0)
            const float* sqp = (kt == 5) ? g_sq96 : (kt == 9) ? g_sq160 : g_sq256;
            float sqj2[4][2];
            #pragma unroll
            for (int fn = 0; fn < 4; fn++) {
                int j = j0 + wn + fn*8 + th*2;
                sqj2[fn][0] = sqp[b*Ln + j];
                sqj2[fn][1] = sqp[b*Ln + j + 1];
            }
            float mind = 1e30f;
            #pragma unroll
            for (int fm = 0; fm < 4; fm++) {
                #pragma unroll
                for (int rr = 0; rr < 2; rr++) {
                    int i = i0 + wm + fm*16 + g + rr*8;
                    float sqi2 = sqp[b*Ln + i];
                    #pragma unroll
                    for (int fn = 0; fn < 4; fn++) {
                        float d0v = sqi2 + sqj2[fn][0] - 2.0f*acc[fm][fn][rr*2+0];
                        float d1v = sqi2 + sqj2[fn][1] - 2.0f*acc[fm][fn][rr*2+1];
                        mind = fminf(mind, fminf(d0v, d1v));
                    }
                }
            }
            #pragma unroll
            for (int o = 16; o; o >>= 1) mind = fminf(mind, __shfl_xor_sync(0xffffffffu, mind, o));
            if (lane == 0) redm[warp] = mind;
            __syncthreads();
            if (tid == 0) {
                float m = redm[0];
                #pragma unroll
                for (int i = 1; i < 8; i++) m = fminf(m, redm[i]);
                s_flag = (m > DCUT) ? 1 : 0;
            }
            __syncthreads();
            if (s_flag) {
                if (tid == 0) {
                    int* f0 = g_flag32 + (b*16 + ti)*64 + tj*4;
                    int* f1 = g_flag32 + (b*16 + tj)*64 + ti*4;
                    #pragma unroll
                    for (int q = 0; q < 4; q++) { f0[q] = 0; f1[q] = 0; }
                }
                return;
            }
        }
        if (kt < 31) {
            int nxt = cur ^ 1;
            #pragma unroll
            for (int q = 0; q < 4; q++) {
                As[nxt][lrow][lk+q]   = totf(((float*)&pa0)[q]);
                As[nxt][lrow][lk+4+q] = totf(((float*)&pa1)[q]);
                Bs[nxt][lrow][lk+q]   = totf(((float*)&pb0)[q]);
                Bs[nxt][lrow][lk+4+q] = totf(((float*)&pb1)[q]);
            }
            __syncthreads();
            cur = nxt;
        }
    }
    float sqj[4][2];
    #pragma unroll
    for (int fn = 0; fn < 4; fn++) {
        int j = j0 + wn + fn*8 + th*2;
        sqj[fn][0] = g_sq[b*Ln + j];
        sqj[fn][1] = g_sq[b*Ln + j + 1];
    }
    float cgmax = 0.f, rg0 = 0.f, rg1 = 0.f;
    #pragma unroll
    for (int fm = 0; fm < 4; fm++) {
        #pragma unroll
        for (int rr = 0; rr < 2; rr++) {
            int i = i0 + wm + fm*16 + g + rr*8;
            float sqi = g_sq[b*Ln + i];
            #pragma unroll
            for (int fn = 0; fn < 4; fn++) {
                float d0v = fmaxf(sqi + sqj[fn][0] - 2.0f*acc[fm][fn][rr*2+0], 0.0f);
                float d1v = fmaxf(sqi + sqj[fn][1] - 2.0f*acc[fm][fn][rr*2+1], 0.0f);
                float s0 = __expf(-0.5f * d0v);
                float s1 = __expf(-0.5f * d1v);
                acc[fm][fn][rr*2+0] = s0;
                acc[fm][fn][rr*2+1] = s1;
                float m01 = fmaxf(s0, s1);
                cgmax = fmaxf(cgmax, m01);
                if (fm < 2) rg0 = fmaxf(rg0, m01); else rg1 = fmaxf(rg1, m01);
            }
        }
    }
    #pragma unroll
    for (int o = 16; o; o >>= 1) {
        cgmax = fmaxf(cgmax, __shfl_xor_sync(0xffffffffu, cgmax, o));
        rg0   = fmaxf(rg0,   __shfl_xor_sync(0xffffffffu, rg0, o));
        rg1   = fmaxf(rg1,   __shfl_xor_sync(0xffffffffu, rg1, o));
    }
    if (lane == 0) { s_cgm[warp] = cgmax; s_rgm[warp][0] = rg0; s_rgm[warp][1] = rg1; }
    __syncthreads();
    if (tid == 0) {
        float tilem = s_cgm[0];
        #pragma unroll
        for (int i = 1; i < 8; i++) tilem = fmaxf(tilem, s_cgm[i]);
        int act = (tilem > THRESH) ? 1 : 0;
        s_flag = act;
        int* f0 = g_flag32 + (b*16 + ti)*64 + tj*4;
        int* f1 = g_flag32 + (b*16 + tj)*64 + ti*4;
        if (act) {
            #pragma unroll
            for (int cg = 0; cg < 4; cg++)
                f0[cg] = (fmaxf(s_cgm[cg], s_cgm[4+cg]) > THRESH) ? 1 : 0;
            if (ti != tj) {
                #pragma unroll
                for (int h = 0; h < 2; h++)
                    #pragma unroll
                    for (int fh = 0; fh < 2; fh++) {
                        float m = s_rgm[h*4+0][fh];
                        m = fmaxf(m, s_rgm[h*4+1][fh]);
                        m = fmaxf(m, s_rgm[h*4+2][fh]);
                        m = fmaxf(m, s_rgm[h*4+3][fh]);
                        f1[h*2+fh] = (m > THRESH) ? 1 : 0;
                    }
            }
        } else {
            #pragma unroll
            for (int q = 0; q < 4; q++) { f0[q] = 0; if (ti != tj) f1[q] = 0; }
        }
    }
    __syncthreads();
    if (s_flag) {
        float* Sb = g_S + (size_t)b*Ln*Ln;
        #pragma unroll
        for (int fm = 0; fm < 4; fm++) {
            #pragma unroll
            for (int rr = 0; rr < 2; rr++) {
                int i = i0 + wm + fm*16 + g + rr*8;
                #pragma unroll
                for (int fn = 0; fn < 4; fn++) {
                    int j = j0 + wn + fn*8 + th*2;
                    float s0 = acc[fm][fn][rr*2+0];
                    float s1 = acc[fm][fn][rr*2+1];
                    *(float2*)&Sb[(size_t)i*Ln + j] = make_float2(s0, s1);
                    if (ti != tj) {
                        Sb[(size_t)j*Ln + i]     = s0;
                        Sb[(size_t)(j+1)*Ln + i] = s1;
                    }
                }
            }
        }
    }
}

// ---------------- 5) sem = S@c / rowsum over ACTIVE 32-chunks (rowsum fused) --
__global__ __launch_bounds__(256)
void sem_kernel() {
    __shared__ float As[2][128][20];
    __shared__ float Bs[2][16][136];
    __shared__ int s_list[64];
    __shared__ int s_nact;
    __shared__ float srs[256];
    int b  = blockIdx.z;
    int i0 = blockIdx.x * 128;
    int d0 = blockIdx.y * 128;
    const float* Cb = g_c + (size_t)b*Ln*Dn;
    const float* Sb = g_S + (size_t)b*Ln*Ln;
    int tid = threadIdx.x;
    int warp = tid >> 5, lane = tid & 31;
    int wm = (warp >> 2) * 64;
    int wn = (warp & 3) * 32;
    int g = lane >> 2, th = lane & 3;

    if (tid == 0) {
        const int* fl = g_flag32 + (b*16 + (i0 >> 7))*64;
        int n = 0;
        for (int c = 0; c < 64; c++)
            if (fl[c]) s_list[n++] = c;
        s_nact = n;
    }
    __syncthreads();
    int total = s_nact * 2;          // each 32-chunk = 2 BK16 steps

    int lrow = tid >> 1, lk = (tid & 1) * 8;
    int kB = tid >> 4, dB = (tid & 15) * 8;
    const float* Ag = Sb + (size_t)(i0 + lrow)*Ln + lk;
    const float* Bg = Cb + (size_t)kB*Dn + d0 + dB;

    float acc[4][4][4];
    #pragma unroll
    for (int i = 0; i < 4; i++)
        #pragma unroll
        for (int j = 0; j < 4; j++)
            #pragma unroll
            for (int q = 0; q < 4; q++) acc[i][j][q] = 0.f;

    float rs = 0.f;
    int k0 = s_list[0] * 32;
    float4 pa0 = *(const float4*)(Ag + k0);
    float4 pa1 = *(const float4*)(Ag + k0 + 4);
    float4 pb0 = *(const float4*)(Bg + (size_t)k0*Dn);
    float4 pb1 = *(const float4*)(Bg + (size_t)k0*Dn + 4);
    rs += (pa0.x+pa0.y+pa0.z+pa0.w) + (pa1.x+pa1.y+pa1.z+pa1.w);
    #pragma unroll
    for (int q = 0; q < 4; q++) {
        As[0][lrow][lk+q]   = totf(((float*)&pa0)[q]);
        As[0][lrow][lk+4+q] = totf(((float*)&pa1)[q]);
        Bs[0][kB][dB+q]     = totf(((float*)&pb0)[q]);
        Bs[0][kB][dB+4+q]   = totf(((float*)&pb1)[q]);
    }
    __syncthreads();
    int cur = 0;
    for (int st = 0; st < total; st++) {
        if (st + 1 < total) {
            int kn = s_list[(st+1) >> 1] * 32 + ((st+1) & 1) * 16;
            pa0 = *(const float4*)(Ag + kn);
            pa1 = *(const float4*)(Ag + kn + 4);
            pb0 = *(const float4*)(Bg + (size_t)kn*Dn);
            pb1 = *(const float4*)(Bg + (size_t)kn*Dn + 4);
        }
        #pragma unroll
        for (int k8 = 0; k8 < 16; k8 += 8) {
            unsigned af[4][4], bf_[4][2];
            #pragma unroll
            for (int fm = 0; fm < 4; fm++) {
                const float* ap = &As[cur][wm + fm*16 + g][k8 + th];
                af[fm][0] = __float_as_uint(ap[0]);
                af[fm][1] = __float_as_uint(ap[8*20]);
                af[fm][2] = __float_as_uint(ap[4]);
                af[fm][3] = __float_as_uint(ap[8*20 + 4]);
            }
            #pragma unroll
            for (int fn = 0; fn < 4; fn++) {
                const float* bp = &Bs[cur][k8 + th][wn + fn*8 + g];
                bf_[fn][0] = __float_as_uint(bp[0]);
                bf_[fn][1] = __float_as_uint(bp[4*136]);
            }
            #pragma unroll
            for (int fm = 0; fm < 4; fm++)
                #pragma unroll
                for (int fn = 0; fn < 4; fn++)
                    mma_tf32(acc[fm][fn], af[fm], bf_[fn]);
        }
        if (st + 1 < total) {
            int nxt = cur ^ 1;
            rs += (pa0.x+pa0.y+pa0.z+pa0.w) + (pa1.x+pa1.y+pa1.z+pa1.w);
            #pragma unroll
            for (int q = 0; q < 4; q++) {
                As[nxt][lrow][lk+q]   = totf(((float*)&pa0)[q]);
                As[nxt][lrow][lk+4+q] = totf(((float*)&pa1)[q]);
                Bs[nxt][kB][dB+q]     = totf(((float*)&pb0)[q]);
                Bs[nxt][kB][dB+4+q]   = totf(((float*)&pb1)[q]);
            }
            __syncthreads();
            cur = nxt;
        }
    }
    __syncthreads();
    srs[tid] = rs;
    __syncthreads();
    float* Tb = g_tsum + (size_t)b*Ln*Dn;
    #pragma unroll
    for (int fm = 0; fm < 4; fm++) {
        #pragma unroll
        for (int rr = 0; rr < 2; rr++) {
            int i = i0 + wm + fm*16 + g + rr*8;
            int rl = i - i0;
            float rinv = 1.0f / (srs[2*rl] + srs[2*rl+1]);
            #pragma unroll
            for (int fn = 0; fn < 4; fn++) {
                int j = d0 + wn + fn*8 + th*2;
                float2 cv = *(const float2*)&Cb[(size_t)i*Dn + j];
                float2 pv = *(const float2*)&g_pe[i*Dn + j];
                float2 ov;
                ov.x = cv.x + pv.x + acc[fm][fn][rr*2+0]*rinv;
                ov.y = cv.y + pv.y + acc[fm][fn][rr*2+1]*rinv;
                *(float2*)&Tb[(size_t)i*Dn + j] = ov;
            }
        }
    }
}

// ---------------- 6) LN(tsum) + weighted mix ----------------------------------
__global__ __launch_bounds__(256)
void final_kernel(const float* __restrict__ wp,
                  const float* __restrict__ gt, const float* __restrict__ bt,
                  float* __restrict__ out) {
    __shared__ float red[8];
    int row = blockIdx.x;
    int t = row & (Ln - 1);
    int tid = threadIdx.x;
    int dA = tid, dB = tid + 256;
    const float* tp = g_tsum + (size_t)row*Dn;
    float v0 = tp[dA], v1 = tp[dB];
    float mu = blockReduce(v0 + v1, red) * (1.0f/Dn);
    float c0 = v0 - mu, c1 = v1 - mu;
    float var = blockReduce(c0*c0 + c1*c1, red) * (1.0f/Dn);
    float inv = rsqrtf(var + EPSf);
    float w0 = wp[0], w1 = wp[1], w2 = wp[2], w3 = wp[3];
    float mx = fmaxf(fmaxf(w0, w1), fmaxf(w2, w3));
    float e0 = expf(w0-mx), e1 = expf(w1-mx), e2 = expf(w2-mx), e3 = expf(w3-mx);
    float esum = 1.0f / (e0+e1+e2+e3);
    w0 = e0*esum; w1 = e1*esum; w2 = e2*esum; w3 = e3*esum;
    const float* cp = g_c + (size_t)row*Dn;
    float tpe0 = c0*inv*gt[dA] + bt[dA];
    float tpe1 = c1*inv*gt[dB] + bt[dB];
    out[(size_t)row*Dn + dA] = w0*cp[dA] + w1*g_pef[t*Dn+dA] + w2*g_pel[t*Dn+dA] + w3*tpe0;
    out[(size_t)row*Dn + dB] = w0*cp[dB] + w1*g_pef[t*Dn+dB] + w2*g_pel[t*Dn+dB] + w3*tpe1;
}

// ---------------- launch ------------------------------------------------------
extern "C" void kernel_launch(void* const* d_in, const int* in_sizes, int n_in,
                              void* d_out, int out_size) {
    const float* x          = (const float*)d_in[0];
    const float* conv_w     = (const float*)d_in[1];
    const float* conv_b     = (const float*)d_in[2];
    const float* pe_learned = (const float*)d_in[3];
    const float* wp         = (const float*)d_in[4];
    const float* gamma_c    = (const float*)d_in[5];
    const float* beta_c     = (const float*)d_in[6];
    const float* gamma_f    = (const float*)d_in[7];
    const float* beta_f     = (const float*)d_in[8];
    const float* gamma_l    = (const float*)d_in[9];
    const float* beta_l     = (const float*)d_in[10];
    const float* gamma_t    = (const float*)d_in[11];
    const float* beta_t     = (const float*)d_in[12];

    wtrans_kernel<<<(NF*3*Dn + 255)/256, 256>>>(conv_w);
    features_kernel<<<(Bn*Ln*Cn + 255)/256, 256>>>(x);
    conv_ln_kernel<<<dim3(Ln/TT, Bn), 256>>>(conv_b, gamma_c, beta_c);
    pe_kernel<<<Ln, 256>>>(pe_learned, gamma_f, beta_f, gamma_l, beta_l);
    gram_kernel<<<dim3(136, Bn), 256>>>();
    sem_kernel<<<dim3(16, 4, Bn), 256>>>();
    final_kernel<<<Bn*Ln, 256>>>(wp, gamma_t, beta_t, (float*)d_out);
}

// round 12
// speedup vs baseline: 2.3269x; 1.0764x over previous
#include <cuda_runtime.h>
#include <math.h>

#define Bn 8
#define Ln 2048
#define Cn 7
#define Dn 512
#define Wn 24
#define NF 56
#define EPSf 1e-5f
#define TT 16
#define THRESH 1e-8f
#define DCUT 42.0f

// ---------------- scratch (device globals; allocation-free kernel_launch) ----
__device__ float g_xcomb[Bn*Ln*NF];
__device__ float g_wT[NF*3*Dn];          // transposed conv weights [f*3+k][d]
__device__ float g_c[(size_t)Bn*Ln*Dn];
__device__ float g_sq[Bn*Ln];
__device__ float g_sq96[Bn*Ln];
__device__ float g_sq160[Bn*Ln];
__device__ float g_sq256[Bn*Ln];
__device__ float g_pe[Ln*Dn];
__device__ float g_pef[Ln*Dn];
__device__ float g_pel[Ln*Dn];
__device__ float g_S[(size_t)Bn*Ln*Ln];
__device__ int   g_flag32[Bn*16*64];     // per (stripe of 128 rows) x (32-col chunk) activity

// ---------------- helpers -----------------------------------------------------
__device__ __forceinline__ float totf(float x) {
    unsigned u;
    asm("cvt.rna.tf32.f32 %0, %1;" : "=r"(u) : "f"(x));
    return __uint_as_float(u);
}

__device__ __forceinline__ void mma_tf32(float* d, const unsigned* a, const unsigned* b) {
    asm volatile(
        "mma.sync.aligned.m16n8k8.row.col.f32.tf32.tf32.f32 "
        "{%0,%1,%2,%3}, {%4,%5,%6,%7}, {%8,%9}, {%0,%1,%2,%3};"
        : "+f"(d[0]), "+f"(d[1]), "+f"(d[2]), "+f"(d[3])
        : "r"(a[0]), "r"(a[1]), "r"(a[2]), "r"(a[3]), "r"(b[0]), "r"(b[1]));
}

__device__ __forceinline__ float blockReduce(float v, float* red) {
    #pragma unroll
    for (int o = 16; o; o >>= 1) v += __shfl_xor_sync(0xffffffffu, v, o);
    if ((threadIdx.x & 31) == 0) red[threadIdx.x >> 5] = v;
    __syncthreads();
    float s = red[0];
    #pragma unroll
    for (int i = 1; i < 8; i++) s += red[i];
    __syncthreads();
    return s;
}

// ---------------- 0) conv weight transpose ------------------------------------
__global__ __launch_bounds__(256)
void wtrans_kernel(const float* __restrict__ cw) {
    int idx = blockIdx.x * 256 + threadIdx.x;
    if (idx >= NF*3*Dn) return;
    int d = idx & (Dn-1);
    int f3k = idx >> 9;
    g_wT[idx] = cw[d*NF*3 + f3k];
}

// ---------------- 1) window stats + lags (smem-tiled) -------------------------
__global__ __launch_bounds__(256)
void features_kernel(const float* __restrict__ x) {
    __shared__ float sxf[152][Cn];
    int b  = blockIdx.y;
    int t0 = blockIdx.x * 128;
    int tid = threadIdx.x;
    const float* xb = x + (size_t)b*Ln*Cn;
    for (int i = tid; i < 151*Cn; i += 256) {
        int r = i / Cn, ch = i - r*Cn;
        int tt = t0 - 23 + r; tt = tt < 0 ? 0 : tt;
        sxf[r][ch] = xb[tt*Cn + ch];
    }
    __syncthreads();
    for (int i = tid; i < 128*Cn; i += 256) {
        int tl = i / Cn, ch = i - tl*Cn;
        float v[Wn];
        #pragma unroll
        for (int w = 0; w < Wn; w++) v[w] = sxf[tl + w][ch];
        float s = 0.f, mx = v[0], mn = v[0];
        #pragma unroll
        for (int w = 0; w < Wn; w++) { s += v[w]; mx = fmaxf(mx, v[w]); mn = fminf(mn, v[w]); }
        float mean = s * (1.0f/Wn);
        float m2 = 0.f;
        #pragma unroll
        for (int w = 0; w < Wn; w++) { float d = v[w]-mean; m2 += d*d; }
        float sd = sqrtf(m2 * (1.0f/(Wn-1)));
        float xc = v[Wn-1];
        int t = t0 + tl;
        float* o = g_xcomb + ((size_t)b*Ln + t)*NF;
        o[ch]      = xc;
        o[7  + ch] = mean;
        o[14 + ch] = mx;
        o[21 + ch] = mn;
        o[28 + ch] = sd;
        o[35 + ch] = xc - sxf[tl + 20][ch];
        o[42 + ch] = xc - sxf[tl + 18][ch];
        o[49 + ch] = xc - sxf[tl + 16][ch];
    }
}

// ---------------- 2) circular conv1d(k=3) + bias + LN + partial sumsq ---------
__global__ __launch_bounds__(256)
void conv_ln_kernel(const float* __restrict__ conv_b,
                    const float* __restrict__ gamma_c, const float* __restrict__ beta_c) {
    __shared__ float sx[TT+2][NF];
    __shared__ float semb[TT][Dn];
    int b  = blockIdx.y;
    int t0 = blockIdx.x * TT;
    int tid = threadIdx.x;
    for (int i = tid; i < (TT+2)*NF; i += 256) {
        int r = i / NF, f = i - r*NF;
        int tt = (t0 - 1 + r + Ln) & (Ln - 1);
        sx[r][f] = g_xcomb[((size_t)b*Ln + tt)*NF + f];
    }
    __syncthreads();
    int d0 = tid * 2;
    float acc0[TT], acc1[TT];
    float bb0 = conv_b[d0], bb1 = conv_b[d0+1];
    #pragma unroll
    for (int t = 0; t < TT; t++) { acc0[t] = bb0; acc1[t] = bb1; }
    const float2* wtp = (const float2*)g_wT;
    for (int f = 0; f < NF; f++) {
        float2 wk0 = wtp[(f*3+0)*(Dn/2) + tid];
        float2 wk1 = wtp[(f*3+1)*(Dn/2) + tid];
        float2 wk2 = wtp[(f*3+2)*(Dn/2) + tid];
        float sv[TT+2];
        #pragma unroll
        for (int r = 0; r < TT+2; r++) sv[r] = sx[r][f];
        #pragma unroll
        for (int t = 0; t < TT; t++) {
            acc0[t] += sv[t]*wk0.x + sv[t+1]*wk1.x + sv[t+2]*wk2.x;
            acc1[t] += sv[t]*wk0.y + sv[t+1]*wk1.y + sv[t+2]*wk2.y;
        }
    }
    #pragma unroll
    for (int t = 0; t < TT; t++) { semb[t][d0] = acc0[t]; semb[t][d0+1] = acc1[t]; }
    __syncthreads();
    int warp = tid >> 5, lane = tid & 31;
    for (int rr = warp; rr < TT; rr += 8) {
        float s = 0.f;
        for (int i = lane; i < Dn; i += 32) s += semb[rr][i];
        #pragma unroll
        for (int o = 16; o; o >>= 1) s += __shfl_xor_sync(0xffffffffu, s, o);
        float mu = s * (1.0f/Dn);
        float q = 0.f;
        for (int i = lane; i < Dn; i += 32) { float d = semb[rr][i]-mu; q += d*d; }
        #pragma unroll
        for (int o = 16; o; o >>= 1) q += __shfl_xor_sync(0xffffffffu, q, o);
        float inv = rsqrtf(q*(1.0f/Dn) + EPSf);
        int t = t0 + rr;
        float* cp = g_c + ((size_t)b*Ln + t)*Dn;
        float sq = 0.f, s96 = 0.f, s160 = 0.f, s256 = 0.f;
        for (int i = lane; i < Dn; i += 32) {
            float cv = (semb[rr][i]-mu)*inv*gamma_c[i] + beta_c[i];
            cp[i] = cv;
            float c2 = cv*cv;
            sq += c2;
            if (i < 96)  s96  += c2;
            if (i < 160) s160 += c2;
            if (i < 256) s256 += c2;
        }
        #pragma unroll
        for (int o = 16; o; o >>= 1) {
            sq   += __shfl_xor_sync(0xffffffffu, sq, o);
            s96  += __shfl_xor_sync(0xffffffffu, s96, o);
            s160 += __shfl_xor_sync(0xffffffffu, s160, o);
            s256 += __shfl_xor_sync(0xffffffffu, s256, o);
        }
        if (lane == 0) {
            g_sq[b*Ln + t]    = sq;
            g_sq96[b*Ln + t]  = s96;
            g_sq160[b*Ln + t] = s160;
            g_sq256[b*Ln + t] = s256;
        }
    }
}

// ---------------- 3) sinusoid PE + LN(pe) + LN(pe_learned) --------------------
__global__ __launch_bounds__(256)
void pe_kernel(const float* __restrict__ pe_learned,
               const float* __restrict__ gf, const float* __restrict__ bf,
               const float* __restrict__ gl, const float* __restrict__ bl) {
    __shared__ float red[8];
    int t = blockIdx.x;
    int tid = threadIdx.x;
    int dA = tid, dB = tid + 256;
    const float kdiv = -9.210340371976184f / (float)Dn;
    float divA = expf((float)(dA & ~1) * kdiv);
    float divB = expf((float)(dB & ~1) * kdiv);
    float sA, cA, sB, cB;
    sincosf((float)t * divA, &sA, &cA);
    sincosf((float)t * divB, &sB, &cB);
    float v0 = (dA & 1) ? cA : sA;
    float v1 = (dB & 1) ? cB : sB;
    g_pe[t*Dn + dA] = v0;
    g_pe[t*Dn + dB] = v1;
    float mu = blockReduce(v0 + v1, red) * (1.0f/Dn);
    float c0 = v0 - mu, c1 = v1 - mu;
    float var = blockReduce(c0*c0 + c1*c1, red) * (1.0f/Dn);
    float inv = rsqrtf(var + EPSf);
    g_pef[t*Dn + dA] = c0*inv*gf[dA] + bf[dA];
    g_pef[t*Dn + dB] = c1*inv*gf[dB] + bf[dB];
    float u0 = pe_learned[t*Dn + dA], u1 = pe_learned[t*Dn + dB];
    float mu2 = blockReduce(u0 + u1, red) * (1.0f/Dn);
    float e0 = u0 - mu2, e1 = u1 - mu2;
    float var2 = blockReduce(e0*e0 + e1*e1, red) * (1.0f/Dn);
    float inv2 = rsqrtf(var2 + EPSf);
    g_pel[t*Dn + dA] = e0*inv2*gl[dA] + bl[dA];
    g_pel[t*Dn + dB] = e1*inv2*gl[dB] + bl[dB];
}

// ---------------- 4) symmetric Gram (tf32 mma) + checkpoint ladder ------------
__global__ __launch_bounds__(256)
void gram_kernel() {
    __shared__ float As[2][128][20];
    __shared__ float Bs[2][128][20];
    __shared__ float redm[8];
    __shared__ float s_cgm[8];
    __shared__ float s_rgm[8][2];
    __shared__ int s_flag;
    int b = blockIdx.y;
    int rr_ = blockIdx.x, dia = 0;
    while (rr_ >= 16 - dia) { rr_ -= 16 - dia; dia++; }
    int ti = rr_, tj = rr_ + dia;
    const float* Cb = g_c + (size_t)b*Ln*Dn;
    int i0 = ti*128, j0 = tj*128;
    int tid = threadIdx.x;
    int warp = tid >> 5, lane = tid & 31;
    int wm = (warp >> 2) * 64;
    int wn = (warp & 3) * 32;
    int g = lane >> 2, th = lane & 3;

    int lrow = tid >> 1, lk = (tid & 1) * 8;
    const float* Ag = Cb + (size_t)(i0 + lrow)*Dn + lk;
    const float* Bg = Cb + (size_t)(j0 + lrow)*Dn + lk;

    float acc[4][4][4];
    #pragma unroll
    for (int i = 0; i < 4; i++)
        #pragma unroll
        for (int j = 0; j < 4; j++)
            #pragma unroll
            for (int q = 0; q < 4; q++) acc[i][j][q] = 0.f;

    float4 pa0 = *(const float4*)(Ag);
    float4 pa1 = *(const float4*)(Ag + 4);
    float4 pb0 = *(const float4*)(Bg);
    float4 pb1 = *(const float4*)(Bg + 4);
    #pragma unroll
    for (int q = 0; q < 4; q++) {
        As[0][lrow][lk+q]   = totf(((float*)&pa0)[q]);
        As[0][lrow][lk+4+q] = totf(((float*)&pa1)[q]);
        Bs[0][lrow][lk+q]   = totf(((float*)&pb0)[q]);
        Bs[0][lrow][lk+4+q] = totf(((float*)&pb1)[q]);
    }
    __syncthreads();
    int cur = 0;
    for (int kt = 0; kt < 32; kt++) {
        if (kt < 31) {
            int ko = (kt+1)*16;
            pa0 = *(const float4*)(Ag + ko);
            pa1 = *(const float4*)(Ag + ko + 4);
            pb0 = *(const float4*)(Bg + ko);
            pb1 = *(const float4*)(Bg + ko + 4);
        }
        #pragma unroll
        for (int k8 = 0; k8 < 16; k8 += 8) {
            unsigned af[4][4], bf_[4][2];
            #pragma unroll
            for (int fm = 0; fm < 4; fm++) {
                const float* ap = &As[cur][wm + fm*16 + g][k8 + th];
                af[fm][0] = __float_as_uint(ap[0]);
                af[fm][1] = __float_as_uint(ap[8*20]);
                af[fm][2] = __float_as_uint(ap[4]);
                af[fm][3] = __float_as_uint(ap[8*20 + 4]);
            }
            #pragma unroll
            for (int fn = 0; fn < 4; fn++) {
                const float* bp = &Bs[cur][wn + fn*8 + g][k8 + th];
                bf_[fn][0] = __float_as_uint(bp[0]);
                bf_[fn][1] = __float_as_uint(bp[4]);
            }
            #pragma unroll
            for (int fm = 0; fm < 4; fm++)
                #pragma unroll
                for (int fn = 0; fn < 4; fn++)
                    mma_tf32(acc[fm][fn], af[fm], bf_[fn]);
        }
        if (ti != tj && (kt == 5 || kt == 9 || kt == 15)) {
            const float* sqp = (kt == 5) ? g_sq96 : (kt == 9) ? g_sq160 : g_sq256;
            float sqj2[4][2];
            #pragma unroll
            for (int fn = 0; fn < 4; fn++) {
                int j = j0 + wn + fn*8 + th*2;
                sqj2[fn][0] = sqp[b*Ln + j];
                sqj2[fn][1] = sqp[b*Ln + j + 1];
            }
            float mind = 1e30f;
            #pragma unroll
            for (int fm = 0; fm < 4; fm++) {
                #pragma unroll
                for (int rr = 0; rr < 2; rr++) {
                    int i = i0 + wm + fm*16 + g + rr*8;
                    float sqi2 = sqp[b*Ln + i];
                    #pragma unroll
                    for (int fn = 0; fn < 4; fn++) {
                        float d0v = sqi2 + sqj2[fn][0] - 2.0f*acc[fm][fn][rr*2+0];
                        float d1v = sqi2 + sqj2[fn][1] - 2.0f*acc[fm][fn][rr*2+1];
                        mind = fminf(mind, fminf(d0v, d1v));
                    }
                }
            }
            #pragma unroll
            for (int o = 16; o; o >>= 1) mind = fminf(mind, __shfl_xor_sync(0xffffffffu, mind, o));
            if (lane == 0) redm[warp] = mind;
            __syncthreads();
            if (tid == 0) {
                float m = redm[0];
                #pragma unroll
                for (int i = 1; i < 8; i++) m = fminf(m, redm[i]);
                s_flag = (m > DCUT) ? 1 : 0;
            }
            __syncthreads();
            if (s_flag) {
                if (tid == 0) {
                    int* f0 = g_flag32 + (b*16 + ti)*64 + tj*4;
                    int* f1 = g_flag32 + (b*16 + tj)*64 + ti*4;
                    #pragma unroll
                    for (int q = 0; q < 4; q++) { f0[q] = 0; f1[q] = 0; }
                }
                return;
            }
        }
        if (kt < 31) {
            int nxt = cur ^ 1;
            #pragma unroll
            for (int q = 0; q < 4; q++) {
                As[nxt][lrow][lk+q]   = totf(((float*)&pa0)[q]);
                As[nxt][lrow][lk+4+q] = totf(((float*)&pa1)[q]);
                Bs[nxt][lrow][lk+q]   = totf(((float*)&pb0)[q]);
                Bs[nxt][lrow][lk+4+q] = totf(((float*)&pb1)[q]);
            }
            __syncthreads();
            cur = nxt;
        }
    }
    float sqj[4][2];
    #pragma unroll
    for (int fn = 0; fn < 4; fn++) {
        int j = j0 + wn + fn*8 + th*2;
        sqj[fn][0] = g_sq[b*Ln + j];
        sqj[fn][1] = g_sq[b*Ln + j + 1];
    }
    float cgmax = 0.f, rg0 = 0.f, rg1 = 0.f;
    #pragma unroll
    for (int fm = 0; fm < 4; fm++) {
        #pragma unroll
        for (int rr = 0; rr < 2; rr++) {
            int i = i0 + wm + fm*16 + g + rr*8;
            float sqi = g_sq[b*Ln + i];
            #pragma unroll
            for (int fn = 0; fn < 4; fn++) {
                float d0v = fmaxf(sqi + sqj[fn][0] - 2.0f*acc[fm][fn][rr*2+0], 0.0f);
                float d1v = fmaxf(sqi + sqj[fn][1] - 2.0f*acc[fm][fn][rr*2+1], 0.0f);
                float s0 = __expf(-0.5f * d0v);
                float s1 = __expf(-0.5f * d1v);
                acc[fm][fn][rr*2+0] = s0;
                acc[fm][fn][rr*2+1] = s1;
                float m01 = fmaxf(s0, s1);
                cgmax = fmaxf(cgmax, m01);
                if (fm < 2) rg0 = fmaxf(rg0, m01); else rg1 = fmaxf(rg1, m01);
            }
        }
    }
    #pragma unroll
    for (int o = 16; o; o >>= 1) {
        cgmax = fmaxf(cgmax, __shfl_xor_sync(0xffffffffu, cgmax, o));
        rg0   = fmaxf(rg0,   __shfl_xor_sync(0xffffffffu, rg0, o));
        rg1   = fmaxf(rg1,   __shfl_xor_sync(0xffffffffu, rg1, o));
    }
    if (lane == 0) { s_cgm[warp] = cgmax; s_rgm[warp][0] = rg0; s_rgm[warp][1] = rg1; }
    __syncthreads();
    if (tid == 0) {
        float tilem = s_cgm[0];
        #pragma unroll
        for (int i = 1; i < 8; i++) tilem = fmaxf(tilem, s_cgm[i]);
        int act = (tilem > THRESH) ? 1 : 0;
        s_flag = act;
        int* f0 = g_flag32 + (b*16 + ti)*64 + tj*4;
        int* f1 = g_flag32 + (b*16 + tj)*64 + ti*4;
        if (act) {
            #pragma unroll
            for (int cg = 0; cg < 4; cg++)
                f0[cg] = (fmaxf(s_cgm[cg], s_cgm[4+cg]) > THRESH) ? 1 : 0;
            if (ti != tj) {
                #pragma unroll
                for (int h = 0; h < 2; h++)
                    #pragma unroll
                    for (int fh = 0; fh < 2; fh++) {
                        float m = s_rgm[h*4+0][fh];
                        m = fmaxf(m, s_rgm[h*4+1][fh]);
                        m = fmaxf(m, s_rgm[h*4+2][fh]);
                        m = fmaxf(m, s_rgm[h*4+3][fh]);
                        f1[h*2+fh] = (m > THRESH) ? 1 : 0;
                    }
            }
        } else {
            #pragma unroll
            for (int q = 0; q < 4; q++) { f0[q] = 0; if (ti != tj) f1[q] = 0; }
        }
    }
    __syncthreads();
    if (s_flag) {
        float* Sb = g_S + (size_t)b*Ln*Ln;
        #pragma unroll
        for (int fm = 0; fm < 4; fm++) {
            #pragma unroll
            for (int rr = 0; rr < 2; rr++) {
                int i = i0 + wm + fm*16 + g + rr*8;
                #pragma unroll
                for (int fn = 0; fn < 4; fn++) {
                    int j = j0 + wn + fn*8 + th*2;
                    float s0 = acc[fm][fn][rr*2+0];
                    float s1 = acc[fm][fn][rr*2+1];
                    *(float2*)&Sb[(size_t)i*Ln + j] = make_float2(s0, s1);
                    if (ti != tj) {
                        Sb[(size_t)j*Ln + i]     = s0;
                        Sb[(size_t)(j+1)*Ln + i] = s1;
                    }
                }
            }
        }
    }
}

// ---------------- 5) sem (32x512 tiles) + fused rowsum + LN + final mix -------
// dynamic smem layout (floats): Bs[2][16][520] | As[2][32][20] | srs[256] | rsum[32][4] | rsq[32][4]
#define SEM_BS_F (2*16*520)
#define SEM_AS_F (2*32*20)
#define SEM_SMEM_BYTES ((SEM_BS_F + SEM_AS_F + 256 + 128 + 128) * 4)

__global__ __launch_bounds__(256)
void sem_kernel(const float* __restrict__ wp,
                const float* __restrict__ gt, const float* __restrict__ bt,
                float* __restrict__ out) {
    extern __shared__ float sm[];
    float* BsD = sm;
    float* AsD = sm + SEM_BS_F;
    float* srs = AsD + SEM_AS_F;
    float* rsum = srs + 256;
    float* rsq  = rsum + 128;
    __shared__ int s_list[64];
    __shared__ int s_nact;

    int b  = blockIdx.y;
    int i0 = blockIdx.x * 32;
    const float* Cb = g_c + (size_t)b*Ln*Dn;
    const float* Sb = g_S + (size_t)b*Ln*Ln;
    int tid = threadIdx.x;
    int warp = tid >> 5, lane = tid & 31;
    int wmr = (warp >> 2) * 16;          // warp row base (0 or 16)
    int wn  = (warp & 3) * 128;          // warp col base
    int g = lane >> 2, th = lane & 3;

    if (tid == 0) {
        const int* fl = g_flag32 + (b*16 + (i0 >> 7))*64;
        int n = 0;
        for (int c = 0; c < 64; c++)
            if (fl[c]) s_list[n++] = c;
        s_nact = n;
    }
    __syncthreads();
    int total = s_nact * 2;

    // loaders
    int lrowA = tid >> 3, lkA = (tid & 7) * 2;       // A: 32 rows x 16 cols
    int kB = tid >> 4, cB = tid & 15;                // B: 16 rows x 512 cols (8 float4/thread)
    const float* AgRow = Sb + (size_t)(i0 + lrowA)*Ln + lkA;
    const float* BgRow = Cb + (size_t)kB*Dn;

    float acc[16][4];
    #pragma unroll
    for (int i = 0; i < 16; i++)
        #pragma unroll
        for (int q = 0; q < 4; q++) acc[i][q] = 0.f;

    float rs = 0.f;
    int k0 = s_list[0] * 32;
    float2 pa = *(const float2*)(AgRow + k0);
    float4 pb[8];
    #pragma unroll
    for (int q = 0; q < 8; q++)
        pb[q] = *(const float4*)(BgRow + (size_t)k0*Dn + (cB + q*16)*4);
    rs += pa.x + pa.y;
    {
        float* ad = AsD + lrowA*20 + lkA;
        ad[0] = totf(pa.x); ad[1] = totf(pa.y);
        #pragma unroll
        for (int q = 0; q < 8; q++) {
            float* bd = BsD + kB*520 + (cB + q*16)*4;
            bd[0] = totf(pb[q].x); bd[1] = totf(pb[q].y);
            bd[2] = totf(pb[q].z); bd[3] = totf(pb[q].w);
        }
    }
    __syncthreads();
    int cur = 0;
    for (int st = 0; st < total; st++) {
        if (st + 1 < total) {
            int kn = s_list[(st+1) >> 1] * 32 + ((st+1) & 1) * 16;
            pa = *(const float2*)(AgRow + kn);
            #pragma unroll
            for (int q = 0; q < 8; q++)
                pb[q] = *(const float4*)(BgRow + (size_t)kn*Dn + (cB + q*16)*4);
        }
        const float* AsC = AsD + cur*(32*20);
        const float* BsC = BsD + cur*(16*520);
        #pragma unroll
        for (int k8 = 0; k8 < 16; k8 += 8) {
            unsigned af[4];
            const float* ap = AsC + (wmr + g)*20 + k8 + th;
            af[0] = __float_as_uint(ap[0]);
            af[1] = __float_as_uint(ap[8*20]);
            af[2] = __float_as_uint(ap[4]);
            af[3] = __float_as_uint(ap[8*20 + 4]);
            #pragma unroll
            for (int fn = 0; fn < 16; fn++) {
                unsigned bf_[2];
                const float* bp = BsC + (k8 + th)*520 + wn + fn*8 + g;
                bf_[0] = __float_as_uint(bp[0]);
                bf_[1] = __float_as_uint(bp[4*520]);
                mma_tf32(acc[fn], af, bf_);
            }
        }
        if (st + 1 < total) {
            int nxt = cur ^ 1;
            rs += pa.x + pa.y;
            float* ad = AsD + nxt*(32*20) + lrowA*20 + lkA;
            ad[0] = totf(pa.x); ad[1] = totf(pa.y);
            #pragma unroll
            for (int q = 0; q < 8; q++) {
                float* bd = BsD + nxt*(16*520) + kB*520 + (cB + q*16)*4;
                bd[0] = totf(pb[q].x); bd[1] = totf(pb[q].y);
                bd[2] = totf(pb[q].z); bd[3] = totf(pb[q].w);
            }
            __syncthreads();
            cur = nxt;
        }
    }
    __syncthreads();
    srs[tid] = rs;
    __syncthreads();

    // row sums of S (full rows staged across all active chunks)
    int r0 = wmr + g, r1 = wmr + g + 8;        // rows in [0,32)
    float rsum0 = 0.f, rsum1 = 0.f;
    #pragma unroll
    for (int k = 0; k < 8; k++) { rsum0 += srs[r0*8 + k]; rsum1 += srs[r1*8 + k]; }
    float rinv0 = 1.0f / rsum0, rinv1 = 1.0f / rsum1;

    // pass 1: acc -> tsum value v = c + pe + sem*rinv ; accumulate row sum/sumsq
    float sum0 = 0.f, sq0 = 0.f, sum1 = 0.f, sq1 = 0.f;
    int gi0 = i0 + r0, gi1 = i0 + r1;
    #pragma unroll
    for (int fn = 0; fn < 16; fn++) {
        int j = wn + fn*8 + th*2;
        float2 cv0 = *(const float2*)&Cb[(size_t)gi0*Dn + j];
        float2 pv0 = *(const float2*)&g_pe[gi0*Dn + j];
        float v00 = cv0.x + pv0.x + acc[fn][0]*rinv0;
        float v01 = cv0.y + pv0.y + acc[fn][1]*rinv0;
        acc[fn][0] = v00; acc[fn][1] = v01;
        sum0 += v00 + v01; sq0 += v00*v00 + v01*v01;
        float2 cv1 = *(const float2*)&Cb[(size_t)gi1*Dn + j];
        float2 pv1 = *(const float2*)&g_pe[gi1*Dn + j];
        float v10 = cv1.x + pv1.x + acc[fn][2]*rinv1;
        float v11 = cv1.y + pv1.y + acc[fn][3]*rinv1;
        acc[fn][2] = v10; acc[fn][3] = v11;
        sum1 += v10 + v11; sq1 += v10*v10 + v11*v11;
    }
    // reduce over th (quad lanes share g)
    #pragma unroll
    for (int o = 1; o <= 2; o <<= 1) {
        sum0 += __shfl_xor_sync(0xffffffffu, sum0, o);
        sq0  += __shfl_xor_sync(0xffffffffu, sq0, o);
        sum1 += __shfl_xor_sync(0xffffffffu, sum1, o);
        sq1  += __shfl_xor_sync(0xffffffffu, sq1, o);
    }
    if (th == 0) {
        rsum[r0*4 + (warp & 3)] = sum0;  rsq[r0*4 + (warp & 3)] = sq0;
        rsum[r1*4 + (warp & 3)] = sum1;  rsq[r1*4 + (warp & 3)] = sq1;
    }
    __syncthreads();
    float ts0 = rsum[r0*4] + rsum[r0*4+1] + rsum[r0*4+2] + rsum[r0*4+3];
    float tq0 = rsq[r0*4]  + rsq[r0*4+1]  + rsq[r0*4+2]  + rsq[r0*4+3];
    float ts1 = rsum[r1*4] + rsum[r1*4+1] + rsum[r1*4+2] + rsum[r1*4+3];
    float tq1 = rsq[r1*4]  + rsq[r1*4+1]  + rsq[r1*4+2]  + rsq[r1*4+3];
    float mu0 = ts0 * (1.0f/Dn);
    float var0 = tq0 * (1.0f/Dn) - mu0*mu0;
    float inv0 = rsqrtf(var0 + EPSf);
    float mu1 = ts1 * (1.0f/Dn);
    float var1 = tq1 * (1.0f/Dn) - mu1*mu1;
    float inv1 = rsqrtf(var1 + EPSf);

    // softmax weights
    float w0 = wp[0], w1 = wp[1], w2 = wp[2], w3 = wp[3];
    float mx = fmaxf(fmaxf(w0, w1), fmaxf(w2, w3));
    float e0 = expf(w0-mx), e1 = expf(w1-mx), e2 = expf(w2-mx), e3 = expf(w3-mx);
    float esum = 1.0f / (e0+e1+e2+e3);
    w0 = e0*esum; w1 = e1*esum; w2 = e2*esum; w3 = e3*esum;

    // pass 2: out = w0*c + w1*pef + w2*pel + w3*((v-mu)*inv*gt + bt)
    float* ob = out + ((size_t)b*Ln)*Dn;
    #pragma unroll
    for (int fn = 0; fn < 16; fn++) {
        int j = wn + fn*8 + th*2;
        float2 gv = *(const float2*)&gt[j];
        float2 bv = *(const float2*)&bt[j];
        {
            float2 cv = *(const float2*)&Cb[(size_t)gi0*Dn + j];
            float2 pf = *(const float2*)&g_pef[gi0*Dn + j];
            float2 pl = *(const float2*)&g_pel[gi0*Dn + j];
            float t0v = (acc[fn][0]-mu0)*inv0*gv.x + bv.x;
            float t1v = (acc[fn][1]-mu0)*inv0*gv.y + bv.y;
            float2 ov;
            ov.x = w0*cv.x + w1*pf.x + w2*pl.x + w3*t0v;
            ov.y = w0*cv.y + w1*pf.y + w2*pl.y + w3*t1v;
            *(float2*)&ob[(size_t)gi0*Dn + j] = ov;
        }
        {
            float2 cv = *(const float2*)&Cb[(size_t)gi1*Dn + j];
            float2 pf = *(const float2*)&g_pef[gi1*Dn + j];
            float2 pl = *(const float2*)&g_pel[gi1*Dn + j];
            float t0v = (acc[fn][2]-mu1)*inv1*gv.x + bv.x;
            float t1v = (acc[fn][3]-mu1)*inv1*gv.y + bv.y;
            float2 ov;
            ov.x = w0*cv.x + w1*pf.x + w2*pl.x + w3*t0v;
            ov.y = w0*cv.y + w1*pf.y + w2*pl.y + w3*t1v;
            *(float2*)&ob[(size_t)gi1*Dn + j] = ov;
        }
    }
}

// ---------------- launch ------------------------------------------------------
extern "C" void kernel_launch(void* const* d_in, const int* in_sizes, int n_in,
                              void* d_out, int out_size) {
    const float* x          = (const float*)d_in[0];
    const float* conv_w     = (const float*)d_in[1];
    const float* conv_b     = (const float*)d_in[2];
    const float* pe_learned = (const float*)d_in[3];
    const float* wp         = (const float*)d_in[4];
    const float* gamma_c    = (const float*)d_in[5];
    const float* beta_c     = (const float*)d_in[6];
    const float* gamma_f    = (const float*)d_in[7];
    const float* beta_f     = (const float*)d_in[8];
    const float* gamma_l    = (const float*)d_in[9];
    const float* beta_l     = (const float*)d_in[10];
    const float* gamma_t    = (const float*)d_in[11];
    const float* beta_t     = (const float*)d_in[12];

    cudaFuncSetAttribute(sem_kernel, cudaFuncAttributeMaxDynamicSharedMemorySize, SEM_SMEM_BYTES);

    wtrans_kernel<<<(NF*3*Dn + 255)/256, 256>>>(conv_w);
    features_kernel<<<dim3(Ln/128, Bn), 256>>>(x);
    conv_ln_kernel<<<dim3(Ln/TT, Bn), 256>>>(conv_b, gamma_c, beta_c);
    pe_kernel<<<Ln, 256>>>(pe_learned, gamma_f, beta_f, gamma_l, beta_l);
    gram_kernel<<<dim3(136, Bn), 256>>>();
    sem_kernel<<<dim3(Ln/32, Bn), 256, SEM_SMEM_BYTES>>>(wp, gamma_t, beta_t, (float*)d_out);
}

// round 13
// speedup vs baseline: 2.4265x; 1.0428x over previous
#include <cuda_runtime.h>
#include <math.h>

#define Bn 8
#define Ln 2048
#define Cn 7
#define Dn 512
#define Wn 24
#define NF 56
#define EPSf 1e-5f
#define TT 16
#define THRESH 1e-7f
#define DCUT 36.0f

// ---------------- scratch (device globals; allocation-free kernel_launch) ----
__device__ float g_xcomb[Bn*Ln*NF];
__device__ float g_wT[NF*3*Dn];          // transposed conv weights [f*3+k][d]
__device__ float g_c[(size_t)Bn*Ln*Dn];
__device__ float g_sq[Bn*Ln];
__device__ float g_sq64[Bn*Ln];
__device__ float g_sq128[Bn*Ln];
__device__ float g_sq256[Bn*Ln];
__device__ float g_pe[Ln*Dn];
__device__ float g_pef[Ln*Dn];
__device__ float g_pel[Ln*Dn];
__device__ float g_S[(size_t)Bn*Ln*Ln];
__device__ int   g_flag32[Bn*16*64];     // per (stripe of 128 rows) x (32-col chunk) activity

// ---------------- helpers -----------------------------------------------------
__device__ __forceinline__ float totf(float x) {
    unsigned u;
    asm("cvt.rna.tf32.f32 %0, %1;" : "=r"(u) : "f"(x));
    return __uint_as_float(u);
}

__device__ __forceinline__ void mma_tf32(float* d, const unsigned* a, const unsigned* b) {
    asm volatile(
        "mma.sync.aligned.m16n8k8.row.col.f32.tf32.tf32.f32 "
        "{%0,%1,%2,%3}, {%4,%5,%6,%7}, {%8,%9}, {%0,%1,%2,%3};"
        : "+f"(d[0]), "+f"(d[1]), "+f"(d[2]), "+f"(d[3])
        : "r"(a[0]), "r"(a[1]), "r"(a[2]), "r"(a[3]), "r"(b[0]), "r"(b[1]));
}

__device__ __forceinline__ float blockReduce(float v, float* red) {
    #pragma unroll
    for (int o = 16; o; o >>= 1) v += __shfl_xor_sync(0xffffffffu, v, o);
    if ((threadIdx.x & 31) == 0) red[threadIdx.x >> 5] = v;
    __syncthreads();
    float s = red[0];
    #pragma unroll
    for (int i = 1; i < 8; i++) s += red[i];
    __syncthreads();
    return s;
}

// ---------------- 0) conv weight transpose ------------------------------------
__global__ __launch_bounds__(256)
void wtrans_kernel(const float* __restrict__ cw) {
    int idx = blockIdx.x * 256 + threadIdx.x;
    if (idx >= NF*3*Dn) return;
    int d = idx & (Dn-1);
    int f3k = idx >> 9;
    g_wT[idx] = cw[d*NF*3 + f3k];
}

// ---------------- 1) window stats + lags (smem-tiled) -------------------------
__global__ __launch_bounds__(256)
void features_kernel(const float* __restrict__ x) {
    __shared__ float sxf[152][Cn];
    int b  = blockIdx.y;
    int t0 = blockIdx.x * 128;
    int tid = threadIdx.x;
    const float* xb = x + (size_t)b*Ln*Cn;
    for (int i = tid; i < 151*Cn; i += 256) {
        int r = i / Cn, ch = i - r*Cn;
        int tt = t0 - 23 + r; tt = tt < 0 ? 0 : tt;
        sxf[r][ch] = xb[tt*Cn + ch];
    }
    __syncthreads();
    for (int i = tid; i < 128*Cn; i += 256) {
        int tl = i / Cn, ch = i - tl*Cn;
        float v[Wn];
        #pragma unroll
        for (int w = 0; w < Wn; w++) v[w] = sxf[tl + w][ch];
        float s = 0.f, mx = v[0], mn = v[0];
        #pragma unroll
        for (int w = 0; w < Wn; w++) { s += v[w]; mx = fmaxf(mx, v[w]); mn = fminf(mn, v[w]); }
        float mean = s * (1.0f/Wn);
        float m2 = 0.f;
        #pragma unroll
        for (int w = 0; w < Wn; w++) { float d = v[w]-mean; m2 += d*d; }
        float sd = sqrtf(m2 * (1.0f/(Wn-1)));
        float xc = v[Wn-1];
        int t = t0 + tl;
        float* o = g_xcomb + ((size_t)b*Ln + t)*NF;
        o[ch]      = xc;
        o[7  + ch] = mean;
        o[14 + ch] = mx;
        o[21 + ch] = mn;
        o[28 + ch] = sd;
        o[35 + ch] = xc - sxf[tl + 20][ch];
        o[42 + ch] = xc - sxf[tl + 18][ch];
        o[49 + ch] = xc - sxf[tl + 16][ch];
    }
}

// ---------------- 2) circular conv1d(k=3) + bias + LN + partial sumsq ---------
__global__ __launch_bounds__(256)
void conv_ln_kernel(const float* __restrict__ conv_b,
                    const float* __restrict__ gamma_c, const float* __restrict__ beta_c) {
    __shared__ float sx[TT+2][NF];
    __shared__ float semb[TT][Dn];
    int b  = blockIdx.y;
    int t0 = blockIdx.x * TT;
    int tid = threadIdx.x;
    for (int i = tid; i < (TT+2)*NF; i += 256) {
        int r = i / NF, f = i - r*NF;
        int tt = (t0 - 1 + r + Ln) & (Ln - 1);
        sx[r][f] = g_xcomb[((size_t)b*Ln + tt)*NF + f];
    }
    __syncthreads();
    int d0 = tid * 2;
    float acc0[TT], acc1[TT];
    float bb0 = conv_b[d0], bb1 = conv_b[d0+1];
    #pragma unroll
    for (int t = 0; t < TT; t++) { acc0[t] = bb0; acc1[t] = bb1; }
    const float2* wtp = (const float2*)g_wT;
    for (int f = 0; f < NF; f++) {
        float2 wk0 = wtp[(f*3+0)*(Dn/2) + tid];
        float2 wk1 = wtp[(f*3+1)*(Dn/2) + tid];
        float2 wk2 = wtp[(f*3+2)*(Dn/2) + tid];
        float sv[TT+2];
        #pragma unroll
        for (int r = 0; r < TT+2; r++) sv[r] = sx[r][f];
        #pragma unroll
        for (int t = 0; t < TT; t++) {
            acc0[t] += sv[t]*wk0.x + sv[t+1]*wk1.x + sv[t+2]*wk2.x;
            acc1[t] += sv[t]*wk0.y + sv[t+1]*wk1.y + sv[t+2]*wk2.y;
        }
    }
    #pragma unroll
    for (int t = 0; t < TT; t++) { semb[t][d0] = acc0[t]; semb[t][d0+1] = acc1[t]; }
    __syncthreads();
    int warp = tid >> 5, lane = tid & 31;
    for (int rr = warp; rr < TT; rr += 8) {
        float s = 0.f;
        for (int i = lane; i < Dn; i += 32) s += semb[rr][i];
        #pragma unroll
        for (int o = 16; o; o >>= 1) s += __shfl_xor_sync(0xffffffffu, s, o);
        float mu = s * (1.0f/Dn);
        float q = 0.f;
        for (int i = lane; i < Dn; i += 32) { float d = semb[rr][i]-mu; q += d*d; }
        #pragma unroll
        for (int o = 16; o; o >>= 1) q += __shfl_xor_sync(0xffffffffu, q, o);
        float inv = rsqrtf(q*(1.0f/Dn) + EPSf);
        int t = t0 + rr;
        float* cp = g_c + ((size_t)b*Ln + t)*Dn;
        float sq = 0.f, s64 = 0.f, s128 = 0.f, s256 = 0.f;
        for (int i = lane; i < Dn; i += 32) {
            float cv = (semb[rr][i]-mu)*inv*gamma_c[i] + beta_c[i];
            cp[i] = cv;
            float c2 = cv*cv;
            sq += c2;
            if (i < 64)  s64  += c2;
            if (i < 128) s128 += c2;
            if (i < 256) s256 += c2;
        }
        #pragma unroll
        for (int o = 16; o; o >>= 1) {
            sq   += __shfl_xor_sync(0xffffffffu, sq, o);
            s64  += __shfl_xor_sync(0xffffffffu, s64, o);
            s128 += __shfl_xor_sync(0xffffffffu, s128, o);
            s256 += __shfl_xor_sync(0xffffffffu, s256, o);
        }
        if (lane == 0) {
            g_sq[b*Ln + t]    = sq;
            g_sq64[b*Ln + t]  = s64;
            g_sq128[b*Ln + t] = s128;
            g_sq256[b*Ln + t] = s256;
        }
    }
}

// ---------------- 3) sinusoid PE + LN(pe) + LN(pe_learned) --------------------
__global__ __launch_bounds__(256)
void pe_kernel(const float* __restrict__ pe_learned,
               const float* __restrict__ gf, const float* __restrict__ bf,
               const float* __restrict__ gl, const float* __restrict__ bl) {
    __shared__ float red[8];
    int t = blockIdx.x;
    int tid = threadIdx.x;
    int dA = tid, dB = tid + 256;
    const float kdiv = -9.210340371976184f / (float)Dn;
    float divA = expf((float)(dA & ~1) * kdiv);
    float divB = expf((float)(dB & ~1) * kdiv);
    float sA, cA, sB, cB;
    sincosf((float)t * divA, &sA, &cA);
    sincosf((float)t * divB, &sB, &cB);
    float v0 = (dA & 1) ? cA : sA;
    float v1 = (dB & 1) ? cB : sB;
    g_pe[t*Dn + dA] = v0;
    g_pe[t*Dn + dB] = v1;
    float mu = blockReduce(v0 + v1, red) * (1.0f/Dn);
    float c0 = v0 - mu, c1 = v1 - mu;
    float var = blockReduce(c0*c0 + c1*c1, red) * (1.0f/Dn);
    float inv = rsqrtf(var + EPSf);
    g_pef[t*Dn + dA] = c0*inv*gf[dA] + bf[dA];
    g_pef[t*Dn + dB] = c1*inv*gf[dB] + bf[dB];
    float u0 = pe_learned[t*Dn + dA], u1 = pe_learned[t*Dn + dB];
    float mu2 = blockReduce(u0 + u1, red) * (1.0f/Dn);
    float e0 = u0 - mu2, e1 = u1 - mu2;
    float var2 = blockReduce(e0*e0 + e1*e1, red) * (1.0f/Dn);
    float inv2 = rsqrtf(var2 + EPSf);
    g_pel[t*Dn + dA] = e0*inv2*gl[dA] + bl[dA];
    g_pel[t*Dn + dB] = e1*inv2*gl[dB] + bl[dB];
}

// ---------------- 4) symmetric Gram (tf32 mma) + early checkpoint ladder ------
__global__ __launch_bounds__(256)
void gram_kernel() {
    __shared__ float As[2][128][20];
    __shared__ float Bs[2][128][20];
    __shared__ float redm[8];
    __shared__ float s_cgm[8];
    __shared__ float s_rgm[8][2];
    __shared__ int s_flag;
    int b = blockIdx.y;
    int rr_ = blockIdx.x, dia = 0;
    while (rr_ >= 16 - dia) { rr_ -= 16 - dia; dia++; }
    int ti = rr_, tj = rr_ + dia;
    const float* Cb = g_c + (size_t)b*Ln*Dn;
    int i0 = ti*128, j0 = tj*128;
    int tid = threadIdx.x;
    int warp = tid >> 5, lane = tid & 31;
    int wm = (warp >> 2) * 64;
    int wn = (warp & 3) * 32;
    int g = lane >> 2, th = lane & 3;

    int lrow = tid >> 1, lk = (tid & 1) * 8;
    const float* Ag = Cb + (size_t)(i0 + lrow)*Dn + lk;
    const float* Bg = Cb + (size_t)(j0 + lrow)*Dn + lk;

    float acc[4][4][4];
    #pragma unroll
    for (int i = 0; i < 4; i++)
        #pragma unroll
        for (int j = 0; j < 4; j++)
            #pragma unroll
            for (int q = 0; q < 4; q++) acc[i][j][q] = 0.f;

    float4 pa0 = *(const float4*)(Ag);
    float4 pa1 = *(const float4*)(Ag + 4);
    float4 pb0 = *(const float4*)(Bg);
    float4 pb1 = *(const float4*)(Bg + 4);
    #pragma unroll
    for (int q = 0; q < 4; q++) {
        As[0][lrow][lk+q]   = totf(((float*)&pa0)[q]);
        As[0][lrow][lk+4+q] = totf(((float*)&pa1)[q]);
        Bs[0][lrow][lk+q]   = totf(((float*)&pb0)[q]);
        Bs[0][lrow][lk+4+q] = totf(((float*)&pb1)[q]);
    }
    __syncthreads();
    int cur = 0;
    for (int kt = 0; kt < 32; kt++) {
        if (kt < 31) {
            int ko = (kt+1)*16;
            pa0 = *(const float4*)(Ag + ko);
            pa1 = *(const float4*)(Ag + ko + 4);
            pb0 = *(const float4*)(Bg + ko);
            pb1 = *(const float4*)(Bg + ko + 4);
        }
        #pragma unroll
        for (int k8 = 0; k8 < 16; k8 += 8) {
            unsigned af[4][4], bf_[4][2];
            #pragma unroll
            for (int fm = 0; fm < 4; fm++) {
                const float* ap = &As[cur][wm + fm*16 + g][k8 + th];
                af[fm][0] = __float_as_uint(ap[0]);
                af[fm][1] = __float_as_uint(ap[8*20]);
                af[fm][2] = __float_as_uint(ap[4]);
                af[fm][3] = __float_as_uint(ap[8*20 + 4]);
            }
            #pragma unroll
            for (int fn = 0; fn < 4; fn++) {
                const float* bp = &Bs[cur][wn + fn*8 + g][k8 + th];
                bf_[fn][0] = __float_as_uint(bp[0]);
                bf_[fn][1] = __float_as_uint(bp[4]);
            }
            #pragma unroll
            for (int fm = 0; fm < 4; fm++)
                #pragma unroll
                for (int fn = 0; fn < 4; fn++)
                    mma_tf32(acc[fm][fn], af[fm], bf_[fn]);
        }
        if (ti != tj && (kt == 3 || kt == 7 || kt == 15)) {
            const float* sqp = (kt == 3) ? g_sq64 : (kt == 7) ? g_sq128 : g_sq256;
            float sqj2[4][2];
            #pragma unroll
            for (int fn = 0; fn < 4; fn++) {
                int j = j0 + wn + fn*8 + th*2;
                sqj2[fn][0] = sqp[b*Ln + j];
                sqj2[fn][1] = sqp[b*Ln + j + 1];
            }
            float mind = 1e30f;
            #pragma unroll
            for (int fm = 0; fm < 4; fm++) {
                #pragma unroll
                for (int rr = 0; rr < 2; rr++) {
                    int i = i0 + wm + fm*16 + g + rr*8;
                    float sqi2 = sqp[b*Ln + i];
                    #pragma unroll
                    for (int fn = 0; fn < 4; fn++) {
                        float d0v = sqi2 + sqj2[fn][0] - 2.0f*acc[fm][fn][rr*2+0];
                        float d1v = sqi2 + sqj2[fn][1] - 2.0f*acc[fm][fn][rr*2+1];
                        mind = fminf(mind, fminf(d0v, d1v));
                    }
                }
            }
            #pragma unroll
            for (int o = 16; o; o >>= 1) mind = fminf(mind, __shfl_xor_sync(0xffffffffu, mind, o));
            if (lane == 0) redm[warp] = mind;
            __syncthreads();
            if (tid == 0) {
                float m = redm[0];
                #pragma unroll
                for (int i = 1; i < 8; i++) m = fminf(m, redm[i]);
                s_flag = (m > DCUT) ? 1 : 0;
            }
            __syncthreads();
            if (s_flag) {
                if (tid == 0) {
                    int* f0 = g_flag32 + (b*16 + ti)*64 + tj*4;
                    int* f1 = g_flag32 + (b*16 + tj)*64 + ti*4;
                    #pragma unroll
                    for (int q = 0; q < 4; q++) { f0[q] = 0; f1[q] = 0; }
                }
                return;
            }
        }
        if (kt < 31) {
            int nxt = cur ^ 1;
            #pragma unroll
            for (int q = 0; q < 4; q++) {
                As[nxt][lrow][lk+q]   = totf(((float*)&pa0)[q]);
                As[nxt][lrow][lk+4+q] = totf(((float*)&pa1)[q]);
                Bs[nxt][lrow][lk+q]   = totf(((float*)&pb0)[q]);
                Bs[nxt][lrow][lk+4+q] = totf(((float*)&pb1)[q]);
            }
            __syncthreads();
            cur = nxt;
        }
    }
    float sqj[4][2];
    #pragma unroll
    for (int fn = 0; fn < 4; fn++) {
        int j = j0 + wn + fn*8 + th*2;
        sqj[fn][0] = g_sq[b*Ln + j];
        sqj[fn][1] = g_sq[b*Ln + j + 1];
    }
    float cgmax = 0.f, rg0 = 0.f, rg1 = 0.f;
    #pragma unroll
    for (int fm = 0; fm < 4; fm++) {
        #pragma unroll
        for (int rr = 0; rr < 2; rr++) {
            int i = i0 + wm + fm*16 + g + rr*8;
            float sqi = g_sq[b*Ln + i];
            #pragma unroll
            for (int fn = 0; fn < 4; fn++) {
                float d0v = fmaxf(sqi + sqj[fn][0] - 2.0f*acc[fm][fn][rr*2+0], 0.0f);
                float d1v = fmaxf(sqi + sqj[fn][1] - 2.0f*acc[fm][fn][rr*2+1], 0.0f);
                float s0 = __expf(-0.5f * d0v);
                float s1 = __expf(-0.5f * d1v);
                acc[fm][fn][rr*2+0] = s0;
                acc[fm][fn][rr*2+1] = s1;
                float m01 = fmaxf(s0, s1);
                cgmax = fmaxf(cgmax, m01);
                if (fm < 2) rg0 = fmaxf(rg0, m01); else rg1 = fmaxf(rg1, m01);
            }
        }
    }
    #pragma unroll
    for (int o = 16; o; o >>= 1) {
        cgmax = fmaxf(cgmax, __shfl_xor_sync(0xffffffffu, cgmax, o));
        rg0   = fmaxf(rg0,   __shfl_xor_sync(0xffffffffu, rg0, o));
        rg1   = fmaxf(rg1,   __shfl_xor_sync(0xffffffffu, rg1, o));
    }
    if (lane == 0) { s_cgm[warp] = cgmax; s_rgm[warp][0] = rg0; s_rgm[warp][1] = rg1; }
    __syncthreads();
    if (tid == 0) {
        float tilem = s_cgm[0];
        #pragma unroll
        for (int i = 1; i < 8; i++) tilem = fmaxf(tilem, s_cgm[i]);
        int act = (tilem > THRESH) ? 1 : 0;
        s_flag = act;
        int* f0 = g_flag32 + (b*16 + ti)*64 + tj*4;
        int* f1 = g_flag32 + (b*16 + tj)*64 + ti*4;
        if (act) {
            #pragma unroll
            for (int cg = 0; cg < 4; cg++)
                f0[cg] = (fmaxf(s_cgm[cg], s_cgm[4+cg]) > THRESH) ? 1 : 0;
            if (ti != tj) {
                #pragma unroll
                for (int h = 0; h < 2; h++)
                    #pragma unroll
                    for (int fh = 0; fh < 2; fh++) {
                        float m = s_rgm[h*4+0][fh];
                        m = fmaxf(m, s_rgm[h*4+1][fh]);
                        m = fmaxf(m, s_rgm[h*4+2][fh]);
                        m = fmaxf(m, s_rgm[h*4+3][fh]);
                        f1[h*2+fh] = (m > THRESH) ? 1 : 0;
                    }
            }
        } else {
            #pragma unroll
            for (int q = 0; q < 4; q++) { f0[q] = 0; if (ti != tj) f1[q] = 0; }
        }
    }
    __syncthreads();
    if (s_flag) {
        float* Sb = g_S + (size_t)b*Ln*Ln;
        #pragma unroll
        for (int fm = 0; fm < 4; fm++) {
            #pragma unroll
            for (int rr = 0; rr < 2; rr++) {
                int i = i0 + wm + fm*16 + g + rr*8;
                #pragma unroll
                for (int fn = 0; fn < 4; fn++) {
                    int j = j0 + wn + fn*8 + th*2;
                    float s0 = acc[fm][fn][rr*2+0];
                    float s1 = acc[fm][fn][rr*2+1];
                    *(float2*)&Sb[(size_t)i*Ln + j] = make_float2(s0, s1);
                    if (ti != tj) {
                        Sb[(size_t)j*Ln + i]     = s0;
                        Sb[(size_t)(j+1)*Ln + i] = s1;
                    }
                }
            }
        }
    }
}

// ---------------- 5) sem (32x512 tiles) + fused rowsum + LN + final mix -------
#define SEM_BS_F (2*16*520)
#define SEM_AS_F (2*32*20)
#define SEM_SMEM_BYTES ((SEM_BS_F + SEM_AS_F + 256 + 128 + 128) * 4)

__global__ __launch_bounds__(256)
void sem_kernel(const float* __restrict__ wp,
                const float* __restrict__ gt, const float* __restrict__ bt,
                float* __restrict__ out) {
    extern __shared__ float sm[];
    float* BsD = sm;
    float* AsD = sm + SEM_BS_F;
    float* srs = AsD + SEM_AS_F;
    float* rsum = srs + 256;
    float* rsq  = rsum + 128;
    __shared__ int s_list[64];
    __shared__ int s_nact;

    int b  = blockIdx.y;
    int i0 = blockIdx.x * 32;
    const float* Cb = g_c + (size_t)b*Ln*Dn;
    const float* Sb = g_S + (size_t)b*Ln*Ln;
    int tid = threadIdx.x;
    int warp = tid >> 5, lane = tid & 31;
    int wmr = (warp >> 2) * 16;
    int wn  = (warp & 3) * 128;
    int g = lane >> 2, th = lane & 3;

    if (tid == 0) {
        const int* fl = g_flag32 + (b*16 + (i0 >> 7))*64;
        int n = 0;
        for (int c = 0; c < 64; c++)
            if (fl[c]) s_list[n++] = c;
        s_nact = n;
    }
    __syncthreads();
    int total = s_nact * 2;

    int lrowA = tid >> 3, lkA = (tid & 7) * 2;
    int kB = tid >> 4, cB = tid & 15;
    const float* AgRow = Sb + (size_t)(i0 + lrowA)*Ln + lkA;
    const float* BgRow = Cb + (size_t)kB*Dn;

    float acc[16][4];
    #pragma unroll
    for (int i = 0; i < 16; i++)
        #pragma unroll
        for (int q = 0; q < 4; q++) acc[i][q] = 0.f;

    float rs = 0.f;
    int k0 = s_list[0] * 32;
    float2 pa = *(const float2*)(AgRow + k0);
    float4 pb[8];
    #pragma unroll
    for (int q = 0; q < 8; q++)
        pb[q] = *(const float4*)(BgRow + (size_t)k0*Dn + (cB + q*16)*4);
    rs += pa.x + pa.y;
    {
        float* ad = AsD + lrowA*20 + lkA;
        ad[0] = totf(pa.x); ad[1] = totf(pa.y);
        #pragma unroll
        for (int q = 0; q < 8; q++) {
            float* bd = BsD + kB*520 + (cB + q*16)*4;
            bd[0] = totf(pb[q].x); bd[1] = totf(pb[q].y);
            bd[2] = totf(pb[q].z); bd[3] = totf(pb[q].w);
        }
    }
    __syncthreads();
    int cur = 0;
    for (int st = 0; st < total; st++) {
        if (st + 1 < total) {
            int kn = s_list[(st+1) >> 1] * 32 + ((st+1) & 1) * 16;
            pa = *(const float2*)(AgRow + kn);
            #pragma unroll
            for (int q = 0; q < 8; q++)
                pb[q] = *(const float4*)(BgRow + (size_t)kn*Dn + (cB + q*16)*4);
        }
        const float* AsC = AsD + cur*(32*20);
        const float* BsC = BsD + cur*(16*520);
        #pragma unroll
        for (int k8 = 0; k8 < 16; k8 += 8) {
            unsigned af[4];
            const float* ap = AsC + (wmr + g)*20 + k8 + th;
            af[0] = __float_as_uint(ap[0]);
            af[1] = __float_as_uint(ap[8*20]);
            af[2] = __float_as_uint(ap[4]);
            af[3] = __float_as_uint(ap[8*20 + 4]);
            #pragma unroll
            for (int fn = 0; fn < 16; fn++) {
                unsigned bf_[2];
                const float* bp = BsC + (k8 + th)*520 + wn + fn*8 + g;
                bf_[0] = __float_as_uint(bp[0]);
                bf_[1] = __float_as_uint(bp[4*520]);
                mma_tf32(acc[fn], af, bf_);
            }
        }
        if (st + 1 < total) {
            int nxt = cur ^ 1;
            rs += pa.x + pa.y;
            float* ad = AsD + nxt*(32*20) + lrowA*20 + lkA;
            ad[0] = totf(pa.x); ad[1] = totf(pa.y);
            #pragma unroll
            for (int q = 0; q < 8; q++) {
                float* bd = BsD + nxt*(16*520) + kB*520 + (cB + q*16)*4;
                bd[0] = totf(pb[q].x); bd[1] = totf(pb[q].y);
                bd[2] = totf(pb[q].z); bd[3] = totf(pb[q].w);
            }
            __syncthreads();
            cur = nxt;
        }
    }
    __syncthreads();
    srs[tid] = rs;
    __syncthreads();

    int r0 = wmr + g, r1 = wmr + g + 8;
    float rsum0 = 0.f, rsum1 = 0.f;
    #pragma unroll
    for (int k = 0; k < 8; k++) { rsum0 += srs[r0*8 + k]; rsum1 += srs[r1*8 + k]; }
    float rinv0 = 1.0f / rsum0, rinv1 = 1.0f / rsum1;

    float sum0 = 0.f, sq0 = 0.f, sum1 = 0.f, sq1 = 0.f;
    int gi0 = i0 + r0, gi1 = i0 + r1;
    #pragma unroll
    for (int fn = 0; fn < 16; fn++) {
        int j = wn + fn*8 + th*2;
        float2 cv0 = *(const float2*)&Cb[(size_t)gi0*Dn + j];
        float2 pv0 = *(const float2*)&g_pe[gi0*Dn + j];
        float v00 = cv0.x + pv0.x + acc[fn][0]*rinv0;
        float v01 = cv0.y + pv0.y + acc[fn][1]*rinv0;
        acc[fn][0] = v00; acc[fn][1] = v01;
        sum0 += v00 + v01; sq0 += v00*v00 + v01*v01;
        float2 cv1 = *(const float2*)&Cb[(size_t)gi1*Dn + j];
        float2 pv1 = *(const float2*)&g_pe[gi1*Dn + j];
        float v10 = cv1.x + pv1.x + acc[fn][2]*rinv1;
        float v11 = cv1.y + pv1.y + acc[fn][3]*rinv1;
        acc[fn][2] = v10; acc[fn][3] = v11;
        sum1 += v10 + v11; sq1 += v10*v10 + v11*v11;
    }
    #pragma unroll
    for (int o = 1; o <= 2; o <<= 1) {
        sum0 += __shfl_xor_sync(0xffffffffu, sum0, o);
        sq0  += __shfl_xor_sync(0xffffffffu, sq0, o);
        sum1 += __shfl_xor_sync(0xffffffffu, sum1, o);
        sq1  += __shfl_xor_sync(0xffffffffu, sq1, o);
    }
    if (th == 0) {
        rsum[r0*4 + (warp & 3)] = sum0;  rsq[r0*4 + (warp & 3)] = sq0;
        rsum[r1*4 + (warp & 3)] = sum1;  rsq[r1*4 + (warp & 3)] = sq1;
    }
    __syncthreads();
    float ts0 = rsum[r0*4] + rsum[r0*4+1] + rsum[r0*4+2] + rsum[r0*4+3];
    float tq0 = rsq[r0*4]  + rsq[r0*4+1]  + rsq[r0*4+2]  + rsq[r0*4+3];
    float ts1 = rsum[r1*4] + rsum[r1*4+1] + rsum[r1*4+2] + rsum[r1*4+3];
    float tq1 = rsq[r1*4]  + rsq[r1*4+1]  + rsq[r1*4+2]  + rsq[r1*4+3];
    float mu0 = ts0 * (1.0f/Dn);
    float var0 = tq0 * (1.0f/Dn) - mu0*mu0;
    float inv0 = rsqrtf(var0 + EPSf);
    float mu1 = ts1 * (1.0f/Dn);
    float var1 = tq1 * (1.0f/Dn) - mu1*mu1;
    float inv1 = rsqrtf(var1 + EPSf);

    float w0 = wp[0], w1 = wp[1], w2 = wp[2], w3 = wp[3];
    float mx = fmaxf(fmaxf(w0, w1), fmaxf(w2, w3));
    float e0 = expf(w0-mx), e1 = expf(w1-mx), e2 = expf(w2-mx), e3 = expf(w3-mx);
    float esum = 1.0f / (e0+e1+e2+e3);
    w0 = e0*esum; w1 = e1*esum; w2 = e2*esum; w3 = e3*esum;

    float* ob = out + ((size_t)b*Ln)*Dn;
    #pragma unroll
    for (int fn = 0; fn < 16; fn++) {
        int j = wn + fn*8 + th*2;
        float2 gv = *(const float2*)&gt[j];
        float2 bv = *(const float2*)&bt[j];
        {
            float2 cv = *(const float2*)&Cb[(size_t)gi0*Dn + j];
            float2 pf = *(const float2*)&g_pef[gi0*Dn + j];
            float2 pl = *(const float2*)&g_pel[gi0*Dn + j];
            float t0v = (acc[fn][0]-mu0)*inv0*gv.x + bv.x;
            float t1v = (acc[fn][1]-mu0)*inv0*gv.y + bv.y;
            float2 ov;
            ov.x = w0*cv.x + w1*pf.x + w2*pl.x + w3*t0v;
            ov.y = w0*cv.y + w1*pf.y + w2*pl.y + w3*t1v;
            *(float2*)&ob[(size_t)gi0*Dn + j] = ov;
        }
        {
            float2 cv = *(const float2*)&Cb[(size_t)gi1*Dn + j];
            float2 pf = *(const float2*)&g_pef[gi1*Dn + j];
            float2 pl = *(const float2*)&g_pel[gi1*Dn + j];
            float t0v = (acc[fn][2]-mu1)*inv1*gv.x + bv.x;
            float t1v = (acc[fn][3]-mu1)*inv1*gv.y + bv.y;
            float2 ov;
            ov.x = w0*cv.x + w1*pf.x + w2*pl.x + w3*t0v;
            ov.y = w0*cv.y + w1*pf.y + w2*pl.y + w3*t1v;
            *(float2*)&ob[(size_t)gi1*Dn + j] = ov;
        }
    }
}

// ---------------- launch ------------------------------------------------------
extern "C" void kernel_launch(void* const* d_in, const int* in_sizes, int n_in,
                              void* d_out, int out_size) {
    const float* x          = (const float*)d_in[0];
    const float* conv_w     = (const float*)d_in[1];
    const float* conv_b     = (const float*)d_in[2];
    const float* pe_learned = (const float*)d_in[3];
    const float* wp         = (const float*)d_in[4];
    const float* gamma_c    = (const float*)d_in[5];
    const float* beta_c     = (const float*)d_in[6];
    const float* gamma_f    = (const float*)d_in[7];
    const float* beta_f     = (const float*)d_in[8];
    const float* gamma_l    = (const float*)d_in[9];
    const float* beta_l     = (const float*)d_in[10];
    const float* gamma_t    = (const float*)d_in[11];
    const float* beta_t     = (const float*)d_in[12];

    cudaFuncSetAttribute(sem_kernel, cudaFuncAttributeMaxDynamicSharedMemorySize, SEM_SMEM_BYTES);

    wtrans_kernel<<<(NF*3*Dn + 255)/256, 256>>>(conv_w);
    features_kernel<<<dim3(Ln/128, Bn), 256>>>(x);
    conv_ln_kernel<<<dim3(Ln/TT, Bn), 256>>>(conv_b, gamma_c, beta_c);
    pe_kernel<<<Ln, 256>>>(pe_learned, gamma_f, beta_f, gamma_l, beta_l);
    gram_kernel<<<dim3(136, Bn), 256>>>();
    sem_kernel<<<dim3(Ln/32, Bn), 256, SEM_SMEM_BYTES>>>(wp, gamma_t, beta_t, (float*)d_out);
}